// round 7
// baseline (speedup 1.0000x reference)
#include <cuda_runtime.h>
#include <cuda_fp16.h>
#include <cstdint>
#include <math.h>

#define BATCH 4096
#define HID 512
#define SEQLEN 7
#define FEATP 192            // padded feature dim (160 -> 192)
#define G4 2048              // 4*HID
#define NCLS 256
#define BT (BATCH * SEQLEN)  // 28672

// ---------------------------------------------------------------------------
// scratch (device globals)
// ---------------------------------------------------------------------------
__device__ __align__(16) float d_pool1[BATCH * 9 * 26 * 10];
__device__ __align__(16) __half d_seq_hi[BT * FEATP];
__device__ __align__(16) __half d_seq_lo[BT * FEATP];
__device__ __align__(16) float d_zx[BT * G4];
// ping-pong cat buffers: [h1|h2] fp16 hi/lo — fused epilogue writes the OTHER
// buffer than the one read, eliminating the cross-CTA read/write race.
__device__ __align__(16) __half d_cat0_hi[BATCH * 1024];
__device__ __align__(16) __half d_cat0_lo[BATCH * 1024];
__device__ __align__(16) __half d_cat1_hi[BATCH * 1024];
__device__ __align__(16) __half d_cat1_lo[BATCH * 1024];
__device__ __align__(16) float d_c1[BATCH * HID];
__device__ __align__(16) float d_c2[BATCH * HID];
// weights: transposed [N,K], gate-permuted cols (col' = 4j+g), fp16 hi/lo
__device__ __align__(16) __half d_W1p_hi[G4 * FEATP];
__device__ __align__(16) __half d_W1p_lo[G4 * FEATP];
__device__ __align__(16) __half d_U1p_hi[G4 * HID];
__device__ __align__(16) __half d_U1p_lo[G4 * HID];
__device__ __align__(16) __half d_WCp_hi[G4 * 1024];
__device__ __align__(16) __half d_WCp_lo[G4 * 1024];
__device__ __align__(16) __half d_FCt_hi[NCLS * HID];
__device__ __align__(16) __half d_FCt_lo[NCLS * HID];
__device__ __align__(16) float d_pb1[G4];                     // permuted biases
__device__ __align__(16) float d_pb2[G4];

// ---------------------------------------------------------------------------
// init: zero recurrent state (both cat buffers + cell states)
// ---------------------------------------------------------------------------
__global__ void init_state(uint32_t* __restrict__ c0h, uint32_t* __restrict__ c0l,
                           uint32_t* __restrict__ c1h, uint32_t* __restrict__ c1l,
                           float* __restrict__ c1, float* __restrict__ c2) {
    int i = blockIdx.x * blockDim.x + threadIdx.x;  // 0..2M-1
    c0h[i] = 0u;
    c0l[i] = 0u;
    c1h[i] = 0u;
    c1l[i] = 0u;
    c1[i] = 0.0f;
    c2[i] = 0.0f;
}

// ---------------------------------------------------------------------------
// weight prep: transpose + gate-permute + fp16 hi/lo split + permuted biases
// ---------------------------------------------------------------------------
#define PREP_W1 (G4 * FEATP)
#define PREP_U1 (G4 * HID)
#define PREP_WC (G4 * 1024)
#define PREP_FC (NCLS * HID)
#define PREP_PB (2 * G4)
#define PREP_TOTAL (PREP_W1 + PREP_U1 + PREP_WC + PREP_FC + PREP_PB)

__global__ void prep_weights(const float* __restrict__ W1, const float* __restrict__ U1,
                             const float* __restrict__ W2, const float* __restrict__ U2,
                             const float* __restrict__ FC,
                             const float* __restrict__ b1, const float* __restrict__ b2,
                             __half* __restrict__ w1h, __half* __restrict__ w1l,
                             __half* __restrict__ u1h, __half* __restrict__ u1l,
                             __half* __restrict__ wch, __half* __restrict__ wcl,
                             __half* __restrict__ fch, __half* __restrict__ fcl,
                             float* __restrict__ pb1, float* __restrict__ pb2) {
    int i = blockIdx.x * blockDim.x + threadIdx.x;
    if (i >= PREP_TOTAL) return;
    if (i >= PREP_W1 + PREP_U1 + PREP_WC + PREP_FC) {
        int o = i - (PREP_W1 + PREP_U1 + PREP_WC + PREP_FC);
        int which = o >> 11;
        int np = o & 2047;
        int src = (np & 3) * HID + (np >> 2);
        if (which == 0) pb1[np] = b1[src]; else pb2[np] = b2[src];
        return;
    }
    float v;
    __half *hi, *lo;
    int o;
    if (i < PREP_W1) {
        o = i;
        int np = o / FEATP, k = o % FEATP;
        int n = (np & 3) * HID + (np >> 2);
        v = (k < 160) ? W1[(size_t)k * G4 + n] : 0.0f;
        hi = w1h; lo = w1l;
    } else if (i < PREP_W1 + PREP_U1) {
        o = i - PREP_W1;
        int np = o >> 9, k = o & 511;
        int n = (np & 3) * HID + (np >> 2);
        v = U1[(size_t)k * G4 + n];
        hi = u1h; lo = u1l;
    } else if (i < PREP_W1 + PREP_U1 + PREP_WC) {
        o = i - PREP_W1 - PREP_U1;
        int np = o >> 10, k = o & 1023;
        int n = (np & 3) * HID + (np >> 2);
        v = (k < HID) ? W2[(size_t)k * G4 + n] : U2[(size_t)(k - HID) * G4 + n];
        hi = wch; lo = wcl;
    } else {
        o = i - PREP_W1 - PREP_U1 - PREP_WC;
        int n = o >> 9, k = o & 511;
        v = FC[(size_t)k * NCLS + n];
        hi = fch; lo = fcl;
    }
    __half h = __float2half_rn(v);
    hi[o] = h;
    lo[o] = __float2half_rn(v - __half2float(h));
}

// ---------------------------------------------------------------------------
// conv1 + relu + maxpool(3,3)
// ---------------------------------------------------------------------------
__global__ __launch_bounds__(256) void conv1_pool(
    const float* __restrict__ x, const float* __restrict__ w,
    const float* __restrict__ bias, float* __restrict__ out) {
    __shared__ float sIn[7 * 80 * 3];
    __shared__ float sW[7 * 3 * 3 * 10];
    int br = blockIdx.x;
    int r = br % 9;
    int b = br / 9;
    const float* xr = x + ((size_t)(b * 15 + r) * 80) * 3;
    for (int i = threadIdx.x; i < 1680; i += blockDim.x) sIn[i] = xr[i];
    for (int i = threadIdx.x; i < 630; i += blockDim.x) sW[i] = w[i];
    __syncthreads();
    for (int item = threadIdx.x; item < 260; item += blockDim.x) {
        int p = item / 10, co = item % 10;
        float best = -1e30f;
#pragma unroll
        for (int dx = 0; dx < 3; dx++) {
            int cw = p * 3 + dx;
            float acc = 0.0f;
#pragma unroll
            for (int kh = 0; kh < 7; kh++)
#pragma unroll
                for (int kw = 0; kw < 3; kw++)
#pragma unroll
                    for (int ci = 0; ci < 3; ci++)
                        acc += sIn[kh * 240 + (cw + kw) * 3 + ci] *
                               sW[((kh * 3 + kw) * 3 + ci) * 10 + co];
            best = fmaxf(best, acc);
        }
        out[((size_t)br * 26 + p) * 10 + co] = fmaxf(best + bias[co], 0.0f);
    }
}

// ---------------------------------------------------------------------------
// conv2 + relu + maxpool(3,3) -> seq hi/lo fp16 (padded to 192)
// ---------------------------------------------------------------------------
__global__ __launch_bounds__(256) void conv2_pool_split(
    const float* __restrict__ in, const float* __restrict__ w,
    const float* __restrict__ bias,
    __half* __restrict__ shi, __half* __restrict__ slo) {
    __shared__ float sIn[3 * 26 * 10];
    __shared__ float sW[3 * 3 * 10 * 20];
    int br = blockIdx.x;
    int r = br % 7;
    int b = br / 7;
    const float* inr = in + ((size_t)(b * 9 + r) * 26) * 10;
    for (int i = threadIdx.x; i < 780; i += blockDim.x) sIn[i] = inr[i];
    for (int i = threadIdx.x; i < 1800; i += blockDim.x) sW[i] = w[i];
    __syncthreads();
    for (int item = threadIdx.x; item < FEATP; item += blockDim.x) {
        float v = 0.0f;
        if (item < 160) {
            int p = item / 20, co = item % 20;
            float best = -1e30f;
#pragma unroll
            for (int dx = 0; dx < 3; dx++) {
                int cw = p * 3 + dx;
                float acc = 0.0f;
#pragma unroll
                for (int kh = 0; kh < 3; kh++)
#pragma unroll
                    for (int kw = 0; kw < 3; kw++)
#pragma unroll
                        for (int ci = 0; ci < 10; ci++)
                            acc += sIn[kh * 260 + (cw + kw) * 10 + ci] *
                                   sW[((kh * 3 + kw) * 10 + ci) * 20 + co];
                best = fmaxf(best, acc);
            }
            v = fmaxf(best + bias[co], 0.0f);
        }
        __half h = __float2half_rn(v);
        shi[(size_t)br * FEATP + item] = h;
        slo[(size_t)br * FEATP + item] = __float2half_rn(v - __half2float(h));
    }
}

// ---------------------------------------------------------------------------
// fp16 3-pass split GEMM: C = (Ahi+Alo) @ (Bhi+Blo)^T, B stored [N,K]
// tile 128x128, BK=32, ldmatrix, 2 CTAs/SM.
// gate==0: C fp32 (+bias +relu); gate==1: fused LSTM gates (permuted cols)
// gate mode writes h into hout_* (a DIFFERENT buffer than A — no aliasing).
// ---------------------------------------------------------------------------
#define ROWB 80
#define TILE_B (128 * ROWB)          // 10240
#define STAGE_B (4 * TILE_B)         // Ah | Al | Bh | Bl = 40960
#define GSM_BYTES (2 * STAGE_B)      // 81920

__device__ __forceinline__ uint32_t smem_u32(const void* p) {
    uint32_t a;
    asm("{ .reg .u64 t; cvta.to.shared.u64 t, %1; cvt.u32.u64 %0, t; }" : "=r"(a) : "l"(p));
    return a;
}
__device__ __forceinline__ void cp_async16(uint32_t sa, const void* gaddr) {
    asm volatile("cp.async.cg.shared.global [%0], [%1], 16;" :: "r"(sa), "l"(gaddr) : "memory");
}
__device__ __forceinline__ void ldmx4(uint32_t* r, uint32_t sa) {
    asm volatile("ldmatrix.sync.aligned.m8n8.x4.shared.b16 {%0,%1,%2,%3}, [%4];"
                 : "=r"(r[0]), "=r"(r[1]), "=r"(r[2]), "=r"(r[3]) : "r"(sa));
}
__device__ __forceinline__ void mma_f16(float* c, const uint32_t* a, uint32_t b0, uint32_t b1) {
    asm volatile(
        "mma.sync.aligned.m16n8k16.row.col.f32.f16.f16.f32 "
        "{%0,%1,%2,%3}, {%4,%5,%6,%7}, {%8,%9}, {%0,%1,%2,%3};"
        : "+f"(c[0]), "+f"(c[1]), "+f"(c[2]), "+f"(c[3])
        : "r"(a[0]), "r"(a[1]), "r"(a[2]), "r"(a[3]), "r"(b0), "r"(b1));
}
__device__ __forceinline__ float sigacc(float x) { return 1.0f / (1.0f + expf(-x)); }

__global__ __launch_bounds__(256, 2) void gemm_f16s(
    int M, int N, int K,
    const __half* __restrict__ Ahi, const __half* __restrict__ Alo, int lda,
    const __half* __restrict__ Bhi, const __half* __restrict__ Blo, int ldb,
    float* __restrict__ C, int ldc,
    const float* __restrict__ Cadd, int ldca,
    const float* __restrict__ bias, int relu,
    int gate, float* __restrict__ cbuf,
    __half* __restrict__ hout_hi, __half* __restrict__ hout_lo, int hoff) {
    extern __shared__ char smem[];
    uint32_t sb0 = smem_u32(smem);
    int tid = threadIdx.x;
    int lane = tid & 31;
    int warp = tid >> 5;
    int wm = warp >> 1;
    int wn = warp & 1;
    int gid = lane >> 2;
    int tig = lane & 3;
    int lane15 = lane & 15;
    int halfsel = (lane >> 4) << 4;

    int bm = blockIdx.y * 128;
    int bn = blockIdx.x * 128;

    const __half* Ah0 = Ahi + (size_t)bm * lda;
    const __half* Al0 = Alo + (size_t)bm * lda;
    const __half* Bh0 = Bhi + (size_t)bn * ldb;
    const __half* Bl0 = Blo + (size_t)bn * ldb;

    float acc[2][8][4];
#pragma unroll
    for (int i = 0; i < 2; i++)
#pragma unroll
        for (int j = 0; j < 8; j++)
#pragma unroll
            for (int r = 0; r < 4; r++) acc[i][j][r] = 0.0f;

    int nst = K >> 5;

#define ISSUE_STAGE(kt, buf) do {                                              \
        uint32_t st = sb0 + (buf) * STAGE_B;                                   \
        int k0 = (kt) << 5;                                                    \
        _Pragma("unroll")                                                      \
        for (int i = 0; i < 2; i++) {                                          \
            int ch = tid + i * 256;                                            \
            int row = ch >> 2, c4 = ch & 3;                                    \
            uint32_t sa = st + row * ROWB + c4 * 16;                           \
            cp_async16(sa,              Ah0 + (size_t)row * lda + k0 + c4 * 8);\
            cp_async16(sa + TILE_B,     Al0 + (size_t)row * lda + k0 + c4 * 8);\
            cp_async16(sa + 2 * TILE_B, Bh0 + (size_t)row * ldb + k0 + c4 * 8);\
            cp_async16(sa + 3 * TILE_B, Bl0 + (size_t)row * ldb + k0 + c4 * 8);\
        }                                                                      \
        asm volatile("cp.async.commit_group;" ::: "memory");                   \
    } while (0)

    ISSUE_STAGE(0, 0);

    for (int kt = 0; kt < nst; kt++) {
        int buf = kt & 1;
        if (kt + 1 < nst) {
            ISSUE_STAGE(kt + 1, buf ^ 1);
            asm volatile("cp.async.wait_group 1;" ::: "memory");
        } else {
            asm volatile("cp.async.wait_group 0;" ::: "memory");
        }
        __syncthreads();

        uint32_t st = sb0 + buf * STAGE_B;
        uint32_t aAddr = st + (uint32_t)((wm * 32 + lane15) * ROWB) + halfsel;
        uint32_t bAddr = st + 2 * TILE_B + (uint32_t)((wn * 64 + lane15) * ROWB) + halfsel;

#pragma unroll
        for (int k16 = 0; k16 < 2; k16++) {
            uint32_t kb = k16 * 32;
            uint32_t a_hi[2][4], a_lo[2][4];
#pragma unroll
            for (int ma = 0; ma < 2; ma++) {
                ldmx4(a_hi[ma], aAddr + ma * (16 * ROWB) + kb);
                ldmx4(a_lo[ma], aAddr + TILE_B + ma * (16 * ROWB) + kb);
            }
#pragma unroll
            for (int nb = 0; nb < 4; nb++) {
                uint32_t bh[4], bl[4];
                ldmx4(bh, bAddr + nb * (16 * ROWB) + kb);
                ldmx4(bl, bAddr + TILE_B + nb * (16 * ROWB) + kb);
#pragma unroll
                for (int hf = 0; hf < 2; hf++) {
                    int na = nb * 2 + hf;
                    uint32_t b0h = bh[hf], b1h = bh[2 + hf];
                    uint32_t b0l = bl[hf], b1l = bl[2 + hf];
#pragma unroll
                    for (int ma = 0; ma < 2; ma++) {
                        mma_f16(acc[ma][na], a_hi[ma], b0h, b1h);
                        mma_f16(acc[ma][na], a_hi[ma], b0l, b1l);
                        mma_f16(acc[ma][na], a_lo[ma], b0h, b1h);
                    }
                }
            }
        }
        __syncthreads();
    }

    // ---- epilogue ----
    if (gate) {
#pragma unroll
        for (int ma = 0; ma < 2; ma++) {
#pragma unroll
            for (int na = 0; na < 8; na++) {
                int row0 = bm + wm * 32 + ma * 16 + gid;
                int col0 = bn + wn * 64 + na * 8 + 2 * tig;
                float v0 = acc[ma][na][0], v1 = acc[ma][na][1];
                float v2 = acc[ma][na][2], v3 = acc[ma][na][3];
                if (Cadd) {
                    float2 ca = *(const float2*)(Cadd + (size_t)row0 * ldca + col0);
                    float2 cb = *(const float2*)(Cadd + (size_t)(row0 + 8) * ldca + col0);
                    v0 += ca.x; v1 += ca.y; v2 += cb.x; v3 += cb.y;
                }
                float bb0 = bias[col0], bb1 = bias[col0 + 1];
                v0 += bb0; v1 += bb1; v2 += bb0; v3 += bb1;
                // tig-partner exchange: even tig holds (i,f), odd holds (g,o)
                float u0 = __shfl_xor_sync(0xffffffffu, v0, 1);
                float u1 = __shfl_xor_sync(0xffffffffu, v1, 1);
                float u2 = __shfl_xor_sync(0xffffffffu, v2, 1);
                float u3 = __shfl_xor_sync(0xffffffffu, v3, 1);
                int odd = tig & 1;
                int row = odd ? (row0 + 8) : row0;
                int j = col0 >> 2;
                float gi = odd ? u2 : v0;
                float gf = odd ? u3 : v1;
                float gc = odd ? v2 : u0;
                float go = odd ? v3 : u1;
                size_t cidx = (size_t)row * HID + j;
                float cv = sigacc(gf) * cbuf[cidx] + sigacc(gi) * tanhf(gc);
                cbuf[cidx] = cv;
                float h = sigacc(go) * tanhf(cv);
                __half hh = __float2half_rn(h);
                size_t o = (size_t)row * 1024 + hoff + j;
                hout_hi[o] = hh;
                hout_lo[o] = __float2half_rn(h - __half2float(hh));
            }
        }
    } else {
#pragma unroll
        for (int ma = 0; ma < 2; ma++) {
#pragma unroll
            for (int na = 0; na < 8; na++) {
                int row0 = bm + wm * 32 + ma * 16 + gid;
                int col = bn + wn * 64 + na * 8 + 2 * tig;
                float v0 = acc[ma][na][0], v1 = acc[ma][na][1];
                float v2 = acc[ma][na][2], v3 = acc[ma][na][3];
                if (bias) {
                    float bb0 = bias[col], bb1 = bias[col + 1];
                    v0 += bb0; v1 += bb1; v2 += bb0; v3 += bb1;
                }
                if (relu) {
                    v0 = fmaxf(v0, 0.0f); v1 = fmaxf(v1, 0.0f);
                    v2 = fmaxf(v2, 0.0f); v3 = fmaxf(v3, 0.0f);
                }
                *(float2*)(C + (size_t)row0 * ldc + col) = make_float2(v0, v1);
                *(float2*)(C + (size_t)(row0 + 8) * ldc + col) = make_float2(v2, v3);
            }
        }
    }
#undef ISSUE_STAGE
}

// ---------------------------------------------------------------------------
// launch
// ---------------------------------------------------------------------------
extern "C" void kernel_launch(void* const* d_in, const int* in_sizes, int n_in,
                              void* d_out, int out_size) {
    const float* x = (const float*)d_in[0];
    const float* c1w = (const float*)d_in[1];
    const float* c1b = (const float*)d_in[2];
    const float* c2w = (const float*)d_in[3];
    const float* c2b = (const float*)d_in[4];
    const float* W1 = (const float*)d_in[5];
    const float* U1 = (const float*)d_in[6];
    const float* b1 = (const float*)d_in[7];
    const float* W2 = (const float*)d_in[8];
    const float* U2 = (const float*)d_in[9];
    const float* b2 = (const float*)d_in[10];
    const float* fcw = (const float*)d_in[11];
    const float* fcb = (const float*)d_in[12];
    float* out = (float*)d_out;

    float *pool1, *zx, *c1, *c2, *pb1, *pb2;
    __half *shi, *slo;
    __half *cat_hi[2], *cat_lo[2];
    __half *w1h, *w1l, *u1h, *u1l, *wch, *wcl, *fch, *fcl;
    cudaGetSymbolAddress((void**)&pool1, d_pool1);
    cudaGetSymbolAddress((void**)&zx, d_zx);
    cudaGetSymbolAddress((void**)&c1, d_c1);
    cudaGetSymbolAddress((void**)&c2, d_c2);
    cudaGetSymbolAddress((void**)&pb1, d_pb1);
    cudaGetSymbolAddress((void**)&pb2, d_pb2);
    cudaGetSymbolAddress((void**)&shi, d_seq_hi);
    cudaGetSymbolAddress((void**)&slo, d_seq_lo);
    cudaGetSymbolAddress((void**)&cat_hi[0], d_cat0_hi);
    cudaGetSymbolAddress((void**)&cat_lo[0], d_cat0_lo);
    cudaGetSymbolAddress((void**)&cat_hi[1], d_cat1_hi);
    cudaGetSymbolAddress((void**)&cat_lo[1], d_cat1_lo);
    cudaGetSymbolAddress((void**)&w1h, d_W1p_hi);
    cudaGetSymbolAddress((void**)&w1l, d_W1p_lo);
    cudaGetSymbolAddress((void**)&u1h, d_U1p_hi);
    cudaGetSymbolAddress((void**)&u1l, d_U1p_lo);
    cudaGetSymbolAddress((void**)&wch, d_WCp_hi);
    cudaGetSymbolAddress((void**)&wcl, d_WCp_lo);
    cudaGetSymbolAddress((void**)&fch, d_FCt_hi);
    cudaGetSymbolAddress((void**)&fcl, d_FCt_lo);

    cudaFuncSetAttribute(gemm_f16s, cudaFuncAttributeMaxDynamicSharedMemorySize, GSM_BYTES);

    init_state<<<(BATCH * 1024 / 2) / 256, 256>>>(
        (uint32_t*)cat_hi[0], (uint32_t*)cat_lo[0],
        (uint32_t*)cat_hi[1], (uint32_t*)cat_lo[1], c1, c2);
    prep_weights<<<(PREP_TOTAL + 255) / 256, 256>>>(W1, U1, W2, U2, fcw, b1, b2,
                                                    w1h, w1l, u1h, u1l, wch, wcl,
                                                    fch, fcl, pb1, pb2);
    conv1_pool<<<BATCH * 9, 256>>>(x, c1w, c1b, pool1);
    conv2_pool_split<<<BATCH * 7, 256>>>(pool1, c2w, c2b, shi, slo);

    // zx = seq @ W1p : [28672,192] x [192,2048] (permuted cols)
    {
        dim3 g(G4 / 128, BT / 128);
        gemm_f16s<<<g, 256, GSM_BYTES>>>(BT, G4, FEATP, shi, slo, FEATP,
                                         w1h, w1l, FEATP, zx, G4,
                                         nullptr, 0, nullptr, 0,
                                         0, nullptr, nullptr, nullptr, 0);
    }

    dim3 ga(G4 / 128, BATCH / 128);
    for (int t = 0; t < SEQLEN; t++) {
        int p = t & 1;
        // layer 1: gates(zx[t] + h1 @ U1p) -> h1, c1
        //   reads cat[p] (h1_{t-1}), writes h1_t -> cat[1-p][:, 0:512]
        gemm_f16s<<<ga, 256, GSM_BYTES>>>(BATCH, G4, HID, cat_hi[p], cat_lo[p], 1024,
                                          u1h, u1l, HID, nullptr, 0,
                                          zx + t * G4, SEQLEN * G4, pb1, 0,
                                          1, c1, cat_hi[1 - p], cat_lo[1 - p], 0);
        // layer 2: gates([h1_t|h2_{t-1}] @ WCp) -> h2, c2
        //   reads cat[1-p], writes h2_t -> cat[p][:, 512:1024]
        gemm_f16s<<<ga, 256, GSM_BYTES>>>(BATCH, G4, 1024, cat_hi[1 - p], cat_lo[1 - p], 1024,
                                          wch, wcl, 1024, nullptr, 0,
                                          nullptr, 0, pb2, 0,
                                          1, c2, cat_hi[p], cat_lo[p], HID);
    }

    // FC head: relu(h2 @ fc_w + fc_b); final h2 lives in cat[(SEQLEN-1)&1] = cat[0]
    {
        int pf = (SEQLEN - 1) & 1;
        dim3 gf(NCLS / 128, BATCH / 128);
        gemm_f16s<<<gf, 256, GSM_BYTES>>>(BATCH, NCLS, HID,
                                          cat_hi[pf] + HID, cat_lo[pf] + HID, 1024,
                                          fch, fcl, HID, out, NCLS,
                                          nullptr, 0, fcb, 1,
                                          0, nullptr, nullptr, nullptr, 0);
    }
}

// round 8
// speedup vs baseline: 1.0666x; 1.0666x over previous
#include <cuda_runtime.h>
#include <cuda_fp16.h>
#include <cstdint>
#include <math.h>

#define BATCH 4096
#define HID 512
#define SEQLEN 7
#define FEATP 192            // padded feature dim (160 -> 192)
#define G4 2048              // 4*HID
#define NCLS 256
#define BT (BATCH * SEQLEN)  // 28672

// ---------------------------------------------------------------------------
// scratch (device globals)
// ---------------------------------------------------------------------------
__device__ __align__(16) float d_pool1[BATCH * 9 * 26 * 10];
__device__ __align__(16) __half d_seq_hi[BT * FEATP];
__device__ __align__(16) __half d_seq_lo[BT * FEATP];
__device__ __align__(16) float d_zx[BT * G4];
// ping-pong cat buffers: [h1|h2] fp16 hi/lo (race-free fused epilogue)
__device__ __align__(16) __half d_cat0_hi[BATCH * 1024];
__device__ __align__(16) __half d_cat0_lo[BATCH * 1024];
__device__ __align__(16) __half d_cat1_hi[BATCH * 1024];
__device__ __align__(16) __half d_cat1_lo[BATCH * 1024];
__device__ __align__(16) float d_c1[BATCH * HID];
__device__ __align__(16) float d_c2[BATCH * HID];
// weights: transposed [N,K], gate-permuted cols (col' = 4j+g), fp16 hi/lo
__device__ __align__(16) __half d_W1p_hi[G4 * FEATP];
__device__ __align__(16) __half d_W1p_lo[G4 * FEATP];
__device__ __align__(16) __half d_U1p_hi[G4 * HID];
__device__ __align__(16) __half d_U1p_lo[G4 * HID];
__device__ __align__(16) __half d_WCp_hi[G4 * 1024];
__device__ __align__(16) __half d_WCp_lo[G4 * 1024];
__device__ __align__(16) __half d_FCt_hi[NCLS * HID];
__device__ __align__(16) __half d_FCt_lo[NCLS * HID];
__device__ __align__(16) float d_pb1[G4];                     // permuted biases
__device__ __align__(16) float d_pb2[G4];

// ---------------------------------------------------------------------------
// init: zero recurrent state
// ---------------------------------------------------------------------------
__global__ void init_state(uint32_t* __restrict__ c0h, uint32_t* __restrict__ c0l,
                           uint32_t* __restrict__ c1h, uint32_t* __restrict__ c1l,
                           float* __restrict__ c1, float* __restrict__ c2) {
    int i = blockIdx.x * blockDim.x + threadIdx.x;
    c0h[i] = 0u;
    c0l[i] = 0u;
    c1h[i] = 0u;
    c1l[i] = 0u;
    c1[i] = 0.0f;
    c2[i] = 0.0f;
}

// ---------------------------------------------------------------------------
// weight prep: transpose + gate-permute + fp16 hi/lo split + permuted biases
// ---------------------------------------------------------------------------
#define PREP_W1 (G4 * FEATP)
#define PREP_U1 (G4 * HID)
#define PREP_WC (G4 * 1024)
#define PREP_FC (NCLS * HID)
#define PREP_PB (2 * G4)
#define PREP_TOTAL (PREP_W1 + PREP_U1 + PREP_WC + PREP_FC + PREP_PB)

__global__ void prep_weights(const float* __restrict__ W1, const float* __restrict__ U1,
                             const float* __restrict__ W2, const float* __restrict__ U2,
                             const float* __restrict__ FC,
                             const float* __restrict__ b1, const float* __restrict__ b2,
                             __half* __restrict__ w1h, __half* __restrict__ w1l,
                             __half* __restrict__ u1h, __half* __restrict__ u1l,
                             __half* __restrict__ wch, __half* __restrict__ wcl,
                             __half* __restrict__ fch, __half* __restrict__ fcl,
                             float* __restrict__ pb1, float* __restrict__ pb2) {
    int i = blockIdx.x * blockDim.x + threadIdx.x;
    if (i >= PREP_TOTAL) return;
    if (i >= PREP_W1 + PREP_U1 + PREP_WC + PREP_FC) {
        int o = i - (PREP_W1 + PREP_U1 + PREP_WC + PREP_FC);
        int which = o >> 11;
        int np = o & 2047;
        int src = (np & 3) * HID + (np >> 2);
        if (which == 0) pb1[np] = b1[src]; else pb2[np] = b2[src];
        return;
    }
    float v;
    __half *hi, *lo;
    int o;
    if (i < PREP_W1) {
        o = i;
        int np = o / FEATP, k = o % FEATP;
        int n = (np & 3) * HID + (np >> 2);
        v = (k < 160) ? W1[(size_t)k * G4 + n] : 0.0f;
        hi = w1h; lo = w1l;
    } else if (i < PREP_W1 + PREP_U1) {
        o = i - PREP_W1;
        int np = o >> 9, k = o & 511;
        int n = (np & 3) * HID + (np >> 2);
        v = U1[(size_t)k * G4 + n];
        hi = u1h; lo = u1l;
    } else if (i < PREP_W1 + PREP_U1 + PREP_WC) {
        o = i - PREP_W1 - PREP_U1;
        int np = o >> 10, k = o & 1023;
        int n = (np & 3) * HID + (np >> 2);
        v = (k < HID) ? W2[(size_t)k * G4 + n] : U2[(size_t)(k - HID) * G4 + n];
        hi = wch; lo = wcl;
    } else {
        o = i - PREP_W1 - PREP_U1 - PREP_WC;
        int n = o >> 9, k = o & 511;
        v = FC[(size_t)k * NCLS + n];
        hi = fch; lo = fcl;
    }
    __half h = __float2half_rn(v);
    hi[o] = h;
    lo[o] = __float2half_rn(v - __half2float(h));
}

// ---------------------------------------------------------------------------
// conv1 + relu + maxpool(3,3): one block per batch sample (weights loaded 1x)
// x: [B,15,80,3] -> out [B,9,26,10]
// ---------------------------------------------------------------------------
__global__ __launch_bounds__(256) void conv1_pool(
    const float* __restrict__ x, const float* __restrict__ w,
    const float* __restrict__ bias, float* __restrict__ out) {
    __shared__ float sIn[15 * 80 * 3];   // 3600
    __shared__ float sW[7 * 3 * 3 * 10]; // 630
    int b = blockIdx.x;
    const float* xb = x + (size_t)b * 3600;
    for (int i = threadIdx.x; i < 3600; i += 256) sIn[i] = xb[i];
    for (int i = threadIdx.x; i < 630; i += 256) sW[i] = w[i];
    __syncthreads();
    for (int item = threadIdx.x; item < 9 * 260; item += 256) {
        int r = item / 260;
        int rem = item - r * 260;
        int p = rem / 10, co = rem - p * 10;
        float best = -1e30f;
#pragma unroll
        for (int dx = 0; dx < 3; dx++) {
            int cw = p * 3 + dx;
            float acc = 0.0f;
#pragma unroll
            for (int kh = 0; kh < 7; kh++)
#pragma unroll
                for (int kw = 0; kw < 3; kw++)
#pragma unroll
                    for (int ci = 0; ci < 3; ci++)
                        acc += sIn[(r + kh) * 240 + (cw + kw) * 3 + ci] *
                               sW[((kh * 3 + kw) * 3 + ci) * 10 + co];
            best = fmaxf(best, acc);
        }
        out[((size_t)(b * 9 + r) * 26 + p) * 10 + co] = fmaxf(best + bias[co], 0.0f);
    }
}

// ---------------------------------------------------------------------------
// conv2 + relu + maxpool(3,3) -> seq hi/lo fp16 (padded to 192); block = sample
// in: [B,9,26,10] -> seq [B,7,192]
// ---------------------------------------------------------------------------
__global__ __launch_bounds__(256) void conv2_pool_split(
    const float* __restrict__ in, const float* __restrict__ w,
    const float* __restrict__ bias,
    __half* __restrict__ shi, __half* __restrict__ slo) {
    __shared__ float sIn[9 * 26 * 10];    // 2340
    __shared__ float sW[3 * 3 * 10 * 20]; // 1800
    int b = blockIdx.x;
    const float* inb = in + (size_t)b * 2340;
    for (int i = threadIdx.x; i < 2340; i += 256) sIn[i] = inb[i];
    for (int i = threadIdx.x; i < 1800; i += 256) sW[i] = w[i];
    __syncthreads();
    for (int item = threadIdx.x; item < 7 * 160; item += 256) {
        int r = item / 160;
        int f = item - r * 160;
        int p = f / 20, co = f - p * 20;
        float best = -1e30f;
#pragma unroll
        for (int dx = 0; dx < 3; dx++) {
            int cw = p * 3 + dx;
            float acc = 0.0f;
#pragma unroll
            for (int kh = 0; kh < 3; kh++)
#pragma unroll
                for (int kw = 0; kw < 3; kw++)
#pragma unroll
                    for (int ci = 0; ci < 10; ci++)
                        acc += sIn[(r + kh) * 260 + (cw + kw) * 10 + ci] *
                               sW[((kh * 3 + kw) * 10 + ci) * 20 + co];
            best = fmaxf(best, acc);
        }
        float v = fmaxf(best + bias[co], 0.0f);
        __half h = __float2half_rn(v);
        size_t o = (size_t)(b * 7 + r) * FEATP + f;
        shi[o] = h;
        slo[o] = __float2half_rn(v - __half2float(h));
    }
    // zero pad features 160..191
    for (int i = threadIdx.x; i < 7 * 32; i += 256) {
        int r = i >> 5;
        size_t o = (size_t)(b * 7 + r) * FEATP + 160 + (i & 31);
        shi[o] = __float2half_rn(0.0f);
        slo[o] = __float2half_rn(0.0f);
    }
}

// ---------------------------------------------------------------------------
// fp16 3-pass split GEMM; gate mode stages pre-activations through SMEM so all
// cbuf / cat accesses are coalesced.
// ---------------------------------------------------------------------------
#define ROWB 80
#define TILE_B (128 * ROWB)          // 10240
#define STAGE_B (4 * TILE_B)         // 40960
#define GSM_BYTES (2 * STAGE_B)      // 81920 (also >= 128*132*4 = 67584)
#define EPI_PITCH 132

__device__ __forceinline__ uint32_t smem_u32(const void* p) {
    uint32_t a;
    asm("{ .reg .u64 t; cvta.to.shared.u64 t, %1; cvt.u32.u64 %0, t; }" : "=r"(a) : "l"(p));
    return a;
}
__device__ __forceinline__ void cp_async16(uint32_t sa, const void* gaddr) {
    asm volatile("cp.async.cg.shared.global [%0], [%1], 16;" :: "r"(sa), "l"(gaddr) : "memory");
}
__device__ __forceinline__ void ldmx4(uint32_t* r, uint32_t sa) {
    asm volatile("ldmatrix.sync.aligned.m8n8.x4.shared.b16 {%0,%1,%2,%3}, [%4];"
                 : "=r"(r[0]), "=r"(r[1]), "=r"(r[2]), "=r"(r[3]) : "r"(sa));
}
__device__ __forceinline__ void mma_f16(float* c, const uint32_t* a, uint32_t b0, uint32_t b1) {
    asm volatile(
        "mma.sync.aligned.m16n8k16.row.col.f32.f16.f16.f32 "
        "{%0,%1,%2,%3}, {%4,%5,%6,%7}, {%8,%9}, {%0,%1,%2,%3};"
        : "+f"(c[0]), "+f"(c[1]), "+f"(c[2]), "+f"(c[3])
        : "r"(a[0]), "r"(a[1]), "r"(a[2]), "r"(a[3]), "r"(b0), "r"(b1));
}
__device__ __forceinline__ float sigacc(float x) { return 1.0f / (1.0f + expf(-x)); }

__global__ __launch_bounds__(256, 2) void gemm_f16s(
    int M, int N, int K,
    const __half* __restrict__ Ahi, const __half* __restrict__ Alo, int lda,
    const __half* __restrict__ Bhi, const __half* __restrict__ Blo, int ldb,
    float* __restrict__ C, int ldc,
    const float* __restrict__ Cadd, int ldca,
    const float* __restrict__ bias, int relu,
    int gate, float* __restrict__ cbuf,
    __half* __restrict__ hout_hi, __half* __restrict__ hout_lo, int hoff) {
    extern __shared__ char smem[];
    uint32_t sb0 = smem_u32(smem);
    int tid = threadIdx.x;
    int lane = tid & 31;
    int warp = tid >> 5;
    int wm = warp >> 1;
    int wn = warp & 1;
    int gid = lane >> 2;
    int tig = lane & 3;
    int lane15 = lane & 15;
    int halfsel = (lane >> 4) << 4;

    int bm = blockIdx.y * 128;
    int bn = blockIdx.x * 128;

    const __half* Ah0 = Ahi + (size_t)bm * lda;
    const __half* Al0 = Alo + (size_t)bm * lda;
    const __half* Bh0 = Bhi + (size_t)bn * ldb;
    const __half* Bl0 = Blo + (size_t)bn * ldb;

    float acc[2][8][4];
#pragma unroll
    for (int i = 0; i < 2; i++)
#pragma unroll
        for (int j = 0; j < 8; j++)
#pragma unroll
            for (int r = 0; r < 4; r++) acc[i][j][r] = 0.0f;

    int nst = K >> 5;

#define ISSUE_STAGE(kt, buf) do {                                              \
        uint32_t st = sb0 + (buf) * STAGE_B;                                   \
        int k0 = (kt) << 5;                                                    \
        _Pragma("unroll")                                                      \
        for (int i = 0; i < 2; i++) {                                          \
            int ch = tid + i * 256;                                            \
            int row = ch >> 2, c4 = ch & 3;                                    \
            uint32_t sa = st + row * ROWB + c4 * 16;                           \
            cp_async16(sa,              Ah0 + (size_t)row * lda + k0 + c4 * 8);\
            cp_async16(sa + TILE_B,     Al0 + (size_t)row * lda + k0 + c4 * 8);\
            cp_async16(sa + 2 * TILE_B, Bh0 + (size_t)row * ldb + k0 + c4 * 8);\
            cp_async16(sa + 3 * TILE_B, Bl0 + (size_t)row * ldb + k0 + c4 * 8);\
        }                                                                      \
        asm volatile("cp.async.commit_group;" ::: "memory");                   \
    } while (0)

    ISSUE_STAGE(0, 0);

    for (int kt = 0; kt < nst; kt++) {
        int buf = kt & 1;
        if (kt + 1 < nst) {
            ISSUE_STAGE(kt + 1, buf ^ 1);
            asm volatile("cp.async.wait_group 1;" ::: "memory");
        } else {
            asm volatile("cp.async.wait_group 0;" ::: "memory");
        }
        __syncthreads();

        uint32_t st = sb0 + buf * STAGE_B;
        uint32_t aAddr = st + (uint32_t)((wm * 32 + lane15) * ROWB) + halfsel;
        uint32_t bAddr = st + 2 * TILE_B + (uint32_t)((wn * 64 + lane15) * ROWB) + halfsel;

#pragma unroll
        for (int k16 = 0; k16 < 2; k16++) {
            uint32_t kb = k16 * 32;
            uint32_t a_hi[2][4], a_lo[2][4];
#pragma unroll
            for (int ma = 0; ma < 2; ma++) {
                ldmx4(a_hi[ma], aAddr + ma * (16 * ROWB) + kb);
                ldmx4(a_lo[ma], aAddr + TILE_B + ma * (16 * ROWB) + kb);
            }
#pragma unroll
            for (int nb = 0; nb < 4; nb++) {
                uint32_t bh[4], bl[4];
                ldmx4(bh, bAddr + nb * (16 * ROWB) + kb);
                ldmx4(bl, bAddr + TILE_B + nb * (16 * ROWB) + kb);
#pragma unroll
                for (int hf = 0; hf < 2; hf++) {
                    int na = nb * 2 + hf;
                    uint32_t b0h = bh[hf], b1h = bh[2 + hf];
                    uint32_t b0l = bl[hf], b1l = bl[2 + hf];
#pragma unroll
                    for (int ma = 0; ma < 2; ma++) {
                        mma_f16(acc[ma][na], a_hi[ma], b0h, b1h);
                        mma_f16(acc[ma][na], a_hi[ma], b0l, b1l);
                        mma_f16(acc[ma][na], a_lo[ma], b0h, b1h);
                    }
                }
            }
        }
        __syncthreads();
    }

    // ---- epilogue ----
    if (gate) {
        // stage bias/Cadd-adjusted pre-activations into smem (reuse pipeline buf)
        float* sg = (float*)smem;
#pragma unroll
        for (int ma = 0; ma < 2; ma++) {
#pragma unroll
            for (int na = 0; na < 8; na++) {
                int rl = wm * 32 + ma * 16 + gid;        // local row 0..127
                int cl = wn * 64 + na * 8 + 2 * tig;     // local col 0..127
                int row0 = bm + rl;
                int col0 = bn + cl;
                float v0 = acc[ma][na][0], v1 = acc[ma][na][1];
                float v2 = acc[ma][na][2], v3 = acc[ma][na][3];
                if (Cadd) {
                    float2 ca = *(const float2*)(Cadd + (size_t)row0 * ldca + col0);
                    float2 cb = *(const float2*)(Cadd + (size_t)(row0 + 8) * ldca + col0);
                    v0 += ca.x; v1 += ca.y; v2 += cb.x; v3 += cb.y;
                }
                float bb0 = bias[col0], bb1 = bias[col0 + 1];
                *(float2*)&sg[rl * EPI_PITCH + cl] = make_float2(v0 + bb0, v1 + bb1);
                *(float2*)&sg[(rl + 8) * EPI_PITCH + cl] = make_float2(v2 + bb0, v3 + bb1);
            }
        }
        __syncthreads();
        // coalesced gate pass: each output = float4 (i,f,g,o) at (row, j)
        int jb = bn >> 2;
#pragma unroll
        for (int it = 0; it < 16; it++) {
            int idx = it * 256 + tid;
            int rl = idx >> 5, jl = idx & 31;
            float4 g = *(const float4*)&sg[rl * EPI_PITCH + jl * 4];
            int grow = bm + rl;
            int j = jb + jl;
            size_t cidx = (size_t)grow * HID + j;
            float cv = sigacc(g.y) * cbuf[cidx] + sigacc(g.x) * tanhf(g.z);
            cbuf[cidx] = cv;
            float h = sigacc(g.w) * tanhf(cv);
            __half hh = __float2half_rn(h);
            size_t o = (size_t)grow * 1024 + hoff + j;
            hout_hi[o] = hh;
            hout_lo[o] = __float2half_rn(h - __half2float(hh));
        }
    } else {
#pragma unroll
        for (int ma = 0; ma < 2; ma++) {
#pragma unroll
            for (int na = 0; na < 8; na++) {
                int row0 = bm + wm * 32 + ma * 16 + gid;
                int col = bn + wn * 64 + na * 8 + 2 * tig;
                float v0 = acc[ma][na][0], v1 = acc[ma][na][1];
                float v2 = acc[ma][na][2], v3 = acc[ma][na][3];
                if (bias) {
                    float bb0 = bias[col], bb1 = bias[col + 1];
                    v0 += bb0; v1 += bb1; v2 += bb0; v3 += bb1;
                }
                if (relu) {
                    v0 = fmaxf(v0, 0.0f); v1 = fmaxf(v1, 0.0f);
                    v2 = fmaxf(v2, 0.0f); v3 = fmaxf(v3, 0.0f);
                }
                *(float2*)(C + (size_t)row0 * ldc + col) = make_float2(v0, v1);
                *(float2*)(C + (size_t)(row0 + 8) * ldc + col) = make_float2(v2, v3);
            }
        }
    }
#undef ISSUE_STAGE
}

// ---------------------------------------------------------------------------
// launch
// ---------------------------------------------------------------------------
extern "C" void kernel_launch(void* const* d_in, const int* in_sizes, int n_in,
                              void* d_out, int out_size) {
    const float* x = (const float*)d_in[0];
    const float* c1w = (const float*)d_in[1];
    const float* c1b = (const float*)d_in[2];
    const float* c2w = (const float*)d_in[3];
    const float* c2b = (const float*)d_in[4];
    const float* W1 = (const float*)d_in[5];
    const float* U1 = (const float*)d_in[6];
    const float* b1 = (const float*)d_in[7];
    const float* W2 = (const float*)d_in[8];
    const float* U2 = (const float*)d_in[9];
    const float* b2 = (const float*)d_in[10];
    const float* fcw = (const float*)d_in[11];
    const float* fcb = (const float*)d_in[12];
    float* out = (float*)d_out;

    float *pool1, *zx, *c1, *c2, *pb1, *pb2;
    __half *shi, *slo;
    __half *cat_hi[2], *cat_lo[2];
    __half *w1h, *w1l, *u1h, *u1l, *wch, *wcl, *fch, *fcl;
    cudaGetSymbolAddress((void**)&pool1, d_pool1);
    cudaGetSymbolAddress((void**)&zx, d_zx);
    cudaGetSymbolAddress((void**)&c1, d_c1);
    cudaGetSymbolAddress((void**)&c2, d_c2);
    cudaGetSymbolAddress((void**)&pb1, d_pb1);
    cudaGetSymbolAddress((void**)&pb2, d_pb2);
    cudaGetSymbolAddress((void**)&shi, d_seq_hi);
    cudaGetSymbolAddress((void**)&slo, d_seq_lo);
    cudaGetSymbolAddress((void**)&cat_hi[0], d_cat0_hi);
    cudaGetSymbolAddress((void**)&cat_lo[0], d_cat0_lo);
    cudaGetSymbolAddress((void**)&cat_hi[1], d_cat1_hi);
    cudaGetSymbolAddress((void**)&cat_lo[1], d_cat1_lo);
    cudaGetSymbolAddress((void**)&w1h, d_W1p_hi);
    cudaGetSymbolAddress((void**)&w1l, d_W1p_lo);
    cudaGetSymbolAddress((void**)&u1h, d_U1p_hi);
    cudaGetSymbolAddress((void**)&u1l, d_U1p_lo);
    cudaGetSymbolAddress((void**)&wch, d_WCp_hi);
    cudaGetSymbolAddress((void**)&wcl, d_WCp_lo);
    cudaGetSymbolAddress((void**)&fch, d_FCt_hi);
    cudaGetSymbolAddress((void**)&fcl, d_FCt_lo);

    cudaFuncSetAttribute(gemm_f16s, cudaFuncAttributeMaxDynamicSharedMemorySize, GSM_BYTES);

    init_state<<<(BATCH * 1024 / 2) / 256, 256>>>(
        (uint32_t*)cat_hi[0], (uint32_t*)cat_lo[0],
        (uint32_t*)cat_hi[1], (uint32_t*)cat_lo[1], c1, c2);
    prep_weights<<<(PREP_TOTAL + 255) / 256, 256>>>(W1, U1, W2, U2, fcw, b1, b2,
                                                    w1h, w1l, u1h, u1l, wch, wcl,
                                                    fch, fcl, pb1, pb2);
    conv1_pool<<<BATCH, 256>>>(x, c1w, c1b, pool1);
    conv2_pool_split<<<BATCH, 256>>>(pool1, c2w, c2b, shi, slo);

    // zx = seq @ W1p : [28672,192] x [192,2048] (permuted cols)
    {
        dim3 g(G4 / 128, BT / 128);
        gemm_f16s<<<g, 256, GSM_BYTES>>>(BT, G4, FEATP, shi, slo, FEATP,
                                         w1h, w1l, FEATP, zx, G4,
                                         nullptr, 0, nullptr, 0,
                                         0, nullptr, nullptr, nullptr, 0);
    }

    dim3 ga(G4 / 128, BATCH / 128);
    for (int t = 0; t < SEQLEN; t++) {
        int p = t & 1;
        // layer 1: reads cat[p], writes h1_t -> cat[1-p][:, 0:512]
        gemm_f16s<<<ga, 256, GSM_BYTES>>>(BATCH, G4, HID, cat_hi[p], cat_lo[p], 1024,
                                          u1h, u1l, HID, nullptr, 0,
                                          zx + t * G4, SEQLEN * G4, pb1, 0,
                                          1, c1, cat_hi[1 - p], cat_lo[1 - p], 0);
        // layer 2: reads cat[1-p], writes h2_t -> cat[p][:, 512:1024]
        gemm_f16s<<<ga, 256, GSM_BYTES>>>(BATCH, G4, 1024, cat_hi[1 - p], cat_lo[1 - p], 1024,
                                          wch, wcl, 1024, nullptr, 0,
                                          nullptr, 0, pb2, 0,
                                          1, c2, cat_hi[p], cat_lo[p], HID);
    }

    // FC head: relu(h2 @ fc_w + fc_b); final h2 lives in cat[0]
    {
        int pf = (SEQLEN - 1) & 1;
        dim3 gf(NCLS / 128, BATCH / 128);
        gemm_f16s<<<gf, 256, GSM_BYTES>>>(BATCH, NCLS, HID,
                                          cat_hi[pf] + HID, cat_lo[pf] + HID, 1024,
                                          fch, fcl, HID, out, NCLS,
                                          nullptr, 0, fcb, 1,
                                          0, nullptr, nullptr, nullptr, 0);
    }
}

// round 9
// speedup vs baseline: 1.4311x; 1.3418x over previous
#include <cuda_runtime.h>
#include <cuda_fp16.h>
#include <cstdint>
#include <math.h>

#define BATCH 4096
#define HID 512
#define SEQLEN 7
#define FEATP 192            // padded feature dim (160 -> 192)
#define G4 2048              // 4*HID
#define NCLS 256
#define BT (BATCH * SEQLEN)  // 28672

// ---------------------------------------------------------------------------
// scratch (device globals)
// ---------------------------------------------------------------------------
__device__ __align__(16) float d_pool1[BATCH * 9 * 26 * 10];
__device__ __align__(16) __half d_seq[BT * FEATP];
__device__ __align__(16) float d_zx[BT * G4];
// ping-pong cat buffers: [h1|h2] fp16 (race-free fused epilogue)
__device__ __align__(16) __half d_cat0[BATCH * 1024];
__device__ __align__(16) __half d_cat1[BATCH * 1024];
__device__ __align__(16) float d_c1[BATCH * HID];
__device__ __align__(16) float d_c2[BATCH * HID];
// weights: transposed [N,K], gate-permuted cols (col' = 4j+g), fp16 hi/lo
__device__ __align__(16) __half d_W1p_hi[G4 * FEATP];
__device__ __align__(16) __half d_W1p_lo[G4 * FEATP];
__device__ __align__(16) __half d_U1p_hi[G4 * HID];
__device__ __align__(16) __half d_U1p_lo[G4 * HID];
__device__ __align__(16) __half d_WCp_hi[G4 * 1024];
__device__ __align__(16) __half d_WCp_lo[G4 * 1024];
__device__ __align__(16) __half d_FCt_hi[NCLS * HID];
__device__ __align__(16) __half d_FCt_lo[NCLS * HID];
__device__ __align__(16) float d_pb1[G4];                     // permuted biases
__device__ __align__(16) float d_pb2[G4];

// ---------------------------------------------------------------------------
// init: zero recurrent state
// ---------------------------------------------------------------------------
__global__ void init_state(uint32_t* __restrict__ c0, uint32_t* __restrict__ c1h,
                           float* __restrict__ c1, float* __restrict__ c2) {
    int i = blockIdx.x * blockDim.x + threadIdx.x;  // 0..2M-1
    c0[i] = 0u;      // BATCH*1024 halves = 2M u32
    c1h[i] = 0u;
    c1[i] = 0.0f;
    c2[i] = 0.0f;
}

// ---------------------------------------------------------------------------
// weight prep: transpose + gate-permute + fp16 hi/lo split + permuted biases
// ---------------------------------------------------------------------------
#define PREP_W1 (G4 * FEATP)
#define PREP_U1 (G4 * HID)
#define PREP_WC (G4 * 1024)
#define PREP_FC (NCLS * HID)
#define PREP_PB (2 * G4)
#define PREP_TOTAL (PREP_W1 + PREP_U1 + PREP_WC + PREP_FC + PREP_PB)

__global__ void prep_weights(const float* __restrict__ W1, const float* __restrict__ U1,
                             const float* __restrict__ W2, const float* __restrict__ U2,
                             const float* __restrict__ FC,
                             const float* __restrict__ b1, const float* __restrict__ b2,
                             __half* __restrict__ w1h, __half* __restrict__ w1l,
                             __half* __restrict__ u1h, __half* __restrict__ u1l,
                             __half* __restrict__ wch, __half* __restrict__ wcl,
                             __half* __restrict__ fch, __half* __restrict__ fcl,
                             float* __restrict__ pb1, float* __restrict__ pb2) {
    int i = blockIdx.x * blockDim.x + threadIdx.x;
    if (i >= PREP_TOTAL) return;
    if (i >= PREP_W1 + PREP_U1 + PREP_WC + PREP_FC) {
        int o = i - (PREP_W1 + PREP_U1 + PREP_WC + PREP_FC);
        int which = o >> 11;
        int np = o & 2047;
        int src = (np & 3) * HID + (np >> 2);
        if (which == 0) pb1[np] = b1[src]; else pb2[np] = b2[src];
        return;
    }
    float v;
    __half *hi, *lo;
    int o;
    if (i < PREP_W1) {
        o = i;
        int np = o / FEATP, k = o % FEATP;
        int n = (np & 3) * HID + (np >> 2);
        v = (k < 160) ? W1[(size_t)k * G4 + n] : 0.0f;
        hi = w1h; lo = w1l;
    } else if (i < PREP_W1 + PREP_U1) {
        o = i - PREP_W1;
        int np = o >> 9, k = o & 511;
        int n = (np & 3) * HID + (np >> 2);
        v = U1[(size_t)k * G4 + n];
        hi = u1h; lo = u1l;
    } else if (i < PREP_W1 + PREP_U1 + PREP_WC) {
        o = i - PREP_W1 - PREP_U1;
        int np = o >> 10, k = o & 1023;
        int n = (np & 3) * HID + (np >> 2);
        v = (k < HID) ? W2[(size_t)k * G4 + n] : U2[(size_t)(k - HID) * G4 + n];
        hi = wch; lo = wcl;
    } else {
        o = i - PREP_W1 - PREP_U1 - PREP_WC;
        int n = o >> 9, k = o & 511;
        v = FC[(size_t)k * NCLS + n];
        hi = fch; lo = fcl;
    }
    __half h = __float2half_rn(v);
    hi[o] = h;
    lo[o] = __float2half_rn(v - __half2float(h));
}

// ---------------------------------------------------------------------------
// conv1 + relu + maxpool(3,3): one block per batch sample
// ---------------------------------------------------------------------------
__global__ __launch_bounds__(256) void conv1_pool(
    const float* __restrict__ x, const float* __restrict__ w,
    const float* __restrict__ bias, float* __restrict__ out) {
    __shared__ float sIn[15 * 80 * 3];   // 3600
    __shared__ float sW[7 * 3 * 3 * 10]; // 630
    int b = blockIdx.x;
    const float* xb = x + (size_t)b * 3600;
    for (int i = threadIdx.x; i < 3600; i += 256) sIn[i] = xb[i];
    for (int i = threadIdx.x; i < 630; i += 256) sW[i] = w[i];
    __syncthreads();
    for (int item = threadIdx.x; item < 9 * 260; item += 256) {
        int r = item / 260;
        int rem = item - r * 260;
        int p = rem / 10, co = rem - p * 10;
        float best = -1e30f;
#pragma unroll
        for (int dx = 0; dx < 3; dx++) {
            int cw = p * 3 + dx;
            float acc = 0.0f;
#pragma unroll
            for (int kh = 0; kh < 7; kh++)
#pragma unroll
                for (int kw = 0; kw < 3; kw++)
#pragma unroll
                    for (int ci = 0; ci < 3; ci++)
                        acc += sIn[(r + kh) * 240 + (cw + kw) * 3 + ci] *
                               sW[((kh * 3 + kw) * 3 + ci) * 10 + co];
            best = fmaxf(best, acc);
        }
        out[((size_t)(b * 9 + r) * 26 + p) * 10 + co] = fmaxf(best + bias[co], 0.0f);
    }
}

// ---------------------------------------------------------------------------
// conv2 + relu + maxpool(3,3) -> seq fp16 (padded to 192); block = sample
// ---------------------------------------------------------------------------
__global__ __launch_bounds__(256) void conv2_pool_h(
    const float* __restrict__ in, const float* __restrict__ w,
    const float* __restrict__ bias, __half* __restrict__ sh) {
    __shared__ float sIn[9 * 26 * 10];    // 2340
    __shared__ float sW[3 * 3 * 10 * 20]; // 1800
    int b = blockIdx.x;
    const float* inb = in + (size_t)b * 2340;
    for (int i = threadIdx.x; i < 2340; i += 256) sIn[i] = inb[i];
    for (int i = threadIdx.x; i < 1800; i += 256) sW[i] = w[i];
    __syncthreads();
    for (int item = threadIdx.x; item < 7 * 160; item += 256) {
        int r = item / 160;
        int f = item - r * 160;
        int p = f / 20, co = f - p * 20;
        float best = -1e30f;
#pragma unroll
        for (int dx = 0; dx < 3; dx++) {
            int cw = p * 3 + dx;
            float acc = 0.0f;
#pragma unroll
            for (int kh = 0; kh < 3; kh++)
#pragma unroll
                for (int kw = 0; kw < 3; kw++)
#pragma unroll
                    for (int ci = 0; ci < 10; ci++)
                        acc += sIn[(r + kh) * 260 + (cw + kw) * 10 + ci] *
                               sW[((kh * 3 + kw) * 10 + ci) * 20 + co];
            best = fmaxf(best, acc);
        }
        float v = fmaxf(best + bias[co], 0.0f);
        sh[(size_t)(b * 7 + r) * FEATP + f] = __float2half_rn(v);
    }
    for (int i = threadIdx.x; i < 7 * 32; i += 256) {
        int r = i >> 5;
        sh[(size_t)(b * 7 + r) * FEATP + 160 + (i & 31)] = __float2half_rn(0.0f);
    }
}

// ---------------------------------------------------------------------------
// fp16 2-pass GEMM: C = A @ (Bhi+Blo)^T,  A single fp16 [M,K], B stored [N,K]
// tile 128x128, BK=32, ldmatrix, 2 CTAs/SM; gate mode = fused LSTM epilogue
// (staged through SMEM for fully coalesced cbuf / cat access).
// ---------------------------------------------------------------------------
#define ROWB 80
#define TILE_B (128 * ROWB)          // 10240
#define STAGE_B (3 * TILE_B)         // A | Bh | Bl = 30720
#define EPI_BYTES (128 * 132 * 4)    // 67584
#define GSM_BYTES EPI_BYTES          // >= 2*STAGE_B (61440)
#define EPI_PITCH 132

__device__ __forceinline__ uint32_t smem_u32(const void* p) {
    uint32_t a;
    asm("{ .reg .u64 t; cvta.to.shared.u64 t, %1; cvt.u32.u64 %0, t; }" : "=r"(a) : "l"(p));
    return a;
}
__device__ __forceinline__ void cp_async16(uint32_t sa, const void* gaddr) {
    asm volatile("cp.async.cg.shared.global [%0], [%1], 16;" :: "r"(sa), "l"(gaddr) : "memory");
}
__device__ __forceinline__ void ldmx4(uint32_t* r, uint32_t sa) {
    asm volatile("ldmatrix.sync.aligned.m8n8.x4.shared.b16 {%0,%1,%2,%3}, [%4];"
                 : "=r"(r[0]), "=r"(r[1]), "=r"(r[2]), "=r"(r[3]) : "r"(sa));
}
__device__ __forceinline__ void mma_f16(float* c, const uint32_t* a, uint32_t b0, uint32_t b1) {
    asm volatile(
        "mma.sync.aligned.m16n8k16.row.col.f32.f16.f16.f32 "
        "{%0,%1,%2,%3}, {%4,%5,%6,%7}, {%8,%9}, {%0,%1,%2,%3};"
        : "+f"(c[0]), "+f"(c[1]), "+f"(c[2]), "+f"(c[3])
        : "r"(a[0]), "r"(a[1]), "r"(a[2]), "r"(a[3]), "r"(b0), "r"(b1));
}
__device__ __forceinline__ float sigacc(float x) { return 1.0f / (1.0f + expf(-x)); }

__global__ __launch_bounds__(256, 2) void gemm_f16s(
    int M, int N, int K,
    const __half* __restrict__ A, int lda,
    const __half* __restrict__ Bhi, const __half* __restrict__ Blo, int ldb,
    float* __restrict__ C, int ldc,
    const float* __restrict__ Cadd, int ldca,
    const float* __restrict__ bias, int relu,
    int gate, float* __restrict__ cbuf,
    __half* __restrict__ hout, int hoff) {
    extern __shared__ char smem[];
    uint32_t sb0 = smem_u32(smem);
    int tid = threadIdx.x;
    int lane = tid & 31;
    int warp = tid >> 5;
    int wm = warp >> 1;
    int wn = warp & 1;
    int gid = lane >> 2;
    int tig = lane & 3;
    int lane15 = lane & 15;
    int halfsel = (lane >> 4) << 4;

    int bm = blockIdx.y * 128;
    int bn = blockIdx.x * 128;

    const __half* A0 = A + (size_t)bm * lda;
    const __half* Bh0 = Bhi + (size_t)bn * ldb;
    const __half* Bl0 = Blo + (size_t)bn * ldb;

    float acc[2][8][4];
#pragma unroll
    for (int i = 0; i < 2; i++)
#pragma unroll
        for (int j = 0; j < 8; j++)
#pragma unroll
            for (int r = 0; r < 4; r++) acc[i][j][r] = 0.0f;

    int nst = K >> 5;

#define ISSUE_STAGE(kt, buf) do {                                              \
        uint32_t st = sb0 + (buf) * STAGE_B;                                   \
        int k0 = (kt) << 5;                                                    \
        _Pragma("unroll")                                                      \
        for (int i = 0; i < 2; i++) {                                          \
            int ch = tid + i * 256;                                            \
            int row = ch >> 2, c4 = ch & 3;                                    \
            uint32_t sa = st + row * ROWB + c4 * 16;                           \
            cp_async16(sa,              A0  + (size_t)row * lda + k0 + c4 * 8);\
            cp_async16(sa + TILE_B,     Bh0 + (size_t)row * ldb + k0 + c4 * 8);\
            cp_async16(sa + 2 * TILE_B, Bl0 + (size_t)row * ldb + k0 + c4 * 8);\
        }                                                                      \
        asm volatile("cp.async.commit_group;" ::: "memory");                   \
    } while (0)

    ISSUE_STAGE(0, 0);

    for (int kt = 0; kt < nst; kt++) {
        int buf = kt & 1;
        if (kt + 1 < nst) {
            ISSUE_STAGE(kt + 1, buf ^ 1);
            asm volatile("cp.async.wait_group 1;" ::: "memory");
        } else {
            asm volatile("cp.async.wait_group 0;" ::: "memory");
        }
        __syncthreads();

        uint32_t st = sb0 + buf * STAGE_B;
        uint32_t aAddr = st + (uint32_t)((wm * 32 + lane15) * ROWB) + halfsel;
        uint32_t bAddr = st + TILE_B + (uint32_t)((wn * 64 + lane15) * ROWB) + halfsel;

#pragma unroll
        for (int k16 = 0; k16 < 2; k16++) {
            uint32_t kb = k16 * 32;
            uint32_t af[2][4];
#pragma unroll
            for (int ma = 0; ma < 2; ma++)
                ldmx4(af[ma], aAddr + ma * (16 * ROWB) + kb);
#pragma unroll
            for (int nb = 0; nb < 4; nb++) {
                uint32_t bh[4], bl[4];
                ldmx4(bh, bAddr + nb * (16 * ROWB) + kb);
                ldmx4(bl, bAddr + TILE_B + nb * (16 * ROWB) + kb);
#pragma unroll
                for (int hf = 0; hf < 2; hf++) {
                    int na = nb * 2 + hf;
                    uint32_t b0h = bh[hf], b1h = bh[2 + hf];
                    uint32_t b0l = bl[hf], b1l = bl[2 + hf];
#pragma unroll
                    for (int ma = 0; ma < 2; ma++) {
                        mma_f16(acc[ma][na], af[ma], b0h, b1h);
                        mma_f16(acc[ma][na], af[ma], b0l, b1l);
                    }
                }
            }
        }
        __syncthreads();
    }

    // ---- epilogue ----
    if (gate) {
        float* sg = (float*)smem;
#pragma unroll
        for (int ma = 0; ma < 2; ma++) {
#pragma unroll
            for (int na = 0; na < 8; na++) {
                int rl = wm * 32 + ma * 16 + gid;
                int cl = wn * 64 + na * 8 + 2 * tig;
                int row0 = bm + rl;
                int col0 = bn + cl;
                float v0 = acc[ma][na][0], v1 = acc[ma][na][1];
                float v2 = acc[ma][na][2], v3 = acc[ma][na][3];
                if (Cadd) {
                    float2 ca = *(const float2*)(Cadd + (size_t)row0 * ldca + col0);
                    float2 cb = *(const float2*)(Cadd + (size_t)(row0 + 8) * ldca + col0);
                    v0 += ca.x; v1 += ca.y; v2 += cb.x; v3 += cb.y;
                }
                float bb0 = bias[col0], bb1 = bias[col0 + 1];
                *(float2*)&sg[rl * EPI_PITCH + cl] = make_float2(v0 + bb0, v1 + bb1);
                *(float2*)&sg[(rl + 8) * EPI_PITCH + cl] = make_float2(v2 + bb0, v3 + bb1);
            }
        }
        __syncthreads();
        int jb = bn >> 2;
#pragma unroll
        for (int it = 0; it < 16; it++) {
            int idx = it * 256 + tid;
            int rl = idx >> 5, jl = idx & 31;
            float4 g = *(const float4*)&sg[rl * EPI_PITCH + jl * 4];
            int grow = bm + rl;
            int j = jb + jl;
            size_t cidx = (size_t)grow * HID + j;
            float cv = sigacc(g.y) * cbuf[cidx] + sigacc(g.x) * tanhf(g.z);
            cbuf[cidx] = cv;
            float h = sigacc(g.w) * tanhf(cv);
            hout[(size_t)grow * 1024 + hoff + j] = __float2half_rn(h);
        }
    } else {
#pragma unroll
        for (int ma = 0; ma < 2; ma++) {
#pragma unroll
            for (int na = 0; na < 8; na++) {
                int row0 = bm + wm * 32 + ma * 16 + gid;
                int col = bn + wn * 64 + na * 8 + 2 * tig;
                float v0 = acc[ma][na][0], v1 = acc[ma][na][1];
                float v2 = acc[ma][na][2], v3 = acc[ma][na][3];
                if (bias) {
                    float bb0 = bias[col], bb1 = bias[col + 1];
                    v0 += bb0; v1 += bb1; v2 += bb0; v3 += bb1;
                }
                if (relu) {
                    v0 = fmaxf(v0, 0.0f); v1 = fmaxf(v1, 0.0f);
                    v2 = fmaxf(v2, 0.0f); v3 = fmaxf(v3, 0.0f);
                }
                *(float2*)(C + (size_t)row0 * ldc + col) = make_float2(v0, v1);
                *(float2*)(C + (size_t)(row0 + 8) * ldc + col) = make_float2(v2, v3);
            }
        }
    }
#undef ISSUE_STAGE
}

// ---------------------------------------------------------------------------
// launch
// ---------------------------------------------------------------------------
extern "C" void kernel_launch(void* const* d_in, const int* in_sizes, int n_in,
                              void* d_out, int out_size) {
    const float* x = (const float*)d_in[0];
    const float* c1w = (const float*)d_in[1];
    const float* c1b = (const float*)d_in[2];
    const float* c2w = (const float*)d_in[3];
    const float* c2b = (const float*)d_in[4];
    const float* W1 = (const float*)d_in[5];
    const float* U1 = (const float*)d_in[6];
    const float* b1 = (const float*)d_in[7];
    const float* W2 = (const float*)d_in[8];
    const float* U2 = (const float*)d_in[9];
    const float* b2 = (const float*)d_in[10];
    const float* fcw = (const float*)d_in[11];
    const float* fcb = (const float*)d_in[12];
    float* out = (float*)d_out;

    float *pool1, *zx, *c1, *c2, *pb1, *pb2;
    __half *seqh;
    __half *cat[2];
    __half *w1h, *w1l, *u1h, *u1l, *wch, *wcl, *fch, *fcl;
    cudaGetSymbolAddress((void**)&pool1, d_pool1);
    cudaGetSymbolAddress((void**)&zx, d_zx);
    cudaGetSymbolAddress((void**)&c1, d_c1);
    cudaGetSymbolAddress((void**)&c2, d_c2);
    cudaGetSymbolAddress((void**)&pb1, d_pb1);
    cudaGetSymbolAddress((void**)&pb2, d_pb2);
    cudaGetSymbolAddress((void**)&seqh, d_seq);
    cudaGetSymbolAddress((void**)&cat[0], d_cat0);
    cudaGetSymbolAddress((void**)&cat[1], d_cat1);
    cudaGetSymbolAddress((void**)&w1h, d_W1p_hi);
    cudaGetSymbolAddress((void**)&w1l, d_W1p_lo);
    cudaGetSymbolAddress((void**)&u1h, d_U1p_hi);
    cudaGetSymbolAddress((void**)&u1l, d_U1p_lo);
    cudaGetSymbolAddress((void**)&wch, d_WCp_hi);
    cudaGetSymbolAddress((void**)&wcl, d_WCp_lo);
    cudaGetSymbolAddress((void**)&fch, d_FCt_hi);
    cudaGetSymbolAddress((void**)&fcl, d_FCt_lo);

    cudaFuncSetAttribute(gemm_f16s, cudaFuncAttributeMaxDynamicSharedMemorySize, GSM_BYTES);

    init_state<<<(BATCH * 1024 / 2) / 256, 256>>>(
        (uint32_t*)cat[0], (uint32_t*)cat[1], c1, c2);
    prep_weights<<<(PREP_TOTAL + 255) / 256, 256>>>(W1, U1, W2, U2, fcw, b1, b2,
                                                    w1h, w1l, u1h, u1l, wch, wcl,
                                                    fch, fcl, pb1, pb2);
    conv1_pool<<<BATCH, 256>>>(x, c1w, c1b, pool1);
    conv2_pool_h<<<BATCH, 256>>>(pool1, c2w, c2b, seqh);

    // zx = seq @ W1p : [28672,192] x [192,2048] (permuted cols)
    {
        dim3 g(G4 / 128, BT / 128);
        gemm_f16s<<<g, 256, GSM_BYTES>>>(BT, G4, FEATP, seqh, FEATP,
                                         w1h, w1l, FEATP, zx, G4,
                                         nullptr, 0, nullptr, 0,
                                         0, nullptr, nullptr, 0);
    }

    dim3 ga(G4 / 128, BATCH / 128);
    for (int t = 0; t < SEQLEN; t++) {
        int p = t & 1;
        // layer 1: reads cat[p], writes h1_t -> cat[1-p][:, 0:512]
        gemm_f16s<<<ga, 256, GSM_BYTES>>>(BATCH, G4, HID, cat[p], 1024,
                                          u1h, u1l, HID, nullptr, 0,
                                          zx + t * G4, SEQLEN * G4, pb1, 0,
                                          1, c1, cat[1 - p], 0);
        // layer 2: reads cat[1-p], writes h2_t -> cat[p][:, 512:1024]
        gemm_f16s<<<ga, 256, GSM_BYTES>>>(BATCH, G4, 1024, cat[1 - p], 1024,
                                          wch, wcl, 1024, nullptr, 0,
                                          nullptr, 0, pb2, 0,
                                          1, c2, cat[p], HID);
    }

    // FC head: relu(h2 @ fc_w + fc_b); final h2 lives in cat[0]
    {
        int pf = (SEQLEN - 1) & 1;
        dim3 gf(NCLS / 128, BATCH / 128);
        gemm_f16s<<<gf, 256, GSM_BYTES>>>(BATCH, NCLS, HID,
                                          cat[pf] + HID, 1024,
                                          fch, fcl, HID, out, NCLS,
                                          nullptr, 0, fcb, 1,
                                          0, nullptr, nullptr, 0);
    }
}

// round 10
// speedup vs baseline: 1.9955x; 1.3944x over previous
#include <cuda_runtime.h>
#include <cuda_fp16.h>
#include <cstdint>
#include <math.h>

#define BATCH 4096
#define HID 512
#define SEQLEN 7
#define FEATP 192            // padded feature dim (160 -> 192)
#define G4 2048              // 4*HID
#define NCLS 256
#define BT (BATCH * SEQLEN)  // 28672

// ---------------------------------------------------------------------------
// scratch (device globals)
// ---------------------------------------------------------------------------
__device__ __align__(16) __half d_seq[BT * FEATP];
__device__ __align__(16) float d_zx[BT * G4];
// ping-pong cat buffers: [h1|h2] fp16 (race-free fused epilogue)
__device__ __align__(16) __half d_cat0[BATCH * 1024];
__device__ __align__(16) __half d_cat1[BATCH * 1024];
__device__ __align__(16) float d_c1[BATCH * HID];
__device__ __align__(16) float d_c2[BATCH * HID];
// weights: transposed [N,K], gate-permuted cols (col' = 4j+g), single fp16
__device__ __align__(16) __half d_W1p[G4 * FEATP];
__device__ __align__(16) __half d_U1p[G4 * HID];
__device__ __align__(16) __half d_WCp[G4 * 1024];
__device__ __align__(16) __half d_FCt[NCLS * HID];
__device__ __align__(16) float d_pb1[G4];                     // permuted biases
__device__ __align__(16) float d_pb2[G4];

// ---------------------------------------------------------------------------
// init: zero recurrent state
// ---------------------------------------------------------------------------
__global__ void init_state(uint32_t* __restrict__ c0, uint32_t* __restrict__ c1h,
                           float* __restrict__ c1, float* __restrict__ c2) {
    int i = blockIdx.x * blockDim.x + threadIdx.x;  // 0..2M-1
    c0[i] = 0u;
    c1h[i] = 0u;
    c1[i] = 0.0f;
    c2[i] = 0.0f;
}

// ---------------------------------------------------------------------------
// weight prep: transpose + gate-permute + fp16 + permuted biases
// ---------------------------------------------------------------------------
#define PREP_W1 (G4 * FEATP)
#define PREP_U1 (G4 * HID)
#define PREP_WC (G4 * 1024)
#define PREP_FC (NCLS * HID)
#define PREP_PB (2 * G4)
#define PREP_TOTAL (PREP_W1 + PREP_U1 + PREP_WC + PREP_FC + PREP_PB)

__global__ void prep_weights(const float* __restrict__ W1, const float* __restrict__ U1,
                             const float* __restrict__ W2, const float* __restrict__ U2,
                             const float* __restrict__ FC,
                             const float* __restrict__ b1, const float* __restrict__ b2,
                             __half* __restrict__ w1p, __half* __restrict__ u1p,
                             __half* __restrict__ wcp, __half* __restrict__ fct,
                             float* __restrict__ pb1, float* __restrict__ pb2) {
    int i = blockIdx.x * blockDim.x + threadIdx.x;
    if (i >= PREP_TOTAL) return;
    if (i >= PREP_W1 + PREP_U1 + PREP_WC + PREP_FC) {
        int o = i - (PREP_W1 + PREP_U1 + PREP_WC + PREP_FC);
        int which = o >> 11;
        int np = o & 2047;
        int src = (np & 3) * HID + (np >> 2);
        if (which == 0) pb1[np] = b1[src]; else pb2[np] = b2[src];
        return;
    }
    float v;
    __half* dst;
    int o;
    if (i < PREP_W1) {
        o = i;
        int np = o / FEATP, k = o % FEATP;
        int n = (np & 3) * HID + (np >> 2);
        v = (k < 160) ? W1[(size_t)k * G4 + n] : 0.0f;
        dst = w1p;
    } else if (i < PREP_W1 + PREP_U1) {
        o = i - PREP_W1;
        int np = o >> 9, k = o & 511;
        int n = (np & 3) * HID + (np >> 2);
        v = U1[(size_t)k * G4 + n];
        dst = u1p;
    } else if (i < PREP_W1 + PREP_U1 + PREP_WC) {
        o = i - PREP_W1 - PREP_U1;
        int np = o >> 10, k = o & 1023;
        int n = (np & 3) * HID + (np >> 2);
        v = (k < HID) ? W2[(size_t)k * G4 + n] : U2[(size_t)(k - HID) * G4 + n];
        dst = wcp;
    } else {
        o = i - PREP_W1 - PREP_U1 - PREP_WC;
        int n = o >> 9, k = o & 511;
        v = FC[(size_t)k * NCLS + n];
        dst = fct;
    }
    dst[o] = __float2half_rn(v);
}

// ---------------------------------------------------------------------------
// fused conv1+pool1+conv2+pool2 -> seq fp16; one block per batch sample.
// pool1 intermediate lives entirely in SMEM (no gmem round-trip).
// ---------------------------------------------------------------------------
__global__ __launch_bounds__(256) void conv12_pool(
    const float* __restrict__ x,
    const float* __restrict__ w1, const float* __restrict__ b1,
    const float* __restrict__ w2, const float* __restrict__ b2,
    __half* __restrict__ sh) {
    __shared__ float sIn[15 * 80 * 3];    // 3600
    __shared__ float sW1[7 * 3 * 3 * 10]; // 630
    __shared__ float sP[9 * 26 * 10];     // 2340
    __shared__ float sW2[3 * 3 * 10 * 20];// 1800
    int b = blockIdx.x;
    const float* xb = x + (size_t)b * 3600;
    for (int i = threadIdx.x; i < 3600; i += 256) sIn[i] = xb[i];
    for (int i = threadIdx.x; i < 630; i += 256) sW1[i] = w1[i];
    for (int i = threadIdx.x; i < 1800; i += 256) sW2[i] = w2[i];
    __syncthreads();

    // stage 1: conv1 + relu + maxpool(3,3) -> sP [9][26][10]
    for (int item = threadIdx.x; item < 9 * 260; item += 256) {
        int r = item / 260;
        int rem = item - r * 260;
        int p = rem / 10, co = rem - p * 10;
        float best = -1e30f;
#pragma unroll
        for (int dx = 0; dx < 3; dx++) {
            int cw = p * 3 + dx;
            float acc = 0.0f;
#pragma unroll
            for (int kh = 0; kh < 7; kh++)
#pragma unroll
                for (int kw = 0; kw < 3; kw++)
#pragma unroll
                    for (int ci = 0; ci < 3; ci++)
                        acc += sIn[(r + kh) * 240 + (cw + kw) * 3 + ci] *
                               sW1[((kh * 3 + kw) * 3 + ci) * 10 + co];
            best = fmaxf(best, acc);
        }
        sP[(r * 26 + p) * 10 + co] = fmaxf(best + b1[co], 0.0f);
    }
    __syncthreads();

    // stage 2: conv2 + relu + maxpool(3,3) -> seq [7][160] + pad to 192
    for (int item = threadIdx.x; item < 7 * 160; item += 256) {
        int r = item / 160;
        int f = item - r * 160;
        int p = f / 20, co = f - p * 20;
        float best = -1e30f;
#pragma unroll
        for (int dx = 0; dx < 3; dx++) {
            int cw = p * 3 + dx;
            float acc = 0.0f;
#pragma unroll
            for (int kh = 0; kh < 3; kh++)
#pragma unroll
                for (int kw = 0; kw < 3; kw++)
#pragma unroll
                    for (int ci = 0; ci < 10; ci++)
                        acc += sP[((r + kh) * 26 + (cw + kw)) * 10 + ci] *
                               sW2[((kh * 3 + kw) * 10 + ci) * 20 + co];
            best = fmaxf(best, acc);
        }
        float v = fmaxf(best + b2[co], 0.0f);
        sh[(size_t)(b * 7 + r) * FEATP + f] = __float2half_rn(v);
    }
    for (int i = threadIdx.x; i < 7 * 32; i += 256) {
        int r = i >> 5;
        sh[(size_t)(b * 7 + r) * FEATP + 160 + (i & 31)] = __float2half_rn(0.0f);
    }
}

// ---------------------------------------------------------------------------
// fp16 1-pass GEMM: C = A @ B^T,  A fp16 [M,K], B fp16 [N,K]
// tile 128x128, BK=32, ldmatrix, 2 CTAs/SM; gate mode = fused LSTM epilogue
// staged through SMEM for coalesced cbuf / cat access.
// ---------------------------------------------------------------------------
#define ROWB 80
#define TILE_B (128 * ROWB)          // 10240
#define STAGE_B (2 * TILE_B)         // A | B = 20480
#define EPI_BYTES (128 * 132 * 4)    // 67584
#define GSM_BYTES EPI_BYTES          // >= 2*STAGE_B (40960)
#define EPI_PITCH 132

__device__ __forceinline__ uint32_t smem_u32(const void* p) {
    uint32_t a;
    asm("{ .reg .u64 t; cvta.to.shared.u64 t, %1; cvt.u32.u64 %0, t; }" : "=r"(a) : "l"(p));
    return a;
}
__device__ __forceinline__ void cp_async16(uint32_t sa, const void* gaddr) {
    asm volatile("cp.async.cg.shared.global [%0], [%1], 16;" :: "r"(sa), "l"(gaddr) : "memory");
}
__device__ __forceinline__ void ldmx4(uint32_t* r, uint32_t sa) {
    asm volatile("ldmatrix.sync.aligned.m8n8.x4.shared.b16 {%0,%1,%2,%3}, [%4];"
                 : "=r"(r[0]), "=r"(r[1]), "=r"(r[2]), "=r"(r[3]) : "r"(sa));
}
__device__ __forceinline__ void mma_f16(float* c, const uint32_t* a, uint32_t b0, uint32_t b1) {
    asm volatile(
        "mma.sync.aligned.m16n8k16.row.col.f32.f16.f16.f32 "
        "{%0,%1,%2,%3}, {%4,%5,%6,%7}, {%8,%9}, {%0,%1,%2,%3};"
        : "+f"(c[0]), "+f"(c[1]), "+f"(c[2]), "+f"(c[3])
        : "r"(a[0]), "r"(a[1]), "r"(a[2]), "r"(a[3]), "r"(b0), "r"(b1));
}
__device__ __forceinline__ float sigacc(float x) { return 1.0f / (1.0f + expf(-x)); }

__global__ __launch_bounds__(256, 2) void gemm_f16(
    int M, int N, int K,
    const __half* __restrict__ A, int lda,
    const __half* __restrict__ B, int ldb,
    float* __restrict__ C, int ldc,
    const float* __restrict__ Cadd, int ldca,
    const float* __restrict__ bias, int relu,
    int gate, float* __restrict__ cbuf,
    __half* __restrict__ hout, int hoff) {
    extern __shared__ char smem[];
    uint32_t sb0 = smem_u32(smem);
    int tid = threadIdx.x;
    int lane = tid & 31;
    int warp = tid >> 5;
    int wm = warp >> 1;
    int wn = warp & 1;
    int gid = lane >> 2;
    int tig = lane & 3;
    int lane15 = lane & 15;
    int halfsel = (lane >> 4) << 4;

    int bm = blockIdx.y * 128;
    int bn = blockIdx.x * 128;

    const __half* A0 = A + (size_t)bm * lda;
    const __half* B0 = B + (size_t)bn * ldb;

    float acc[2][8][4];
#pragma unroll
    for (int i = 0; i < 2; i++)
#pragma unroll
        for (int j = 0; j < 8; j++)
#pragma unroll
            for (int r = 0; r < 4; r++) acc[i][j][r] = 0.0f;

    int nst = K >> 5;

#define ISSUE_STAGE(kt, buf) do {                                              \
        uint32_t st = sb0 + (buf) * STAGE_B;                                   \
        int k0 = (kt) << 5;                                                    \
        _Pragma("unroll")                                                      \
        for (int i = 0; i < 2; i++) {                                          \
            int ch = tid + i * 256;                                            \
            int row = ch >> 2, c4 = ch & 3;                                    \
            uint32_t sa = st + row * ROWB + c4 * 16;                           \
            cp_async16(sa,          A0 + (size_t)row * lda + k0 + c4 * 8);     \
            cp_async16(sa + TILE_B, B0 + (size_t)row * ldb + k0 + c4 * 8);     \
        }                                                                      \
        asm volatile("cp.async.commit_group;" ::: "memory");                   \
    } while (0)

    ISSUE_STAGE(0, 0);

    for (int kt = 0; kt < nst; kt++) {
        int buf = kt & 1;
        if (kt + 1 < nst) {
            ISSUE_STAGE(kt + 1, buf ^ 1);
            asm volatile("cp.async.wait_group 1;" ::: "memory");
        } else {
            asm volatile("cp.async.wait_group 0;" ::: "memory");
        }
        __syncthreads();

        uint32_t st = sb0 + buf * STAGE_B;
        uint32_t aAddr = st + (uint32_t)((wm * 32 + lane15) * ROWB) + halfsel;
        uint32_t bAddr = st + TILE_B + (uint32_t)((wn * 64 + lane15) * ROWB) + halfsel;

#pragma unroll
        for (int k16 = 0; k16 < 2; k16++) {
            uint32_t kb = k16 * 32;
            uint32_t af[2][4];
#pragma unroll
            for (int ma = 0; ma < 2; ma++)
                ldmx4(af[ma], aAddr + ma * (16 * ROWB) + kb);
#pragma unroll
            for (int nb = 0; nb < 4; nb++) {
                uint32_t bh[4];
                ldmx4(bh, bAddr + nb * (16 * ROWB) + kb);
#pragma unroll
                for (int hf = 0; hf < 2; hf++) {
                    int na = nb * 2 + hf;
#pragma unroll
                    for (int ma = 0; ma < 2; ma++)
                        mma_f16(acc[ma][na], af[ma], bh[hf], bh[2 + hf]);
                }
            }
        }
        __syncthreads();
    }

    // ---- epilogue ----
    if (gate) {
        float* sg = (float*)smem;
#pragma unroll
        for (int ma = 0; ma < 2; ma++) {
#pragma unroll
            for (int na = 0; na < 8; na++) {
                int rl = wm * 32 + ma * 16 + gid;
                int cl = wn * 64 + na * 8 + 2 * tig;
                int row0 = bm + rl;
                int col0 = bn + cl;
                float v0 = acc[ma][na][0], v1 = acc[ma][na][1];
                float v2 = acc[ma][na][2], v3 = acc[ma][na][3];
                if (Cadd) {
                    float2 ca = *(const float2*)(Cadd + (size_t)row0 * ldca + col0);
                    float2 cb = *(const float2*)(Cadd + (size_t)(row0 + 8) * ldca + col0);
                    v0 += ca.x; v1 += ca.y; v2 += cb.x; v3 += cb.y;
                }
                float bb0 = bias[col0], bb1 = bias[col0 + 1];
                *(float2*)&sg[rl * EPI_PITCH + cl] = make_float2(v0 + bb0, v1 + bb1);
                *(float2*)&sg[(rl + 8) * EPI_PITCH + cl] = make_float2(v2 + bb0, v3 + bb1);
            }
        }
        __syncthreads();
        int jb = bn >> 2;
#pragma unroll
        for (int it = 0; it < 16; it++) {
            int idx = it * 256 + tid;
            int rl = idx >> 5, jl = idx & 31;
            float4 g = *(const float4*)&sg[rl * EPI_PITCH + jl * 4];
            int grow = bm + rl;
            int j = jb + jl;
            size_t cidx = (size_t)grow * HID + j;
            float cv = sigacc(g.y) * cbuf[cidx] + sigacc(g.x) * tanhf(g.z);
            cbuf[cidx] = cv;
            float h = sigacc(g.w) * tanhf(cv);
            hout[(size_t)grow * 1024 + hoff + j] = __float2half_rn(h);
        }
    } else {
#pragma unroll
        for (int ma = 0; ma < 2; ma++) {
#pragma unroll
            for (int na = 0; na < 8; na++) {
                int row0 = bm + wm * 32 + ma * 16 + gid;
                int col = bn + wn * 64 + na * 8 + 2 * tig;
                float v0 = acc[ma][na][0], v1 = acc[ma][na][1];
                float v2 = acc[ma][na][2], v3 = acc[ma][na][3];
                if (bias) {
                    float bb0 = bias[col], bb1 = bias[col + 1];
                    v0 += bb0; v1 += bb1; v2 += bb0; v3 += bb1;
                }
                if (relu) {
                    v0 = fmaxf(v0, 0.0f); v1 = fmaxf(v1, 0.0f);
                    v2 = fmaxf(v2, 0.0f); v3 = fmaxf(v3, 0.0f);
                }
                *(float2*)(C + (size_t)row0 * ldc + col) = make_float2(v0, v1);
                *(float2*)(C + (size_t)(row0 + 8) * ldc + col) = make_float2(v2, v3);
            }
        }
    }
#undef ISSUE_STAGE
}

// ---------------------------------------------------------------------------
// launch
// ---------------------------------------------------------------------------
extern "C" void kernel_launch(void* const* d_in, const int* in_sizes, int n_in,
                              void* d_out, int out_size) {
    const float* x = (const float*)d_in[0];
    const float* c1w = (const float*)d_in[1];
    const float* c1b = (const float*)d_in[2];
    const float* c2w = (const float*)d_in[3];
    const float* c2b = (const float*)d_in[4];
    const float* W1 = (const float*)d_in[5];
    const float* U1 = (const float*)d_in[6];
    const float* b1 = (const float*)d_in[7];
    const float* W2 = (const float*)d_in[8];
    const float* U2 = (const float*)d_in[9];
    const float* b2 = (const float*)d_in[10];
    const float* fcw = (const float*)d_in[11];
    const float* fcb = (const float*)d_in[12];
    float* out = (float*)d_out;

    float *zx, *c1, *c2, *pb1, *pb2;
    __half *seqh;
    __half *cat[2];
    __half *w1p, *u1p, *wcp, *fct;
    cudaGetSymbolAddress((void**)&zx, d_zx);
    cudaGetSymbolAddress((void**)&c1, d_c1);
    cudaGetSymbolAddress((void**)&c2, d_c2);
    cudaGetSymbolAddress((void**)&pb1, d_pb1);
    cudaGetSymbolAddress((void**)&pb2, d_pb2);
    cudaGetSymbolAddress((void**)&seqh, d_seq);
    cudaGetSymbolAddress((void**)&cat[0], d_cat0);
    cudaGetSymbolAddress((void**)&cat[1], d_cat1);
    cudaGetSymbolAddress((void**)&w1p, d_W1p);
    cudaGetSymbolAddress((void**)&u1p, d_U1p);
    cudaGetSymbolAddress((void**)&wcp, d_WCp);
    cudaGetSymbolAddress((void**)&fct, d_FCt);

    cudaFuncSetAttribute(gemm_f16, cudaFuncAttributeMaxDynamicSharedMemorySize, GSM_BYTES);

    init_state<<<(BATCH * 1024 / 2) / 256, 256>>>(
        (uint32_t*)cat[0], (uint32_t*)cat[1], c1, c2);
    prep_weights<<<(PREP_TOTAL + 255) / 256, 256>>>(W1, U1, W2, U2, fcw, b1, b2,
                                                    w1p, u1p, wcp, fct, pb1, pb2);
    conv12_pool<<<BATCH, 256>>>(x, c1w, c1b, c2w, c2b, seqh);

    // zx = seq @ W1p : [28672,192] x [192,2048] (permuted cols)
    {
        dim3 g(G4 / 128, BT / 128);
        gemm_f16<<<g, 256, GSM_BYTES>>>(BT, G4, FEATP, seqh, FEATP,
                                        w1p, FEATP, zx, G4,
                                        nullptr, 0, nullptr, 0,
                                        0, nullptr, nullptr, 0);
    }

    dim3 ga(G4 / 128, BATCH / 128);
    for (int t = 0; t < SEQLEN; t++) {
        int p = t & 1;
        // layer 1: reads cat[p], writes h1_t -> cat[1-p][:, 0:512]
        gemm_f16<<<ga, 256, GSM_BYTES>>>(BATCH, G4, HID, cat[p], 1024,
                                         u1p, HID, nullptr, 0,
                                         zx + t * G4, SEQLEN * G4, pb1, 0,
                                         1, c1, cat[1 - p], 0);
        // layer 2: reads cat[1-p], writes h2_t -> cat[p][:, 512:1024]
        gemm_f16<<<ga, 256, GSM_BYTES>>>(BATCH, G4, 1024, cat[1 - p], 1024,
                                         wcp, 1024, nullptr, 0,
                                         nullptr, 0, pb2, 0,
                                         1, c2, cat[p], HID);
    }

    // FC head: relu(h2 @ fc_w + fc_b); final h2 lives in cat[0]
    {
        int pf = (SEQLEN - 1) & 1;
        dim3 gf(NCLS / 128, BATCH / 128);
        gemm_f16<<<gf, 256, GSM_BYTES>>>(BATCH, NCLS, HID,
                                         cat[pf] + HID, 1024,
                                         fct, HID, out, NCLS,
                                         nullptr, 0, fcb, 1,
                                         0, nullptr, nullptr, 0);
    }
}

// round 11
// speedup vs baseline: 2.0785x; 1.0416x over previous
#include <cuda_runtime.h>
#include <cuda_fp16.h>
#include <cstdint>
#include <math.h>

#define BATCH 4096
#define HID 512
#define SEQLEN 7
#define FEATP 192            // padded feature dim (160 -> 192)
#define G4 2048              // 4*HID
#define NCLS 256
#define BT (BATCH * SEQLEN)  // 28672

// ---------------------------------------------------------------------------
// scratch (device globals)
// ---------------------------------------------------------------------------
__device__ __align__(16) __half d_seq[BT * FEATP];
__device__ __align__(16) float d_zx[BT * G4];
// ping-pong cat buffers: [h1|h2] fp16 (race-free fused epilogue)
__device__ __align__(16) __half d_cat0[BATCH * 1024];
__device__ __align__(16) __half d_cat1[BATCH * 1024];
__device__ __align__(16) float d_c1[BATCH * HID];
__device__ __align__(16) float d_c2[BATCH * HID];
// weights: transposed [N,K], gate-permuted cols (col' = 4j+g), single fp16
__device__ __align__(16) __half d_W1p[G4 * FEATP];
__device__ __align__(16) __half d_U1p[G4 * HID];
__device__ __align__(16) __half d_WCp[G4 * 1024];
__device__ __align__(16) __half d_FCt[NCLS * HID];
__device__ __align__(16) float d_pb1[G4];                     // permuted biases
__device__ __align__(16) float d_pb2[G4];

// ---------------------------------------------------------------------------
// init: zero recurrent state
// ---------------------------------------------------------------------------
__global__ void init_state(uint32_t* __restrict__ c0, uint32_t* __restrict__ c1h,
                           float* __restrict__ c1, float* __restrict__ c2) {
    int i = blockIdx.x * blockDim.x + threadIdx.x;  // 0..2M-1
    c0[i] = 0u;
    c1h[i] = 0u;
    c1[i] = 0.0f;
    c2[i] = 0.0f;
}

// ---------------------------------------------------------------------------
// weight prep: transpose + gate-permute + fp16 + permuted biases
// ---------------------------------------------------------------------------
#define PREP_W1 (G4 * FEATP)
#define PREP_U1 (G4 * HID)
#define PREP_WC (G4 * 1024)
#define PREP_FC (NCLS * HID)
#define PREP_PB (2 * G4)
#define PREP_TOTAL (PREP_W1 + PREP_U1 + PREP_WC + PREP_FC + PREP_PB)

__global__ void prep_weights(const float* __restrict__ W1, const float* __restrict__ U1,
                             const float* __restrict__ W2, const float* __restrict__ U2,
                             const float* __restrict__ FC,
                             const float* __restrict__ b1, const float* __restrict__ b2,
                             __half* __restrict__ w1p, __half* __restrict__ u1p,
                             __half* __restrict__ wcp, __half* __restrict__ fct,
                             float* __restrict__ pb1, float* __restrict__ pb2) {
    int i = blockIdx.x * blockDim.x + threadIdx.x;
    if (i >= PREP_TOTAL) return;
    if (i >= PREP_W1 + PREP_U1 + PREP_WC + PREP_FC) {
        int o = i - (PREP_W1 + PREP_U1 + PREP_WC + PREP_FC);
        int which = o >> 11;
        int np = o & 2047;
        int src = (np & 3) * HID + (np >> 2);
        if (which == 0) pb1[np] = b1[src]; else pb2[np] = b2[src];
        return;
    }
    float v;
    __half* dst;
    int o;
    if (i < PREP_W1) {
        o = i;
        int np = o / FEATP, k = o % FEATP;
        int n = (np & 3) * HID + (np >> 2);
        v = (k < 160) ? W1[(size_t)k * G4 + n] : 0.0f;
        dst = w1p;
    } else if (i < PREP_W1 + PREP_U1) {
        o = i - PREP_W1;
        int np = o >> 9, k = o & 511;
        int n = (np & 3) * HID + (np >> 2);
        v = U1[(size_t)k * G4 + n];
        dst = u1p;
    } else if (i < PREP_W1 + PREP_U1 + PREP_WC) {
        o = i - PREP_W1 - PREP_U1;
        int np = o >> 10, k = o & 1023;
        int n = (np & 3) * HID + (np >> 2);
        v = (k < HID) ? W2[(size_t)k * G4 + n] : U2[(size_t)(k - HID) * G4 + n];
        dst = wcp;
    } else {
        o = i - PREP_W1 - PREP_U1 - PREP_WC;
        int n = o >> 9, k = o & 511;
        v = FC[(size_t)k * NCLS + n];
        dst = fct;
    }
    dst[o] = __float2half_rn(v);
}

// ---------------------------------------------------------------------------
// fused conv1+pool1+conv2+pool2 -> seq fp16; one block per batch sample.
// ---------------------------------------------------------------------------
__global__ __launch_bounds__(256) void conv12_pool(
    const float* __restrict__ x,
    const float* __restrict__ w1, const float* __restrict__ b1,
    const float* __restrict__ w2, const float* __restrict__ b2,
    __half* __restrict__ sh) {
    __shared__ float sIn[15 * 80 * 3];    // 3600
    __shared__ float sW1[7 * 3 * 3 * 10]; // 630
    __shared__ float sP[9 * 26 * 10];     // 2340
    __shared__ float sW2[3 * 3 * 10 * 20];// 1800
    int b = blockIdx.x;
    const float* xb = x + (size_t)b * 3600;
    for (int i = threadIdx.x; i < 3600; i += 256) sIn[i] = xb[i];
    for (int i = threadIdx.x; i < 630; i += 256) sW1[i] = w1[i];
    for (int i = threadIdx.x; i < 1800; i += 256) sW2[i] = w2[i];
    __syncthreads();

    for (int item = threadIdx.x; item < 9 * 260; item += 256) {
        int r = item / 260;
        int rem = item - r * 260;
        int p = rem / 10, co = rem - p * 10;
        float best = -1e30f;
#pragma unroll
        for (int dx = 0; dx < 3; dx++) {
            int cw = p * 3 + dx;
            float acc = 0.0f;
#pragma unroll
            for (int kh = 0; kh < 7; kh++)
#pragma unroll
                for (int kw = 0; kw < 3; kw++)
#pragma unroll
                    for (int ci = 0; ci < 3; ci++)
                        acc += sIn[(r + kh) * 240 + (cw + kw) * 3 + ci] *
                               sW1[((kh * 3 + kw) * 3 + ci) * 10 + co];
            best = fmaxf(best, acc);
        }
        sP[(r * 26 + p) * 10 + co] = fmaxf(best + b1[co], 0.0f);
    }
    __syncthreads();

    for (int item = threadIdx.x; item < 7 * 160; item += 256) {
        int r = item / 160;
        int f = item - r * 160;
        int p = f / 20, co = f - p * 20;
        float best = -1e30f;
#pragma unroll
        for (int dx = 0; dx < 3; dx++) {
            int cw = p * 3 + dx;
            float acc = 0.0f;
#pragma unroll
            for (int kh = 0; kh < 3; kh++)
#pragma unroll
                for (int kw = 0; kw < 3; kw++)
#pragma unroll
                    for (int ci = 0; ci < 10; ci++)
                        acc += sP[((r + kh) * 26 + (cw + kw)) * 10 + ci] *
                               sW2[((kh * 3 + kw) * 10 + ci) * 20 + co];
            best = fmaxf(best, acc);
        }
        float v = fmaxf(best + b2[co], 0.0f);
        sh[(size_t)(b * 7 + r) * FEATP + f] = __float2half_rn(v);
    }
    for (int i = threadIdx.x; i < 7 * 32; i += 256) {
        int r = i >> 5;
        sh[(size_t)(b * 7 + r) * FEATP + 160 + (i & 31)] = __float2half_rn(0.0f);
    }
}

// ---------------------------------------------------------------------------
// fp16 1-pass GEMM: C = A @ B^T. 3-stage cp.async ring, ONE barrier per stage.
// tile 128x128, BK=32, ldmatrix, 2 CTAs/SM; gate mode = fused LSTM epilogue.
// ---------------------------------------------------------------------------
#define ROWB 80
#define TILE_B (128 * ROWB)          // 10240
#define STAGE_B (2 * TILE_B)         // A | B = 20480
#define NSTAGE 3                     // 61440 bytes ring
#define EPI_BYTES (128 * 132 * 4)    // 67584
#define GSM_BYTES EPI_BYTES          // >= NSTAGE*STAGE_B (61440)
#define EPI_PITCH 132

__device__ __forceinline__ uint32_t smem_u32(const void* p) {
    uint32_t a;
    asm("{ .reg .u64 t; cvta.to.shared.u64 t, %1; cvt.u32.u64 %0, t; }" : "=r"(a) : "l"(p));
    return a;
}
__device__ __forceinline__ void cp_async16(uint32_t sa, const void* gaddr) {
    asm volatile("cp.async.cg.shared.global [%0], [%1], 16;" :: "r"(sa), "l"(gaddr) : "memory");
}
__device__ __forceinline__ void ldmx4(uint32_t* r, uint32_t sa) {
    asm volatile("ldmatrix.sync.aligned.m8n8.x4.shared.b16 {%0,%1,%2,%3}, [%4];"
                 : "=r"(r[0]), "=r"(r[1]), "=r"(r[2]), "=r"(r[3]) : "r"(sa));
}
__device__ __forceinline__ void mma_f16(float* c, const uint32_t* a, uint32_t b0, uint32_t b1) {
    asm volatile(
        "mma.sync.aligned.m16n8k16.row.col.f32.f16.f16.f32 "
        "{%0,%1,%2,%3}, {%4,%5,%6,%7}, {%8,%9}, {%0,%1,%2,%3};"
        : "+f"(c[0]), "+f"(c[1]), "+f"(c[2]), "+f"(c[3])
        : "r"(a[0]), "r"(a[1]), "r"(a[2]), "r"(a[3]), "r"(b0), "r"(b1));
}
__device__ __forceinline__ float sigacc(float x) { return 1.0f / (1.0f + expf(-x)); }

__global__ __launch_bounds__(256, 2) void gemm_f16(
    int M, int N, int K,
    const __half* __restrict__ A, int lda,
    const __half* __restrict__ B, int ldb,
    float* __restrict__ C, int ldc,
    const float* __restrict__ Cadd, int ldca,
    const float* __restrict__ bias, int relu,
    int gate, float* __restrict__ cbuf,
    __half* __restrict__ hout, int hoff) {
    extern __shared__ char smem[];
    uint32_t sb0 = smem_u32(smem);
    int tid = threadIdx.x;
    int lane = tid & 31;
    int warp = tid >> 5;
    int wm = warp >> 1;
    int wn = warp & 1;
    int gid = lane >> 2;
    int tig = lane & 3;
    int lane15 = lane & 15;
    int halfsel = (lane >> 4) << 4;

    int bm = blockIdx.y * 128;
    int bn = blockIdx.x * 128;

    const __half* A0 = A + (size_t)bm * lda;
    const __half* B0 = B + (size_t)bn * ldb;

    float acc[2][8][4];
#pragma unroll
    for (int i = 0; i < 2; i++)
#pragma unroll
        for (int j = 0; j < 8; j++)
#pragma unroll
            for (int r = 0; r < 4; r++) acc[i][j][r] = 0.0f;

    int nst = K >> 5;

    // per-thread copy coords (constant across stages)
    int cp_row = tid >> 2, cp_c4 = tid & 3;
    int cp_row2 = (tid + 256) >> 2, cp_c42 = (tid + 256) & 3;

    // issue stage kt's copies into ring slot; ALWAYS commits a group
#define ISSUE_STAGE(kt, slot) do {                                             \
        if ((kt) < nst) {                                                      \
            uint32_t st = sb0 + (slot) * STAGE_B;                              \
            int k0 = (kt) << 5;                                                \
            uint32_t sa = st + cp_row * ROWB + cp_c4 * 16;                     \
            cp_async16(sa,          A0 + (size_t)cp_row * lda + k0 + cp_c4 * 8);\
            cp_async16(sa + TILE_B, B0 + (size_t)cp_row * ldb + k0 + cp_c4 * 8);\
            uint32_t sb = st + cp_row2 * ROWB + cp_c42 * 16;                   \
            cp_async16(sb,          A0 + (size_t)cp_row2 * lda + k0 + cp_c42 * 8);\
            cp_async16(sb + TILE_B, B0 + (size_t)cp_row2 * ldb + k0 + cp_c42 * 8);\
        }                                                                      \
        asm volatile("cp.async.commit_group;" ::: "memory");                   \
    } while (0)

    ISSUE_STAGE(0, 0);
    ISSUE_STAGE(1, 1);

    int slot = 0, slot2 = 2;   // slot = kt%3, slot2 = (kt+2)%3
    for (int kt = 0; kt < nst; kt++) {
        asm volatile("cp.async.wait_group 1;" ::: "memory");
        __syncthreads();
        ISSUE_STAGE(kt + 2, slot2);

        uint32_t st = sb0 + slot * STAGE_B;
        uint32_t aAddr = st + (uint32_t)((wm * 32 + lane15) * ROWB) + halfsel;
        uint32_t bAddr = st + TILE_B + (uint32_t)((wn * 64 + lane15) * ROWB) + halfsel;

#pragma unroll
        for (int k16 = 0; k16 < 2; k16++) {
            uint32_t kb = k16 * 32;
            uint32_t af[2][4];
#pragma unroll
            for (int ma = 0; ma < 2; ma++)
                ldmx4(af[ma], aAddr + ma * (16 * ROWB) + kb);
#pragma unroll
            for (int nb = 0; nb < 4; nb++) {
                uint32_t bh[4];
                ldmx4(bh, bAddr + nb * (16 * ROWB) + kb);
#pragma unroll
                for (int hf = 0; hf < 2; hf++) {
                    int na = nb * 2 + hf;
#pragma unroll
                    for (int ma = 0; ma < 2; ma++)
                        mma_f16(acc[ma][na], af[ma], bh[hf], bh[2 + hf]);
                }
            }
        }
        slot = (slot == 2) ? 0 : slot + 1;
        slot2 = (slot2 == 2) ? 0 : slot2 + 1;
    }
    __syncthreads();   // ring buffers -> epilogue smem reuse

    // ---- epilogue ----
    if (gate) {
        float* sg = (float*)smem;
#pragma unroll
        for (int ma = 0; ma < 2; ma++) {
#pragma unroll
            for (int na = 0; na < 8; na++) {
                int rl = wm * 32 + ma * 16 + gid;
                int cl = wn * 64 + na * 8 + 2 * tig;
                int row0 = bm + rl;
                int col0 = bn + cl;
                float v0 = acc[ma][na][0], v1 = acc[ma][na][1];
                float v2 = acc[ma][na][2], v3 = acc[ma][na][3];
                if (Cadd) {
                    float2 ca = *(const float2*)(Cadd + (size_t)row0 * ldca + col0);
                    float2 cb = *(const float2*)(Cadd + (size_t)(row0 + 8) * ldca + col0);
                    v0 += ca.x; v1 += ca.y; v2 += cb.x; v3 += cb.y;
                }
                float bb0 = bias[col0], bb1 = bias[col0 + 1];
                *(float2*)&sg[rl * EPI_PITCH + cl] = make_float2(v0 + bb0, v1 + bb1);
                *(float2*)&sg[(rl + 8) * EPI_PITCH + cl] = make_float2(v2 + bb0, v3 + bb1);
            }
        }
        __syncthreads();
        int jb = bn >> 2;
#pragma unroll
        for (int it = 0; it < 16; it++) {
            int idx = it * 256 + tid;
            int rl = idx >> 5, jl = idx & 31;
            float4 g = *(const float4*)&sg[rl * EPI_PITCH + jl * 4];
            int grow = bm + rl;
            int j = jb + jl;
            size_t cidx = (size_t)grow * HID + j;
            float cv = sigacc(g.y) * cbuf[cidx] + sigacc(g.x) * tanhf(g.z);
            cbuf[cidx] = cv;
            float h = sigacc(g.w) * tanhf(cv);
            hout[(size_t)grow * 1024 + hoff + j] = __float2half_rn(h);
        }
    } else {
#pragma unroll
        for (int ma = 0; ma < 2; ma++) {
#pragma unroll
            for (int na = 0; na < 8; na++) {
                int row0 = bm + wm * 32 + ma * 16 + gid;
                int col = bn + wn * 64 + na * 8 + 2 * tig;
                float v0 = acc[ma][na][0], v1 = acc[ma][na][1];
                float v2 = acc[ma][na][2], v3 = acc[ma][na][3];
                if (bias) {
                    float bb0 = bias[col], bb1 = bias[col + 1];
                    v0 += bb0; v1 += bb1; v2 += bb0; v3 += bb1;
                }
                if (relu) {
                    v0 = fmaxf(v0, 0.0f); v1 = fmaxf(v1, 0.0f);
                    v2 = fmaxf(v2, 0.0f); v3 = fmaxf(v3, 0.0f);
                }
                *(float2*)(C + (size_t)row0 * ldc + col) = make_float2(v0, v1);
                *(float2*)(C + (size_t)(row0 + 8) * ldc + col) = make_float2(v2, v3);
            }
        }
    }
#undef ISSUE_STAGE
}

// ---------------------------------------------------------------------------
// launch
// ---------------------------------------------------------------------------
extern "C" void kernel_launch(void* const* d_in, const int* in_sizes, int n_in,
                              void* d_out, int out_size) {
    const float* x = (const float*)d_in[0];
    const float* c1w = (const float*)d_in[1];
    const float* c1b = (const float*)d_in[2];
    const float* c2w = (const float*)d_in[3];
    const float* c2b = (const float*)d_in[4];
    const float* W1 = (const float*)d_in[5];
    const float* U1 = (const float*)d_in[6];
    const float* b1 = (const float*)d_in[7];
    const float* W2 = (const float*)d_in[8];
    const float* U2 = (const float*)d_in[9];
    const float* b2 = (const float*)d_in[10];
    const float* fcw = (const float*)d_in[11];
    const float* fcb = (const float*)d_in[12];
    float* out = (float*)d_out;

    float *zx, *c1, *c2, *pb1, *pb2;
    __half *seqh;
    __half *cat[2];
    __half *w1p, *u1p, *wcp, *fct;
    cudaGetSymbolAddress((void**)&zx, d_zx);
    cudaGetSymbolAddress((void**)&c1, d_c1);
    cudaGetSymbolAddress((void**)&c2, d_c2);
    cudaGetSymbolAddress((void**)&pb1, d_pb1);
    cudaGetSymbolAddress((void**)&pb2, d_pb2);
    cudaGetSymbolAddress((void**)&seqh, d_seq);
    cudaGetSymbolAddress((void**)&cat[0], d_cat0);
    cudaGetSymbolAddress((void**)&cat[1], d_cat1);
    cudaGetSymbolAddress((void**)&w1p, d_W1p);
    cudaGetSymbolAddress((void**)&u1p, d_U1p);
    cudaGetSymbolAddress((void**)&wcp, d_WCp);
    cudaGetSymbolAddress((void**)&fct, d_FCt);

    cudaFuncSetAttribute(gemm_f16, cudaFuncAttributeMaxDynamicSharedMemorySize, GSM_BYTES);

    init_state<<<(BATCH * 1024 / 2) / 256, 256>>>(
        (uint32_t*)cat[0], (uint32_t*)cat[1], c1, c2);
    prep_weights<<<(PREP_TOTAL + 255) / 256, 256>>>(W1, U1, W2, U2, fcw, b1, b2,
                                                    w1p, u1p, wcp, fct, pb1, pb2);
    conv12_pool<<<BATCH, 256>>>(x, c1w, c1b, c2w, c2b, seqh);

    // zx = seq @ W1p : [28672,192] x [192,2048] (permuted cols)
    {
        dim3 g(G4 / 128, BT / 128);
        gemm_f16<<<g, 256, GSM_BYTES>>>(BT, G4, FEATP, seqh, FEATP,
                                        w1p, FEATP, zx, G4,
                                        nullptr, 0, nullptr, 0,
                                        0, nullptr, nullptr, 0);
    }

    dim3 ga(G4 / 128, BATCH / 128);
    for (int t = 0; t < SEQLEN; t++) {
        int p = t & 1;
        // layer 1: reads cat[p], writes h1_t -> cat[1-p][:, 0:512]
        gemm_f16<<<ga, 256, GSM_BYTES>>>(BATCH, G4, HID, cat[p], 1024,
                                         u1p, HID, nullptr, 0,
                                         zx + t * G4, SEQLEN * G4, pb1, 0,
                                         1, c1, cat[1 - p], 0);
        // layer 2: reads cat[1-p], writes h2_t -> cat[p][:, 512:1024]
        gemm_f16<<<ga, 256, GSM_BYTES>>>(BATCH, G4, 1024, cat[1 - p], 1024,
                                         wcp, 1024, nullptr, 0,
                                         nullptr, 0, pb2, 0,
                                         1, c2, cat[p], HID);
    }

    // FC head: relu(h2 @ fc_w + fc_b); final h2 lives in cat[0]
    {
        int pf = (SEQLEN - 1) & 1;
        dim3 gf(NCLS / 128, BATCH / 128);
        gemm_f16<<<gf, 256, GSM_BYTES>>>(BATCH, NCLS, HID,
                                         cat[pf] + HID, 1024,
                                         fct, HID, out, NCLS,
                                         nullptr, 0, fcb, 1,
                                         0, nullptr, nullptr, 0);
    }
}

// round 12
// speedup vs baseline: 2.2073x; 1.0620x over previous
#include <cuda_runtime.h>
#include <cuda_fp16.h>
#include <cstdint>
#include <math.h>

#define BATCH 4096
#define HID 512
#define SEQLEN 7
#define FEATP 192            // padded feature dim (160 -> 192)
#define G4 2048              // 4*HID
#define NCLS 256
#define BT (BATCH * SEQLEN)  // 28672

// ---------------------------------------------------------------------------
// scratch (device globals)
// ---------------------------------------------------------------------------
__device__ __align__(16) __half d_seq[BT * FEATP];
__device__ __align__(16) float d_zx[BT * G4];
// ping-pong cat buffers: [h1|h2] fp16 (race-free fused epilogue)
__device__ __align__(16) __half d_cat0[BATCH * 1024];
__device__ __align__(16) __half d_cat1[BATCH * 1024];
__device__ __align__(16) float d_c1[BATCH * HID];
__device__ __align__(16) float d_c2[BATCH * HID];
// weights: transposed [N,K], gate-permuted cols (col' = 4j+g), single fp16
__device__ __align__(16) __half d_W1p[G4 * FEATP];
__device__ __align__(16) __half d_U1p[G4 * HID];
__device__ __align__(16) __half d_WCp[G4 * 1024];
__device__ __align__(16) __half d_FCt[NCLS * HID];
__device__ __align__(16) float d_pb1[G4];                     // permuted biases
__device__ __align__(16) float d_pb2[G4];

// ---------------------------------------------------------------------------
// init: zero recurrent state
// ---------------------------------------------------------------------------
__global__ void init_state(uint32_t* __restrict__ c0, uint32_t* __restrict__ c1h,
                           float* __restrict__ c1, float* __restrict__ c2) {
    int i = blockIdx.x * blockDim.x + threadIdx.x;  // 0..2M-1
    c0[i] = 0u;
    c1h[i] = 0u;
    c1[i] = 0.0f;
    c2[i] = 0.0f;
}

// ---------------------------------------------------------------------------
// weight prep: transpose + gate-permute + fp16 + permuted biases
// ---------------------------------------------------------------------------
#define PREP_W1 (G4 * FEATP)
#define PREP_U1 (G4 * HID)
#define PREP_WC (G4 * 1024)
#define PREP_FC (NCLS * HID)
#define PREP_PB (2 * G4)
#define PREP_TOTAL (PREP_W1 + PREP_U1 + PREP_WC + PREP_FC + PREP_PB)

__global__ void prep_weights(const float* __restrict__ W1, const float* __restrict__ U1,
                             const float* __restrict__ W2, const float* __restrict__ U2,
                             const float* __restrict__ FC,
                             const float* __restrict__ b1, const float* __restrict__ b2,
                             __half* __restrict__ w1p, __half* __restrict__ u1p,
                             __half* __restrict__ wcp, __half* __restrict__ fct,
                             float* __restrict__ pb1, float* __restrict__ pb2) {
    int i = blockIdx.x * blockDim.x + threadIdx.x;
    if (i >= PREP_TOTAL) return;
    if (i >= PREP_W1 + PREP_U1 + PREP_WC + PREP_FC) {
        int o = i - (PREP_W1 + PREP_U1 + PREP_WC + PREP_FC);
        int which = o >> 11;
        int np = o & 2047;
        int src = (np & 3) * HID + (np >> 2);
        if (which == 0) pb1[np] = b1[src]; else pb2[np] = b2[src];
        return;
    }
    float v;
    __half* dst;
    int o;
    if (i < PREP_W1) {
        o = i;
        int np = o / FEATP, k = o % FEATP;
        int n = (np & 3) * HID + (np >> 2);
        v = (k < 160) ? W1[(size_t)k * G4 + n] : 0.0f;
        dst = w1p;
    } else if (i < PREP_W1 + PREP_U1) {
        o = i - PREP_W1;
        int np = o >> 9, k = o & 511;
        int n = (np & 3) * HID + (np >> 2);
        v = U1[(size_t)k * G4 + n];
        dst = u1p;
    } else if (i < PREP_W1 + PREP_U1 + PREP_WC) {
        o = i - PREP_W1 - PREP_U1;
        int np = o >> 10, k = o & 1023;
        int n = (np & 3) * HID + (np >> 2);
        v = (k < HID) ? W2[(size_t)k * G4 + n] : U2[(size_t)(k - HID) * G4 + n];
        dst = wcp;
    } else {
        o = i - PREP_W1 - PREP_U1 - PREP_WC;
        int n = o >> 9, k = o & 511;
        v = FC[(size_t)k * NCLS + n];
        dst = fct;
    }
    dst[o] = __float2half_rn(v);
}

// ---------------------------------------------------------------------------
// fused conv1+pool1+conv2+pool2 -> seq fp16; one block per batch sample.
// ---------------------------------------------------------------------------
__global__ __launch_bounds__(256) void conv12_pool(
    const float* __restrict__ x,
    const float* __restrict__ w1, const float* __restrict__ b1,
    const float* __restrict__ w2, const float* __restrict__ b2,
    __half* __restrict__ sh) {
    __shared__ float sIn[15 * 80 * 3];    // 3600
    __shared__ float sW1[7 * 3 * 3 * 10]; // 630
    __shared__ float sP[9 * 26 * 10];     // 2340
    __shared__ float sW2[3 * 3 * 10 * 20];// 1800
    int b = blockIdx.x;
    const float* xb = x + (size_t)b * 3600;
    for (int i = threadIdx.x; i < 3600; i += 256) sIn[i] = xb[i];
    for (int i = threadIdx.x; i < 630; i += 256) sW1[i] = w1[i];
    for (int i = threadIdx.x; i < 1800; i += 256) sW2[i] = w2[i];
    __syncthreads();

    for (int item = threadIdx.x; item < 9 * 260; item += 256) {
        int r = item / 260;
        int rem = item - r * 260;
        int p = rem / 10, co = rem - p * 10;
        float best = -1e30f;
#pragma unroll
        for (int dx = 0; dx < 3; dx++) {
            int cw = p * 3 + dx;
            float acc = 0.0f;
#pragma unroll
            for (int kh = 0; kh < 7; kh++)
#pragma unroll
                for (int kw = 0; kw < 3; kw++)
#pragma unroll
                    for (int ci = 0; ci < 3; ci++)
                        acc += sIn[(r + kh) * 240 + (cw + kw) * 3 + ci] *
                               sW1[((kh * 3 + kw) * 3 + ci) * 10 + co];
            best = fmaxf(best, acc);
        }
        sP[(r * 26 + p) * 10 + co] = fmaxf(best + b1[co], 0.0f);
    }
    __syncthreads();

    for (int item = threadIdx.x; item < 7 * 160; item += 256) {
        int r = item / 160;
        int f = item - r * 160;
        int p = f / 20, co = f - p * 20;
        float best = -1e30f;
#pragma unroll
        for (int dx = 0; dx < 3; dx++) {
            int cw = p * 3 + dx;
            float acc = 0.0f;
#pragma unroll
            for (int kh = 0; kh < 3; kh++)
#pragma unroll
                for (int kw = 0; kw < 3; kw++)
#pragma unroll
                    for (int ci = 0; ci < 10; ci++)
                        acc += sP[((r + kh) * 26 + (cw + kw)) * 10 + ci] *
                               sW2[((kh * 3 + kw) * 10 + ci) * 20 + co];
            best = fmaxf(best, acc);
        }
        float v = fmaxf(best + b2[co], 0.0f);
        sh[(size_t)(b * 7 + r) * FEATP + f] = __float2half_rn(v);
    }
    for (int i = threadIdx.x; i < 7 * 32; i += 256) {
        int r = i >> 5;
        sh[(size_t)(b * 7 + r) * FEATP + 160 + (i & 31)] = __float2half_rn(0.0f);
    }
}

// ---------------------------------------------------------------------------
// fp16 1-pass GEMM: C = A @ B^T. 512 threads, warp tile 32x32 (4x4 warps),
// 3-stage cp.async ring, one barrier per stage, 2 CTAs/SM (32 warps/SM).
// gate mode = fused LSTM epilogue staged through SMEM.
// ---------------------------------------------------------------------------
#define ROWB 80
#define TILE_B (128 * ROWB)          // 10240
#define STAGE_B (2 * TILE_B)         // A | B = 20480
#define NSTAGE 3                     // 61440 bytes ring
#define EPI_BYTES (128 * 132 * 4)    // 67584
#define GSM_BYTES EPI_BYTES          // >= NSTAGE*STAGE_B (61440)
#define EPI_PITCH 132
#define NTHR 512

__device__ __forceinline__ uint32_t smem_u32(const void* p) {
    uint32_t a;
    asm("{ .reg .u64 t; cvta.to.shared.u64 t, %1; cvt.u32.u64 %0, t; }" : "=r"(a) : "l"(p));
    return a;
}
__device__ __forceinline__ void cp_async16(uint32_t sa, const void* gaddr) {
    asm volatile("cp.async.cg.shared.global [%0], [%1], 16;" :: "r"(sa), "l"(gaddr) : "memory");
}
__device__ __forceinline__ void ldmx4(uint32_t* r, uint32_t sa) {
    asm volatile("ldmatrix.sync.aligned.m8n8.x4.shared.b16 {%0,%1,%2,%3}, [%4];"
                 : "=r"(r[0]), "=r"(r[1]), "=r"(r[2]), "=r"(r[3]) : "r"(sa));
}
__device__ __forceinline__ void mma_f16(float* c, const uint32_t* a, uint32_t b0, uint32_t b1) {
    asm volatile(
        "mma.sync.aligned.m16n8k16.row.col.f32.f16.f16.f32 "
        "{%0,%1,%2,%3}, {%4,%5,%6,%7}, {%8,%9}, {%0,%1,%2,%3};"
        : "+f"(c[0]), "+f"(c[1]), "+f"(c[2]), "+f"(c[3])
        : "r"(a[0]), "r"(a[1]), "r"(a[2]), "r"(a[3]), "r"(b0), "r"(b1));
}
__device__ __forceinline__ float sigacc(float x) { return 1.0f / (1.0f + expf(-x)); }

__global__ __launch_bounds__(NTHR, 2) void gemm_f16(
    int M, int N, int K,
    const __half* __restrict__ A, int lda,
    const __half* __restrict__ B, int ldb,
    float* __restrict__ C, int ldc,
    const float* __restrict__ Cadd, int ldca,
    const float* __restrict__ bias, int relu,
    int gate, float* __restrict__ cbuf,
    __half* __restrict__ hout, int hoff) {
    extern __shared__ char smem[];
    uint32_t sb0 = smem_u32(smem);
    int tid = threadIdx.x;
    int lane = tid & 31;
    int warp = tid >> 5;           // 0..15
    int wm = warp >> 2;            // 0..3 -> 32-row slab
    int wn = warp & 3;             // 0..3 -> 32-col slab
    int gid = lane >> 2;
    int tig = lane & 3;
    int lane15 = lane & 15;
    int halfsel = (lane >> 4) << 4;

    int bm = blockIdx.y * 128;
    int bn = blockIdx.x * 128;

    const __half* A0 = A + (size_t)bm * lda;
    const __half* B0 = B + (size_t)bn * ldb;

    float acc[2][4][4];
#pragma unroll
    for (int i = 0; i < 2; i++)
#pragma unroll
        for (int j = 0; j < 4; j++)
#pragma unroll
            for (int r = 0; r < 4; r++) acc[i][j][r] = 0.0f;

    int nst = K >> 5;

    // per-thread copy coords: 512 threads x (1 A + 1 B) 16B chunk per stage
    int cp_row = tid >> 2, cp_c4 = tid & 3;

#define ISSUE_STAGE(kt, slot) do {                                             \
        if ((kt) < nst) {                                                      \
            uint32_t st = sb0 + (slot) * STAGE_B;                              \
            int k0 = (kt) << 5;                                                \
            uint32_t sa = st + cp_row * ROWB + cp_c4 * 16;                     \
            cp_async16(sa,          A0 + (size_t)cp_row * lda + k0 + cp_c4 * 8);\
            cp_async16(sa + TILE_B, B0 + (size_t)cp_row * ldb + k0 + cp_c4 * 8);\
        }                                                                      \
        asm volatile("cp.async.commit_group;" ::: "memory");                   \
    } while (0)

    ISSUE_STAGE(0, 0);
    ISSUE_STAGE(1, 1);

    int slot = 0, slot2 = 2;
    for (int kt = 0; kt < nst; kt++) {
        asm volatile("cp.async.wait_group 1;" ::: "memory");
        __syncthreads();
        ISSUE_STAGE(kt + 2, slot2);

        uint32_t st = sb0 + slot * STAGE_B;
        uint32_t aAddr = st + (uint32_t)((wm * 32 + lane15) * ROWB) + halfsel;
        uint32_t bAddr = st + TILE_B + (uint32_t)((wn * 32 + lane15) * ROWB) + halfsel;

#pragma unroll
        for (int k16 = 0; k16 < 2; k16++) {
            uint32_t kb = k16 * 32;
            uint32_t af[2][4], bf[2][4];
            // batch all fragment loads (one latency wait, max MLP)
            ldmx4(af[0], aAddr + kb);
            ldmx4(af[1], aAddr + 16 * ROWB + kb);
            ldmx4(bf[0], bAddr + kb);
            ldmx4(bf[1], bAddr + 16 * ROWB + kb);
#pragma unroll
            for (int nb = 0; nb < 2; nb++) {
#pragma unroll
                for (int hf = 0; hf < 2; hf++) {
                    int na = nb * 2 + hf;
#pragma unroll
                    for (int ma = 0; ma < 2; ma++)
                        mma_f16(acc[ma][na], af[ma], bf[nb][hf], bf[nb][2 + hf]);
                }
            }
        }
        slot = (slot == 2) ? 0 : slot + 1;
        slot2 = (slot2 == 2) ? 0 : slot2 + 1;
    }
    __syncthreads();   // ring buffers -> epilogue smem reuse

    // ---- epilogue ----
    if (gate) {
        float* sg = (float*)smem;
#pragma unroll
        for (int ma = 0; ma < 2; ma++) {
#pragma unroll
            for (int na = 0; na < 4; na++) {
                int rl = wm * 32 + ma * 16 + gid;
                int cl = wn * 32 + na * 8 + 2 * tig;
                int row0 = bm + rl;
                int col0 = bn + cl;
                float v0 = acc[ma][na][0], v1 = acc[ma][na][1];
                float v2 = acc[ma][na][2], v3 = acc[ma][na][3];
                if (Cadd) {
                    float2 ca = *(const float2*)(Cadd + (size_t)row0 * ldca + col0);
                    float2 cb = *(const float2*)(Cadd + (size_t)(row0 + 8) * ldca + col0);
                    v0 += ca.x; v1 += ca.y; v2 += cb.x; v3 += cb.y;
                }
                float bb0 = bias[col0], bb1 = bias[col0 + 1];
                *(float2*)&sg[rl * EPI_PITCH + cl] = make_float2(v0 + bb0, v1 + bb1);
                *(float2*)&sg[(rl + 8) * EPI_PITCH + cl] = make_float2(v2 + bb0, v3 + bb1);
            }
        }
        __syncthreads();
        int jb = bn >> 2;
#pragma unroll
        for (int it = 0; it < 8; it++) {
            int idx = it * NTHR + tid;
            int rl = idx >> 5, jl = idx & 31;
            float4 g = *(const float4*)&sg[rl * EPI_PITCH + jl * 4];
            int grow = bm + rl;
            int j = jb + jl;
            size_t cidx = (size_t)grow * HID + j;
            float cv = sigacc(g.y) * cbuf[cidx] + sigacc(g.x) * tanhf(g.z);
            cbuf[cidx] = cv;
            float h = sigacc(g.w) * tanhf(cv);
            hout[(size_t)grow * 1024 + hoff + j] = __float2half_rn(h);
        }
    } else {
#pragma unroll
        for (int ma = 0; ma < 2; ma++) {
#pragma unroll
            for (int na = 0; na < 4; na++) {
                int row0 = bm + wm * 32 + ma * 16 + gid;
                int col = bn + wn * 32 + na * 8 + 2 * tig;
                float v0 = acc[ma][na][0], v1 = acc[ma][na][1];
                float v2 = acc[ma][na][2], v3 = acc[ma][na][3];
                if (bias) {
                    float bb0 = bias[col], bb1 = bias[col + 1];
                    v0 += bb0; v1 += bb1; v2 += bb0; v3 += bb1;
                }
                if (relu) {
                    v0 = fmaxf(v0, 0.0f); v1 = fmaxf(v1, 0.0f);
                    v2 = fmaxf(v2, 0.0f); v3 = fmaxf(v3, 0.0f);
                }
                *(float2*)(C + (size_t)row0 * ldc + col) = make_float2(v0, v1);
                *(float2*)(C + (size_t)(row0 + 8) * ldc + col) = make_float2(v2, v3);
            }
        }
    }
#undef ISSUE_STAGE
}

// ---------------------------------------------------------------------------
// launch
// ---------------------------------------------------------------------------
extern "C" void kernel_launch(void* const* d_in, const int* in_sizes, int n_in,
                              void* d_out, int out_size) {
    const float* x = (const float*)d_in[0];
    const float* c1w = (const float*)d_in[1];
    const float* c1b = (const float*)d_in[2];
    const float* c2w = (const float*)d_in[3];
    const float* c2b = (const float*)d_in[4];
    const float* W1 = (const float*)d_in[5];
    const float* U1 = (const float*)d_in[6];
    const float* b1 = (const float*)d_in[7];
    const float* W2 = (const float*)d_in[8];
    const float* U2 = (const float*)d_in[9];
    const float* b2 = (const float*)d_in[10];
    const float* fcw = (const float*)d_in[11];
    const float* fcb = (const float*)d_in[12];
    float* out = (float*)d_out;

    float *zx, *c1, *c2, *pb1, *pb2;
    __half *seqh;
    __half *cat[2];
    __half *w1p, *u1p, *wcp, *fct;
    cudaGetSymbolAddress((void**)&zx, d_zx);
    cudaGetSymbolAddress((void**)&c1, d_c1);
    cudaGetSymbolAddress((void**)&c2, d_c2);
    cudaGetSymbolAddress((void**)&pb1, d_pb1);
    cudaGetSymbolAddress((void**)&pb2, d_pb2);
    cudaGetSymbolAddress((void**)&seqh, d_seq);
    cudaGetSymbolAddress((void**)&cat[0], d_cat0);
    cudaGetSymbolAddress((void**)&cat[1], d_cat1);
    cudaGetSymbolAddress((void**)&w1p, d_W1p);
    cudaGetSymbolAddress((void**)&u1p, d_U1p);
    cudaGetSymbolAddress((void**)&wcp, d_WCp);
    cudaGetSymbolAddress((void**)&fct, d_FCt);

    cudaFuncSetAttribute(gemm_f16, cudaFuncAttributeMaxDynamicSharedMemorySize, GSM_BYTES);

    init_state<<<(BATCH * 1024 / 2) / 256, 256>>>(
        (uint32_t*)cat[0], (uint32_t*)cat[1], c1, c2);
    prep_weights<<<(PREP_TOTAL + 255) / 256, 256>>>(W1, U1, W2, U2, fcw, b1, b2,
                                                    w1p, u1p, wcp, fct, pb1, pb2);
    conv12_pool<<<BATCH, 256>>>(x, c1w, c1b, c2w, c2b, seqh);

    // zx = seq @ W1p : [28672,192] x [192,2048] (permuted cols)
    {
        dim3 g(G4 / 128, BT / 128);
        gemm_f16<<<g, NTHR, GSM_BYTES>>>(BT, G4, FEATP, seqh, FEATP,
                                         w1p, FEATP, zx, G4,
                                         nullptr, 0, nullptr, 0,
                                         0, nullptr, nullptr, 0);
    }

    dim3 ga(G4 / 128, BATCH / 128);
    for (int t = 0; t < SEQLEN; t++) {
        int p = t & 1;
        // layer 1: reads cat[p], writes h1_t -> cat[1-p][:, 0:512]
        gemm_f16<<<ga, NTHR, GSM_BYTES>>>(BATCH, G4, HID, cat[p], 1024,
                                          u1p, HID, nullptr, 0,
                                          zx + t * G4, SEQLEN * G4, pb1, 0,
                                          1, c1, cat[1 - p], 0);
        // layer 2: reads cat[1-p], writes h2_t -> cat[p][:, 512:1024]
        gemm_f16<<<ga, NTHR, GSM_BYTES>>>(BATCH, G4, 1024, cat[1 - p], 1024,
                                          wcp, 1024, nullptr, 0,
                                          nullptr, 0, pb2, 0,
                                          1, c2, cat[p], HID);
    }

    // FC head: relu(h2 @ fc_w + fc_b); final h2 lives in cat[0]
    {
        int pf = (SEQLEN - 1) & 1;
        dim3 gf(NCLS / 128, BATCH / 128);
        gemm_f16<<<gf, NTHR, GSM_BYTES>>>(BATCH, NCLS, HID,
                                          cat[pf] + HID, 1024,
                                          fct, HID, out, NCLS,
                                          nullptr, 0, fcb, 1,
                                          0, nullptr, nullptr, 0);
    }
}

// round 13
// speedup vs baseline: 2.2088x; 1.0007x over previous
#include <cuda_runtime.h>
#include <cuda_fp16.h>
#include <cstdint>
#include <math.h>

#define BATCH 4096
#define HID 512
#define SEQLEN 7
#define FEATP 192            // padded feature dim (160 -> 192)
#define G4 2048              // 4*HID
#define NCLS 256
#define BT (BATCH * SEQLEN)  // 28672

// ---------------------------------------------------------------------------
// scratch (device globals)
// ---------------------------------------------------------------------------
__device__ __align__(16) __half d_seq[BT * FEATP];
__device__ __align__(16) float d_zx[BT * G4];
// ping-pong cat buffers: [h1|h2] fp16 (race-free fused epilogue)
__device__ __align__(16) __half d_cat0[BATCH * 1024];
__device__ __align__(16) __half d_cat1[BATCH * 1024];
__device__ __align__(16) float d_c1[BATCH * HID];
__device__ __align__(16) float d_c2[BATCH * HID];
// weights: transposed [N,K], gate-permuted cols (col' = 4j+g), single fp16
__device__ __align__(16) __half d_W1p[G4 * FEATP];
__device__ __align__(16) __half d_U1p[G4 * HID];
__device__ __align__(16) __half d_WCp[G4 * 1024];
__device__ __align__(16) __half d_FCt[NCLS * HID];
__device__ __align__(16) float d_pb1[G4];                     // permuted biases
__device__ __align__(16) float d_pb2[G4];

// ---------------------------------------------------------------------------
// init: zero recurrent state
// ---------------------------------------------------------------------------
__global__ void init_state(uint32_t* __restrict__ c0, uint32_t* __restrict__ c1h,
                           float* __restrict__ c1, float* __restrict__ c2) {
    int i = blockIdx.x * blockDim.x + threadIdx.x;  // 0..2M-1
    c0[i] = 0u;
    c1h[i] = 0u;
    c1[i] = 0.0f;
    c2[i] = 0.0f;
}

// ---------------------------------------------------------------------------
// weight prep: transpose + gate-permute + fp16 + permuted biases
// ---------------------------------------------------------------------------
#define PREP_W1 (G4 * FEATP)
#define PREP_U1 (G4 * HID)
#define PREP_WC (G4 * 1024)
#define PREP_FC (NCLS * HID)
#define PREP_PB (2 * G4)
#define PREP_TOTAL (PREP_W1 + PREP_U1 + PREP_WC + PREP_FC + PREP_PB)

__global__ void prep_weights(const float* __restrict__ W1, const float* __restrict__ U1,
                             const float* __restrict__ W2, const float* __restrict__ U2,
                             const float* __restrict__ FC,
                             const float* __restrict__ b1, const float* __restrict__ b2,
                             __half* __restrict__ w1p, __half* __restrict__ u1p,
                             __half* __restrict__ wcp, __half* __restrict__ fct,
                             float* __restrict__ pb1, float* __restrict__ pb2) {
    int i = blockIdx.x * blockDim.x + threadIdx.x;
    if (i >= PREP_TOTAL) return;
    if (i >= PREP_W1 + PREP_U1 + PREP_WC + PREP_FC) {
        int o = i - (PREP_W1 + PREP_U1 + PREP_WC + PREP_FC);
        int which = o >> 11;
        int np = o & 2047;
        int src = (np & 3) * HID + (np >> 2);
        if (which == 0) pb1[np] = b1[src]; else pb2[np] = b2[src];
        return;
    }
    float v;
    __half* dst;
    int o;
    if (i < PREP_W1) {
        o = i;
        int np = o / FEATP, k = o % FEATP;
        int n = (np & 3) * HID + (np >> 2);
        v = (k < 160) ? W1[(size_t)k * G4 + n] : 0.0f;
        dst = w1p;
    } else if (i < PREP_W1 + PREP_U1) {
        o = i - PREP_W1;
        int np = o >> 9, k = o & 511;
        int n = (np & 3) * HID + (np >> 2);
        v = U1[(size_t)k * G4 + n];
        dst = u1p;
    } else if (i < PREP_W1 + PREP_U1 + PREP_WC) {
        o = i - PREP_W1 - PREP_U1;
        int np = o >> 10, k = o & 1023;
        int n = (np & 3) * HID + (np >> 2);
        v = (k < HID) ? W2[(size_t)k * G4 + n] : U2[(size_t)(k - HID) * G4 + n];
        dst = wcp;
    } else {
        o = i - PREP_W1 - PREP_U1 - PREP_WC;
        int n = o >> 9, k = o & 511;
        v = FC[(size_t)k * NCLS + n];
        dst = fct;
    }
    dst[o] = __float2half_rn(v);
}

// ---------------------------------------------------------------------------
// fused conv1+pool1+conv2+pool2 -> seq fp16; one block per batch sample.
// ---------------------------------------------------------------------------
__global__ __launch_bounds__(256) void conv12_pool(
    const float* __restrict__ x,
    const float* __restrict__ w1, const float* __restrict__ b1,
    const float* __restrict__ w2, const float* __restrict__ b2,
    __half* __restrict__ sh) {
    __shared__ float sIn[15 * 80 * 3];    // 3600
    __shared__ float sW1[7 * 3 * 3 * 10]; // 630
    __shared__ float sP[9 * 26 * 10];     // 2340
    __shared__ float sW2[3 * 3 * 10 * 20];// 1800
    int b = blockIdx.x;
    const float* xb = x + (size_t)b * 3600;
    for (int i = threadIdx.x; i < 3600; i += 256) sIn[i] = xb[i];
    for (int i = threadIdx.x; i < 630; i += 256) sW1[i] = w1[i];
    for (int i = threadIdx.x; i < 1800; i += 256) sW2[i] = w2[i];
    __syncthreads();

    for (int item = threadIdx.x; item < 9 * 260; item += 256) {
        int r = item / 260;
        int rem = item - r * 260;
        int p = rem / 10, co = rem - p * 10;
        float best = -1e30f;
#pragma unroll
        for (int dx = 0; dx < 3; dx++) {
            int cw = p * 3 + dx;
            float acc = 0.0f;
#pragma unroll
            for (int kh = 0; kh < 7; kh++)
#pragma unroll
                for (int kw = 0; kw < 3; kw++)
#pragma unroll
                    for (int ci = 0; ci < 3; ci++)
                        acc += sIn[(r + kh) * 240 + (cw + kw) * 3 + ci] *
                               sW1[((kh * 3 + kw) * 3 + ci) * 10 + co];
            best = fmaxf(best, acc);
        }
        sP[(r * 26 + p) * 10 + co] = fmaxf(best + b1[co], 0.0f);
    }
    __syncthreads();

    for (int item = threadIdx.x; item < 7 * 160; item += 256) {
        int r = item / 160;
        int f = item - r * 160;
        int p = f / 20, co = f - p * 20;
        float best = -1e30f;
#pragma unroll
        for (int dx = 0; dx < 3; dx++) {
            int cw = p * 3 + dx;
            float acc = 0.0f;
#pragma unroll
            for (int kh = 0; kh < 3; kh++)
#pragma unroll
                for (int kw = 0; kw < 3; kw++)
#pragma unroll
                    for (int ci = 0; ci < 10; ci++)
                        acc += sP[((r + kh) * 26 + (cw + kw)) * 10 + ci] *
                               sW2[((kh * 3 + kw) * 10 + ci) * 20 + co];
            best = fmaxf(best, acc);
        }
        float v = fmaxf(best + b2[co], 0.0f);
        sh[(size_t)(b * 7 + r) * FEATP + f] = __float2half_rn(v);
    }
    for (int i = threadIdx.x; i < 7 * 32; i += 256) {
        int r = i >> 5;
        sh[(size_t)(b * 7 + r) * FEATP + 160 + (i & 31)] = __float2half_rn(0.0f);
    }
}

// ---------------------------------------------------------------------------
// fp16 1-pass GEMM: C = A @ B^T. 512 threads, warp tile 32x32 (4x4 warps),
// 3-stage cp.async ring, one barrier per stage, 2 CTAs/SM (32 warps/SM).
// gate mode = fused LSTM epilogue staged through SMEM.
// ---------------------------------------------------------------------------
#define ROWB 80
#define TILE_B (128 * ROWB)          // 10240
#define STAGE_B (2 * TILE_B)         // A | B = 20480
#define NSTAGE 3                     // 61440 bytes ring
#define EPI_BYTES (128 * 132 * 4)    // 67584
#define GSM_BYTES EPI_BYTES          // >= NSTAGE*STAGE_B (61440)
#define EPI_PITCH 132
#define NTHR 512

__device__ __forceinline__ uint32_t smem_u32(const void* p) {
    uint32_t a;
    asm("{ .reg .u64 t; cvta.to.shared.u64 t, %1; cvt.u32.u64 %0, t; }" : "=r"(a) : "l"(p));
    return a;
}
__device__ __forceinline__ void cp_async16(uint32_t sa, const void* gaddr) {
    asm volatile("cp.async.cg.shared.global [%0], [%1], 16;" :: "r"(sa), "l"(gaddr) : "memory");
}
__device__ __forceinline__ void ldmx4(uint32_t* r, uint32_t sa) {
    asm volatile("ldmatrix.sync.aligned.m8n8.x4.shared.b16 {%0,%1,%2,%3}, [%4];"
                 : "=r"(r[0]), "=r"(r[1]), "=r"(r[2]), "=r"(r[3]) : "r"(sa));
}
__device__ __forceinline__ void mma_f16(float* c, const uint32_t* a, uint32_t b0, uint32_t b1) {
    asm volatile(
        "mma.sync.aligned.m16n8k16.row.col.f32.f16.f16.f32 "
        "{%0,%1,%2,%3}, {%4,%5,%6,%7}, {%8,%9}, {%0,%1,%2,%3};"
        : "+f"(c[0]), "+f"(c[1]), "+f"(c[2]), "+f"(c[3])
        : "r"(a[0]), "r"(a[1]), "r"(a[2]), "r"(a[3]), "r"(b0), "r"(b1));
}
__device__ __forceinline__ float sigacc(float x) { return 1.0f / (1.0f + expf(-x)); }

__global__ __launch_bounds__(NTHR, 2) void gemm_f16(
    int M, int N, int K,
    const __half* __restrict__ A, int lda,
    const __half* __restrict__ B, int ldb,
    float* __restrict__ C, int ldc,
    const float* __restrict__ Cadd, int ldca,
    const float* __restrict__ bias, int relu,
    int gate, float* __restrict__ cbuf,
    __half* __restrict__ hout, int hoff) {
    extern __shared__ char smem[];
    uint32_t sb0 = smem_u32(smem);
    int tid = threadIdx.x;
    int lane = tid & 31;
    int warp = tid >> 5;           // 0..15
    int wm = warp >> 2;            // 0..3 -> 32-row slab
    int wn = warp & 3;             // 0..3 -> 32-col slab
    int gid = lane >> 2;
    int tig = lane & 3;
    int lane15 = lane & 15;
    int halfsel = (lane >> 4) << 4;

    int bm = blockIdx.y * 128;
    int bn = blockIdx.x * 128;

    const __half* A0 = A + (size_t)bm * lda;
    const __half* B0 = B + (size_t)bn * ldb;

    float acc[2][4][4];
#pragma unroll
    for (int i = 0; i < 2; i++)
#pragma unroll
        for (int j = 0; j < 4; j++)
#pragma unroll
            for (int r = 0; r < 4; r++) acc[i][j][r] = 0.0f;

    int nst = K >> 5;

    // per-thread copy coords: 512 threads x (1 A + 1 B) 16B chunk per stage
    int cp_row = tid >> 2, cp_c4 = tid & 3;

#define ISSUE_STAGE(kt, slot) do {                                             \
        if ((kt) < nst) {                                                      \
            uint32_t st = sb0 + (slot) * STAGE_B;                              \
            int k0 = (kt) << 5;                                                \
            uint32_t sa = st + cp_row * ROWB + cp_c4 * 16;                     \
            cp_async16(sa,          A0 + (size_t)cp_row * lda + k0 + cp_c4 * 8);\
            cp_async16(sa + TILE_B, B0 + (size_t)cp_row * ldb + k0 + cp_c4 * 8);\
        }                                                                      \
        asm volatile("cp.async.commit_group;" ::: "memory");                   \
    } while (0)

    ISSUE_STAGE(0, 0);
    ISSUE_STAGE(1, 1);

    int slot = 0, slot2 = 2;
    for (int kt = 0; kt < nst; kt++) {
        asm volatile("cp.async.wait_group 1;" ::: "memory");
        __syncthreads();
        ISSUE_STAGE(kt + 2, slot2);

        uint32_t st = sb0 + slot * STAGE_B;
        uint32_t aAddr = st + (uint32_t)((wm * 32 + lane15) * ROWB) + halfsel;
        uint32_t bAddr = st + TILE_B + (uint32_t)((wn * 32 + lane15) * ROWB) + halfsel;

#pragma unroll
        for (int k16 = 0; k16 < 2; k16++) {
            uint32_t kb = k16 * 32;
            uint32_t af[2][4], bf[2][4];
            // batch all fragment loads (one latency wait, max MLP)
            ldmx4(af[0], aAddr + kb);
            ldmx4(af[1], aAddr + 16 * ROWB + kb);
            ldmx4(bf[0], bAddr + kb);
            ldmx4(bf[1], bAddr + 16 * ROWB + kb);
#pragma unroll
            for (int nb = 0; nb < 2; nb++) {
#pragma unroll
                for (int hf = 0; hf < 2; hf++) {
                    int na = nb * 2 + hf;
#pragma unroll
                    for (int ma = 0; ma < 2; ma++)
                        mma_f16(acc[ma][na], af[ma], bf[nb][hf], bf[nb][2 + hf]);
                }
            }
        }
        slot = (slot == 2) ? 0 : slot + 1;
        slot2 = (slot2 == 2) ? 0 : slot2 + 1;
    }
    __syncthreads();   // ring buffers -> epilogue smem reuse

    // ---- epilogue ----
    if (gate) {
        float* sg = (float*)smem;
#pragma unroll
        for (int ma = 0; ma < 2; ma++) {
#pragma unroll
            for (int na = 0; na < 4; na++) {
                int rl = wm * 32 + ma * 16 + gid;
                int cl = wn * 32 + na * 8 + 2 * tig;
                int row0 = bm + rl;
                int col0 = bn + cl;
                float v0 = acc[ma][na][0], v1 = acc[ma][na][1];
                float v2 = acc[ma][na][2], v3 = acc[ma][na][3];
                if (Cadd) {
                    float2 ca = *(const float2*)(Cadd + (size_t)row0 * ldca + col0);
                    float2 cb = *(const float2*)(Cadd + (size_t)(row0 + 8) * ldca + col0);
                    v0 += ca.x; v1 += ca.y; v2 += cb.x; v3 += cb.y;
                }
                float bb0 = bias[col0], bb1 = bias[col0 + 1];
                *(float2*)&sg[rl * EPI_PITCH + cl] = make_float2(v0 + bb0, v1 + bb1);
                *(float2*)&sg[(rl + 8) * EPI_PITCH + cl] = make_float2(v2 + bb0, v3 + bb1);
            }
        }
        __syncthreads();
        int jb = bn >> 2;
#pragma unroll
        for (int it = 0; it < 8; it++) {
            int idx = it * NTHR + tid;
            int rl = idx >> 5, jl = idx & 31;
            float4 g = *(const float4*)&sg[rl * EPI_PITCH + jl * 4];
            int grow = bm + rl;
            int j = jb + jl;
            size_t cidx = (size_t)grow * HID + j;
            float cv = sigacc(g.y) * cbuf[cidx] + sigacc(g.x) * tanhf(g.z);
            cbuf[cidx] = cv;
            float h = sigacc(g.w) * tanhf(cv);
            hout[(size_t)grow * 1024 + hoff + j] = __float2half_rn(h);
        }
    } else {
#pragma unroll
        for (int ma = 0; ma < 2; ma++) {
#pragma unroll
            for (int na = 0; na < 4; na++) {
                int row0 = bm + wm * 32 + ma * 16 + gid;
                int col = bn + wn * 32 + na * 8 + 2 * tig;
                float v0 = acc[ma][na][0], v1 = acc[ma][na][1];
                float v2 = acc[ma][na][2], v3 = acc[ma][na][3];
                if (bias) {
                    float bb0 = bias[col], bb1 = bias[col + 1];
                    v0 += bb0; v1 += bb1; v2 += bb0; v3 += bb1;
                }
                if (relu) {
                    v0 = fmaxf(v0, 0.0f); v1 = fmaxf(v1, 0.0f);
                    v2 = fmaxf(v2, 0.0f); v3 = fmaxf(v3, 0.0f);
                }
                *(float2*)(C + (size_t)row0 * ldc + col) = make_float2(v0, v1);
                *(float2*)(C + (size_t)(row0 + 8) * ldc + col) = make_float2(v2, v3);
            }
        }
    }
#undef ISSUE_STAGE
}

// ---------------------------------------------------------------------------
// launch
// ---------------------------------------------------------------------------
extern "C" void kernel_launch(void* const* d_in, const int* in_sizes, int n_in,
                              void* d_out, int out_size) {
    const float* x = (const float*)d_in[0];
    const float* c1w = (const float*)d_in[1];
    const float* c1b = (const float*)d_in[2];
    const float* c2w = (const float*)d_in[3];
    const float* c2b = (const float*)d_in[4];
    const float* W1 = (const float*)d_in[5];
    const float* U1 = (const float*)d_in[6];
    const float* b1 = (const float*)d_in[7];
    const float* W2 = (const float*)d_in[8];
    const float* U2 = (const float*)d_in[9];
    const float* b2 = (const float*)d_in[10];
    const float* fcw = (const float*)d_in[11];
    const float* fcb = (const float*)d_in[12];
    float* out = (float*)d_out;

    float *zx, *c1, *c2, *pb1, *pb2;
    __half *seqh;
    __half *cat[2];
    __half *w1p, *u1p, *wcp, *fct;
    cudaGetSymbolAddress((void**)&zx, d_zx);
    cudaGetSymbolAddress((void**)&c1, d_c1);
    cudaGetSymbolAddress((void**)&c2, d_c2);
    cudaGetSymbolAddress((void**)&pb1, d_pb1);
    cudaGetSymbolAddress((void**)&pb2, d_pb2);
    cudaGetSymbolAddress((void**)&seqh, d_seq);
    cudaGetSymbolAddress((void**)&cat[0], d_cat0);
    cudaGetSymbolAddress((void**)&cat[1], d_cat1);
    cudaGetSymbolAddress((void**)&w1p, d_W1p);
    cudaGetSymbolAddress((void**)&u1p, d_U1p);
    cudaGetSymbolAddress((void**)&wcp, d_WCp);
    cudaGetSymbolAddress((void**)&fct, d_FCt);

    cudaFuncSetAttribute(gemm_f16, cudaFuncAttributeMaxDynamicSharedMemorySize, GSM_BYTES);

    init_state<<<(BATCH * 1024 / 2) / 256, 256>>>(
        (uint32_t*)cat[0], (uint32_t*)cat[1], c1, c2);
    prep_weights<<<(PREP_TOTAL + 255) / 256, 256>>>(W1, U1, W2, U2, fcw, b1, b2,
                                                    w1p, u1p, wcp, fct, pb1, pb2);
    conv12_pool<<<BATCH, 256>>>(x, c1w, c1b, c2w, c2b, seqh);

    // zx = seq @ W1p : [28672,192] x [192,2048] (permuted cols)
    {
        dim3 g(G4 / 128, BT / 128);
        gemm_f16<<<g, NTHR, GSM_BYTES>>>(BT, G4, FEATP, seqh, FEATP,
                                         w1p, FEATP, zx, G4,
                                         nullptr, 0, nullptr, 0,
                                         0, nullptr, nullptr, 0);
    }

    dim3 ga(G4 / 128, BATCH / 128);
    for (int t = 0; t < SEQLEN; t++) {
        int p = t & 1;
        // layer 1: reads cat[p], writes h1_t -> cat[1-p][:, 0:512]
        gemm_f16<<<ga, NTHR, GSM_BYTES>>>(BATCH, G4, HID, cat[p], 1024,
                                          u1p, HID, nullptr, 0,
                                          zx + t * G4, SEQLEN * G4, pb1, 0,
                                          1, c1, cat[1 - p], 0);
        // layer 2: reads cat[1-p], writes h2_t -> cat[p][:, 512:1024]
        gemm_f16<<<ga, NTHR, GSM_BYTES>>>(BATCH, G4, 1024, cat[1 - p], 1024,
                                          wcp, 1024, nullptr, 0,
                                          nullptr, 0, pb2, 0,
                                          1, c2, cat[p], HID);
    }

    // FC head: relu(h2 @ fc_w + fc_b); final h2 lives in cat[0]
    {
        int pf = (SEQLEN - 1) & 1;
        dim3 gf(NCLS / 128, BATCH / 128);
        gemm_f16<<<gf, NTHR, GSM_BYTES>>>(BATCH, NCLS, HID,
                                          cat[pf] + HID, 1024,
                                          fct, HID, out, NCLS,
                                          nullptr, 0, fcb, 1,
                                          0, nullptr, nullptr, 0);
    }
}

// round 14
// speedup vs baseline: 2.2458x; 1.0167x over previous
#include <cuda_runtime.h>
#include <cuda_fp16.h>
#include <cstdint>
#include <math.h>

#define BATCH 4096
#define HID 512
#define SEQLEN 7
#define FEATP 192
#define G4 2048
#define NCLS 256
#define BT (BATCH * SEQLEN)

// ---------------------------------------------------------------------------
// scratch
// ---------------------------------------------------------------------------
__device__ __align__(16) __half d_seq[BT * FEATP];
__device__ __align__(16) float d_zx[BT * G4];
__device__ __align__(16) __half d_cat0[BATCH * 1024];
__device__ __align__(16) __half d_cat1[BATCH * 1024];
__device__ __align__(16) float d_c1[BATCH * HID];
__device__ __align__(16) float d_c2[BATCH * HID];
__device__ __align__(16) __half d_W1p[G4 * FEATP];
__device__ __align__(16) __half d_U1p[G4 * HID];
__device__ __align__(16) __half d_WCp[G4 * 1024];
__device__ __align__(16) __half d_FCt[NCLS * HID];
__device__ __align__(16) float d_pb1[G4];
__device__ __align__(16) float d_pb2[G4];

// ---------------------------------------------------------------------------
__global__ void init_state(uint32_t* __restrict__ c0, uint32_t* __restrict__ c1h,
                           float* __restrict__ c1, float* __restrict__ c2) {
    int i = blockIdx.x * blockDim.x + threadIdx.x;
    c0[i] = 0u;
    c1h[i] = 0u;
    c1[i] = 0.0f;
    c2[i] = 0.0f;
}

// ---------------------------------------------------------------------------
#define PREP_W1 (G4 * FEATP)
#define PREP_U1 (G4 * HID)
#define PREP_WC (G4 * 1024)
#define PREP_FC (NCLS * HID)
#define PREP_PB (2 * G4)
#define PREP_TOTAL (PREP_W1 + PREP_U1 + PREP_WC + PREP_FC + PREP_PB)

__global__ void prep_weights(const float* __restrict__ W1, const float* __restrict__ U1,
                             const float* __restrict__ W2, const float* __restrict__ U2,
                             const float* __restrict__ FC,
                             const float* __restrict__ b1, const float* __restrict__ b2,
                             __half* __restrict__ w1p, __half* __restrict__ u1p,
                             __half* __restrict__ wcp, __half* __restrict__ fct,
                             float* __restrict__ pb1, float* __restrict__ pb2) {
    int i = blockIdx.x * blockDim.x + threadIdx.x;
    if (i >= PREP_TOTAL) return;
    if (i >= PREP_W1 + PREP_U1 + PREP_WC + PREP_FC) {
        int o = i - (PREP_W1 + PREP_U1 + PREP_WC + PREP_FC);
        int which = o >> 11;
        int np = o & 2047;
        int src = (np & 3) * HID + (np >> 2);
        if (which == 0) pb1[np] = b1[src]; else pb2[np] = b2[src];
        return;
    }
    float v;
    __half* dst;
    int o;
    if (i < PREP_W1) {
        o = i;
        int np = o / FEATP, k = o % FEATP;
        int n = (np & 3) * HID + (np >> 2);
        v = (k < 160) ? W1[(size_t)k * G4 + n] : 0.0f;
        dst = w1p;
    } else if (i < PREP_W1 + PREP_U1) {
        o = i - PREP_W1;
        int np = o >> 9, k = o & 511;
        int n = (np & 3) * HID + (np >> 2);
        v = U1[(size_t)k * G4 + n];
        dst = u1p;
    } else if (i < PREP_W1 + PREP_U1 + PREP_WC) {
        o = i - PREP_W1 - PREP_U1;
        int np = o >> 10, k = o & 1023;
        int n = (np & 3) * HID + (np >> 2);
        v = (k < HID) ? W2[(size_t)k * G4 + n] : U2[(size_t)(k - HID) * G4 + n];
        dst = wcp;
    } else {
        o = i - PREP_W1 - PREP_U1 - PREP_WC;
        int n = o >> 9, k = o & 511;
        v = FC[(size_t)k * NCLS + n];
        dst = fct;
    }
    dst[o] = __float2half_rn(v);
}

// ---------------------------------------------------------------------------
// fused conv1+pool1+conv2+pool2 -> seq fp16; one block per batch sample.
// ---------------------------------------------------------------------------
__global__ __launch_bounds__(256) void conv12_pool(
    const float* __restrict__ x,
    const float* __restrict__ w1, const float* __restrict__ b1,
    const float* __restrict__ w2, const float* __restrict__ b2,
    __half* __restrict__ sh) {
    __shared__ float sIn[15 * 80 * 3];
    __shared__ float sW1[7 * 3 * 3 * 10];
    __shared__ float sP[9 * 26 * 10];
    __shared__ float sW2[3 * 3 * 10 * 20];
    int b = blockIdx.x;
    const float* xb = x + (size_t)b * 3600;
    for (int i = threadIdx.x; i < 3600; i += 256) sIn[i] = xb[i];
    for (int i = threadIdx.x; i < 630; i += 256) sW1[i] = w1[i];
    for (int i = threadIdx.x; i < 1800; i += 256) sW2[i] = w2[i];
    __syncthreads();

    for (int item = threadIdx.x; item < 9 * 260; item += 256) {
        int r = item / 260;
        int rem = item - r * 260;
        int p = rem / 10, co = rem - p * 10;
        float best = -1e30f;
#pragma unroll
        for (int dx = 0; dx < 3; dx++) {
            int cw = p * 3 + dx;
            float acc = 0.0f;
#pragma unroll
            for (int kh = 0; kh < 7; kh++)
#pragma unroll
                for (int kw = 0; kw < 3; kw++)
#pragma unroll
                    for (int ci = 0; ci < 3; ci++)
                        acc += sIn[(r + kh) * 240 + (cw + kw) * 3 + ci] *
                               sW1[((kh * 3 + kw) * 3 + ci) * 10 + co];
            best = fmaxf(best, acc);
        }
        sP[(r * 26 + p) * 10 + co] = fmaxf(best + b1[co], 0.0f);
    }
    __syncthreads();

    for (int item = threadIdx.x; item < 7 * 160; item += 256) {
        int r = item / 160;
        int f = item - r * 160;
        int p = f / 20, co = f - p * 20;
        float best = -1e30f;
#pragma unroll
        for (int dx = 0; dx < 3; dx++) {
            int cw = p * 3 + dx;
            float acc = 0.0f;
#pragma unroll
            for (int kh = 0; kh < 3; kh++)
#pragma unroll
                for (int kw = 0; kw < 3; kw++)
#pragma unroll
                    for (int ci = 0; ci < 10; ci++)
                        acc += sP[((r + kh) * 26 + (cw + kw)) * 10 + ci] *
                               sW2[((kh * 3 + kw) * 10 + ci) * 20 + co];
            best = fmaxf(best, acc);
        }
        float v = fmaxf(best + b2[co], 0.0f);
        sh[(size_t)(b * 7 + r) * FEATP + f] = __float2half_rn(v);
    }
    for (int i = threadIdx.x; i < 7 * 32; i += 256) {
        int r = i >> 5;
        sh[(size_t)(b * 7 + r) * FEATP + 160 + (i & 31)] = __float2half_rn(0.0f);
    }
}

// ---------------------------------------------------------------------------
// dual-job fp16 1-pass GEMM: tile 128x64, 256 thr (8 warps: 4 wm x 2 wn),
// 3-stage cp.async ring, 4 CTAs/SM. Two independent jobs per launch
// (blockIdx.x selects) — used to run layer2(t) and layer1(t+1) concurrently.
// ---------------------------------------------------------------------------
struct GemmJob {
    const __half* A; int lda; int K;
    const __half* B; int ldb;
    const float* Cadd; int ldca;
    const float* bias;
    float* C; int ldc;
    int relu, gate;
    float* cbuf;
    __half* hout; int hoff;
    int nx;                      // N tiles (N = nx*64)
};

#define ROWB 80
#define A_TILE_B (128 * ROWB)        // 10240
#define B_TILE_B (64 * ROWB)         // 5120
#define STAGE_B (A_TILE_B + B_TILE_B) // 15360
#define GSM_BYTES 46080              // 3*STAGE_B; >= epi 128*68*4=34816
#define EPI_PITCH 68
#define NTHR 256

__device__ __forceinline__ uint32_t smem_u32(const void* p) {
    uint32_t a;
    asm("{ .reg .u64 t; cvta.to.shared.u64 t, %1; cvt.u32.u64 %0, t; }" : "=r"(a) : "l"(p));
    return a;
}
__device__ __forceinline__ void cp_async16(uint32_t sa, const void* gaddr) {
    asm volatile("cp.async.cg.shared.global [%0], [%1], 16;" :: "r"(sa), "l"(gaddr) : "memory");
}
__device__ __forceinline__ void ldmx4(uint32_t* r, uint32_t sa) {
    asm volatile("ldmatrix.sync.aligned.m8n8.x4.shared.b16 {%0,%1,%2,%3}, [%4];"
                 : "=r"(r[0]), "=r"(r[1]), "=r"(r[2]), "=r"(r[3]) : "r"(sa));
}
__device__ __forceinline__ void mma_f16(float* c, const uint32_t* a, uint32_t b0, uint32_t b1) {
    asm volatile(
        "mma.sync.aligned.m16n8k16.row.col.f32.f16.f16.f32 "
        "{%0,%1,%2,%3}, {%4,%5,%6,%7}, {%8,%9}, {%0,%1,%2,%3};"
        : "+f"(c[0]), "+f"(c[1]), "+f"(c[2]), "+f"(c[3])
        : "r"(a[0]), "r"(a[1]), "r"(a[2]), "r"(a[3]), "r"(b0), "r"(b1));
}
__device__ __forceinline__ float sigacc(float x) { return 1.0f / (1.0f + expf(-x)); }

__global__ __launch_bounds__(NTHR, 4) void gemm_dual(int M, GemmJob j0, GemmJob j1) {
    extern __shared__ char smem[];
    uint32_t sb0 = smem_u32(smem);
    int tid = threadIdx.x;
    int lane = tid & 31;
    int warp = tid >> 5;           // 0..7
    int wm = warp >> 1;            // 0..3 -> 32-row slab
    int wn = warp & 1;             // 0..1 -> 32-col slab
    int gid = lane >> 2;
    int tig = lane & 3;
    int lane15 = lane & 15;
    int halfsel = (lane >> 4) << 4;

    int isj0 = (int)(blockIdx.x < (unsigned)j0.nx);
    GemmJob j = isj0 ? j0 : j1;
    int bn = (isj0 ? blockIdx.x : blockIdx.x - j0.nx) * 64;
    int bm = blockIdx.y * 128;

    const __half* A0 = j.A + (size_t)bm * j.lda;
    const __half* B0 = j.B + (size_t)bn * j.ldb;
    int lda = j.lda, ldb = j.ldb;

    float acc[2][4][4];
#pragma unroll
    for (int i = 0; i < 2; i++)
#pragma unroll
        for (int jj = 0; jj < 4; jj++)
#pragma unroll
            for (int r = 0; r < 4; r++) acc[i][jj][r] = 0.0f;

    int nst = j.K >> 5;

    // copy coords: 3 chunks/thread: A rows tid>>2 and 64+(tid>>2), B row tid>>2
    int cp_row = tid >> 2, cp_c4 = tid & 3;

#define ISSUE_STAGE(kt, slot) do {                                             \
        if ((kt) < nst) {                                                      \
            uint32_t st = sb0 + (slot) * STAGE_B;                              \
            int k0 = (kt) << 5;                                                \
            uint32_t sa = st + cp_row * ROWB + cp_c4 * 16;                     \
            cp_async16(sa, A0 + (size_t)cp_row * lda + k0 + cp_c4 * 8);        \
            cp_async16(sa + 64 * ROWB,                                         \
                       A0 + (size_t)(cp_row + 64) * lda + k0 + cp_c4 * 8);     \
            cp_async16(st + A_TILE_B + cp_row * ROWB + cp_c4 * 16,             \
                       B0 + (size_t)cp_row * ldb + k0 + cp_c4 * 8);            \
        }                                                                      \
        asm volatile("cp.async.commit_group;" ::: "memory");                   \
    } while (0)

    ISSUE_STAGE(0, 0);
    ISSUE_STAGE(1, 1);

    int slot = 0, slot2 = 2;
    for (int kt = 0; kt < nst; kt++) {
        asm volatile("cp.async.wait_group 1;" ::: "memory");
        __syncthreads();
        ISSUE_STAGE(kt + 2, slot2);

        uint32_t st = sb0 + slot * STAGE_B;
        uint32_t aAddr = st + (uint32_t)((wm * 32 + lane15) * ROWB) + halfsel;
        uint32_t bAddr = st + A_TILE_B + (uint32_t)((wn * 32 + lane15) * ROWB) + halfsel;

#pragma unroll
        for (int k16 = 0; k16 < 2; k16++) {
            uint32_t kb = k16 * 32;
            uint32_t af[2][4], bf[2][4];
            ldmx4(af[0], aAddr + kb);
            ldmx4(af[1], aAddr + 16 * ROWB + kb);
            ldmx4(bf[0], bAddr + kb);
            ldmx4(bf[1], bAddr + 16 * ROWB + kb);
#pragma unroll
            for (int nb = 0; nb < 2; nb++) {
#pragma unroll
                for (int hf = 0; hf < 2; hf++) {
                    int na = nb * 2 + hf;
#pragma unroll
                    for (int ma = 0; ma < 2; ma++)
                        mma_f16(acc[ma][na], af[ma], bf[nb][hf], bf[nb][2 + hf]);
                }
            }
        }
        slot = (slot == 2) ? 0 : slot + 1;
        slot2 = (slot2 == 2) ? 0 : slot2 + 1;
    }
    __syncthreads();

    // ---- epilogue ----
    if (j.gate) {
        float* sg = (float*)smem;
#pragma unroll
        for (int ma = 0; ma < 2; ma++) {
#pragma unroll
            for (int na = 0; na < 4; na++) {
                int rl = wm * 32 + ma * 16 + gid;
                int cl = wn * 32 + na * 8 + 2 * tig;
                int row0 = bm + rl;
                int col0 = bn + cl;
                float v0 = acc[ma][na][0], v1 = acc[ma][na][1];
                float v2 = acc[ma][na][2], v3 = acc[ma][na][3];
                if (j.Cadd) {
                    float2 ca = *(const float2*)(j.Cadd + (size_t)row0 * j.ldca + col0);
                    float2 cb = *(const float2*)(j.Cadd + (size_t)(row0 + 8) * j.ldca + col0);
                    v0 += ca.x; v1 += ca.y; v2 += cb.x; v3 += cb.y;
                }
                float bb0 = j.bias[col0], bb1 = j.bias[col0 + 1];
                *(float2*)&sg[rl * EPI_PITCH + cl] = make_float2(v0 + bb0, v1 + bb1);
                *(float2*)&sg[(rl + 8) * EPI_PITCH + cl] = make_float2(v2 + bb0, v3 + bb1);
            }
        }
        __syncthreads();
        int jb = bn >> 2;
#pragma unroll
        for (int it = 0; it < 8; it++) {
            int idx = it * NTHR + tid;       // 0..2047 over 128 rows x 16 j
            int rl = idx >> 4, jl = idx & 15;
            float4 g = *(const float4*)&sg[rl * EPI_PITCH + jl * 4];
            int grow = bm + rl;
            int jcol = jb + jl;
            size_t cidx = (size_t)grow * HID + jcol;
            float cv = sigacc(g.y) * j.cbuf[cidx] + sigacc(g.x) * tanhf(g.z);
            j.cbuf[cidx] = cv;
            float h = sigacc(g.w) * tanhf(cv);
            j.hout[(size_t)grow * 1024 + j.hoff + jcol] = __float2half_rn(h);
        }
    } else {
#pragma unroll
        for (int ma = 0; ma < 2; ma++) {
#pragma unroll
            for (int na = 0; na < 4; na++) {
                int row0 = bm + wm * 32 + ma * 16 + gid;
                int col = bn + wn * 32 + na * 8 + 2 * tig;
                float v0 = acc[ma][na][0], v1 = acc[ma][na][1];
                float v2 = acc[ma][na][2], v3 = acc[ma][na][3];
                if (j.bias) {
                    float bb0 = j.bias[col], bb1 = j.bias[col + 1];
                    v0 += bb0; v1 += bb1; v2 += bb0; v3 += bb1;
                }
                if (j.relu) {
                    v0 = fmaxf(v0, 0.0f); v1 = fmaxf(v1, 0.0f);
                    v2 = fmaxf(v2, 0.0f); v3 = fmaxf(v3, 0.0f);
                }
                *(float2*)(j.C + (size_t)row0 * j.ldc + col) = make_float2(v0, v1);
                *(float2*)(j.C + (size_t)(row0 + 8) * j.ldc + col) = make_float2(v2, v3);
            }
        }
    }
#undef ISSUE_STAGE
}

// ---------------------------------------------------------------------------
// launch
// ---------------------------------------------------------------------------
extern "C" void kernel_launch(void* const* d_in, const int* in_sizes, int n_in,
                              void* d_out, int out_size) {
    const float* x = (const float*)d_in[0];
    const float* c1w = (const float*)d_in[1];
    const float* c1b = (const float*)d_in[2];
    const float* c2w = (const float*)d_in[3];
    const float* c2b = (const float*)d_in[4];
    const float* W1 = (const float*)d_in[5];
    const float* U1 = (const float*)d_in[6];
    const float* b1 = (const float*)d_in[7];
    const float* W2 = (const float*)d_in[8];
    const float* U2 = (const float*)d_in[9];
    const float* b2 = (const float*)d_in[10];
    const float* fcw = (const float*)d_in[11];
    const float* fcb = (const float*)d_in[12];
    float* out = (float*)d_out;

    float *zx, *c1, *c2, *pb1, *pb2;
    __half *seqh;
    __half *cat[2];
    __half *w1p, *u1p, *wcp, *fct;
    cudaGetSymbolAddress((void**)&zx, d_zx);
    cudaGetSymbolAddress((void**)&c1, d_c1);
    cudaGetSymbolAddress((void**)&c2, d_c2);
    cudaGetSymbolAddress((void**)&pb1, d_pb1);
    cudaGetSymbolAddress((void**)&pb2, d_pb2);
    cudaGetSymbolAddress((void**)&seqh, d_seq);
    cudaGetSymbolAddress((void**)&cat[0], d_cat0);
    cudaGetSymbolAddress((void**)&cat[1], d_cat1);
    cudaGetSymbolAddress((void**)&w1p, d_W1p);
    cudaGetSymbolAddress((void**)&u1p, d_U1p);
    cudaGetSymbolAddress((void**)&wcp, d_WCp);
    cudaGetSymbolAddress((void**)&fct, d_FCt);

    cudaFuncSetAttribute(gemm_dual, cudaFuncAttributeMaxDynamicSharedMemorySize, GSM_BYTES);

    init_state<<<(BATCH * 1024 / 2) / 256, 256>>>(
        (uint32_t*)cat[0], (uint32_t*)cat[1], c1, c2);
    prep_weights<<<(PREP_TOTAL + 255) / 256, 256>>>(W1, U1, W2, U2, fcw, b1, b2,
                                                    w1p, u1p, wcp, fct, pb1, pb2);
    conv12_pool<<<BATCH, 256>>>(x, c1w, c1b, c2w, c2b, seqh);

    GemmJob nil{};
    nil.nx = 0;

    // layer-1 job for timestep t (reads cat[(t)&1], writes cat[1-(t&1)][0:512])
    auto L1 = [&](int t) {
        GemmJob jb{};
        int p = t & 1;
        jb.A = cat[p]; jb.lda = 1024; jb.K = HID;
        jb.B = u1p; jb.ldb = HID;
        jb.Cadd = zx + t * G4; jb.ldca = SEQLEN * G4;
        jb.bias = pb1;
        jb.C = nullptr; jb.ldc = 0; jb.relu = 0; jb.gate = 1;
        jb.cbuf = c1; jb.hout = cat[1 - p]; jb.hoff = 0;
        jb.nx = G4 / 64;
        return jb;
    };
    // layer-2 job for timestep t (reads cat[1-(t&1)], writes cat[t&1][512:1024])
    auto L2 = [&](int t) {
        GemmJob jb{};
        int p = t & 1;
        jb.A = cat[1 - p]; jb.lda = 1024; jb.K = 1024;
        jb.B = wcp; jb.ldb = 1024;
        jb.Cadd = nullptr; jb.ldca = 0;
        jb.bias = pb2;
        jb.C = nullptr; jb.ldc = 0; jb.relu = 0; jb.gate = 1;
        jb.cbuf = c2; jb.hout = cat[p]; jb.hoff = HID;
        jb.nx = G4 / 64;
        return jb;
    };

    // zx = seq @ W1p : [28672,192] x [192,2048]
    {
        GemmJob jb{};
        jb.A = seqh; jb.lda = FEATP; jb.K = FEATP;
        jb.B = w1p; jb.ldb = FEATP;
        jb.Cadd = nullptr; jb.ldca = 0; jb.bias = nullptr;
        jb.C = zx; jb.ldc = G4; jb.relu = 0; jb.gate = 0;
        jb.cbuf = nullptr; jb.hout = nullptr; jb.hoff = 0;
        jb.nx = G4 / 64;
        dim3 g(jb.nx, BT / 128);
        gemm_dual<<<g, NTHR, GSM_BYTES>>>(BT, jb, nil);
    }

    // L1(0)
    {
        GemmJob jb = L1(0);
        dim3 g(jb.nx, BATCH / 128);
        gemm_dual<<<g, NTHR, GSM_BYTES>>>(BATCH, jb, nil);
    }
    // combined phases: {L2(t) || L1(t+1)} for t = 0..5
    for (int t = 0; t < SEQLEN - 1; t++) {
        GemmJob ja = L2(t);
        GemmJob jb = L1(t + 1);
        dim3 g(ja.nx + jb.nx, BATCH / 128);
        gemm_dual<<<g, NTHR, GSM_BYTES>>>(BATCH, ja, jb);
    }
    // L2(6)
    {
        GemmJob jb = L2(SEQLEN - 1);
        dim3 g(jb.nx, BATCH / 128);
        gemm_dual<<<g, NTHR, GSM_BYTES>>>(BATCH, jb, nil);
    }

    // FC head: relu(h2 @ fc_w + fc_b); final h2 in cat[(SEQLEN-1)&1] = cat[0]
    {
        GemmJob jb{};
        int pf = (SEQLEN - 1) & 1;
        jb.A = cat[pf] + HID; jb.lda = 1024; jb.K = HID;
        jb.B = fct; jb.ldb = HID;
        jb.Cadd = nullptr; jb.ldca = 0; jb.bias = fcb;
        jb.C = out; jb.ldc = NCLS; jb.relu = 1; jb.gate = 0;
        jb.cbuf = nullptr; jb.hout = nullptr; jb.hoff = 0;
        jb.nx = NCLS / 64;
        dim3 g(jb.nx, BATCH / 128);
        gemm_dual<<<g, NTHR, GSM_BYTES>>>(BATCH, jb, nil);
    }
}

// round 15
// speedup vs baseline: 2.2572x; 1.0051x over previous
#include <cuda_runtime.h>
#include <cuda_fp16.h>
#include <cstdint>
#include <math.h>

#define BATCH 4096
#define HID 512
#define SEQLEN 7
#define FEATP 192
#define G4 2048
#define NCLS 256
#define BT (BATCH * SEQLEN)

// ---------------------------------------------------------------------------
// scratch
// ---------------------------------------------------------------------------
__device__ __align__(16) __half d_seq[BT * FEATP];
__device__ __align__(16) float d_zx[BT * G4];
__device__ __align__(16) __half d_cat0[BATCH * 1024];
__device__ __align__(16) __half d_cat1[BATCH * 1024];
__device__ __align__(16) float d_c1[BATCH * HID];
__device__ __align__(16) float d_c2[BATCH * HID];
__device__ __align__(16) __half d_W1p[G4 * FEATP];
__device__ __align__(16) __half d_U1p[G4 * HID];
__device__ __align__(16) __half d_WCp[G4 * 1024];
__device__ __align__(16) __half d_FCt[NCLS * HID];
__device__ __align__(16) float d_pb1[G4];
__device__ __align__(16) float d_pb2[G4];

// ---------------------------------------------------------------------------
__global__ void init_state(uint32_t* __restrict__ c0, uint32_t* __restrict__ c1h,
                           float* __restrict__ c1, float* __restrict__ c2) {
    int i = blockIdx.x * blockDim.x + threadIdx.x;
    c0[i] = 0u;
    c1h[i] = 0u;
    c1[i] = 0.0f;
    c2[i] = 0.0f;
}

// ---------------------------------------------------------------------------
#define PREP_W1 (G4 * FEATP)
#define PREP_U1 (G4 * HID)
#define PREP_WC (G4 * 1024)
#define PREP_FC (NCLS * HID)
#define PREP_PB (2 * G4)
#define PREP_TOTAL (PREP_W1 + PREP_U1 + PREP_WC + PREP_FC + PREP_PB)

__global__ void prep_weights(const float* __restrict__ W1, const float* __restrict__ U1,
                             const float* __restrict__ W2, const float* __restrict__ U2,
                             const float* __restrict__ FC,
                             const float* __restrict__ b1, const float* __restrict__ b2,
                             __half* __restrict__ w1p, __half* __restrict__ u1p,
                             __half* __restrict__ wcp, __half* __restrict__ fct,
                             float* __restrict__ pb1, float* __restrict__ pb2) {
    int i = blockIdx.x * blockDim.x + threadIdx.x;
    if (i >= PREP_TOTAL) return;
    if (i >= PREP_W1 + PREP_U1 + PREP_WC + PREP_FC) {
        int o = i - (PREP_W1 + PREP_U1 + PREP_WC + PREP_FC);
        int which = o >> 11;
        int np = o & 2047;
        int src = (np & 3) * HID + (np >> 2);
        if (which == 0) pb1[np] = b1[src]; else pb2[np] = b2[src];
        return;
    }
    float v;
    __half* dst;
    int o;
    if (i < PREP_W1) {
        o = i;
        int np = o / FEATP, k = o % FEATP;
        int n = (np & 3) * HID + (np >> 2);
        v = (k < 160) ? W1[(size_t)k * G4 + n] : 0.0f;
        dst = w1p;
    } else if (i < PREP_W1 + PREP_U1) {
        o = i - PREP_W1;
        int np = o >> 9, k = o & 511;
        int n = (np & 3) * HID + (np >> 2);
        v = U1[(size_t)k * G4 + n];
        dst = u1p;
    } else if (i < PREP_W1 + PREP_U1 + PREP_WC) {
        o = i - PREP_W1 - PREP_U1;
        int np = o >> 10, k = o & 1023;
        int n = (np & 3) * HID + (np >> 2);
        v = (k < HID) ? W2[(size_t)k * G4 + n] : U2[(size_t)(k - HID) * G4 + n];
        dst = wcp;
    } else {
        o = i - PREP_W1 - PREP_U1 - PREP_WC;
        int n = o >> 9, k = o & 511;
        v = FC[(size_t)k * NCLS + n];
        dst = fct;
    }
    dst[o] = __float2half_rn(v);
}

// ---------------------------------------------------------------------------
// fused conv1+pool1+conv2+pool2 -> seq fp16; one block per batch sample.
// ---------------------------------------------------------------------------
__global__ __launch_bounds__(256) void conv12_pool(
    const float* __restrict__ x,
    const float* __restrict__ w1, const float* __restrict__ b1,
    const float* __restrict__ w2, const float* __restrict__ b2,
    __half* __restrict__ sh) {
    __shared__ float sIn[15 * 80 * 3];
    __shared__ float sW1[7 * 3 * 3 * 10];
    __shared__ float sP[9 * 26 * 10];
    __shared__ float sW2[3 * 3 * 10 * 20];
    int b = blockIdx.x;
    const float* xb = x + (size_t)b * 3600;
    for (int i = threadIdx.x; i < 3600; i += 256) sIn[i] = xb[i];
    for (int i = threadIdx.x; i < 630; i += 256) sW1[i] = w1[i];
    for (int i = threadIdx.x; i < 1800; i += 256) sW2[i] = w2[i];
    __syncthreads();

    for (int item = threadIdx.x; item < 9 * 260; item += 256) {
        int r = item / 260;
        int rem = item - r * 260;
        int p = rem / 10, co = rem - p * 10;
        float best = -1e30f;
#pragma unroll
        for (int dx = 0; dx < 3; dx++) {
            int cw = p * 3 + dx;
            float acc = 0.0f;
#pragma unroll
            for (int kh = 0; kh < 7; kh++)
#pragma unroll
                for (int kw = 0; kw < 3; kw++)
#pragma unroll
                    for (int ci = 0; ci < 3; ci++)
                        acc += sIn[(r + kh) * 240 + (cw + kw) * 3 + ci] *
                               sW1[((kh * 3 + kw) * 3 + ci) * 10 + co];
            best = fmaxf(best, acc);
        }
        sP[(r * 26 + p) * 10 + co] = fmaxf(best + b1[co], 0.0f);
    }
    __syncthreads();

    for (int item = threadIdx.x; item < 7 * 160; item += 256) {
        int r = item / 160;
        int f = item - r * 160;
        int p = f / 20, co = f - p * 20;
        float best = -1e30f;
#pragma unroll
        for (int dx = 0; dx < 3; dx++) {
            int cw = p * 3 + dx;
            float acc = 0.0f;
#pragma unroll
            for (int kh = 0; kh < 3; kh++)
#pragma unroll
                for (int kw = 0; kw < 3; kw++)
#pragma unroll
                    for (int ci = 0; ci < 10; ci++)
                        acc += sP[((r + kh) * 26 + (cw + kw)) * 10 + ci] *
                               sW2[((kh * 3 + kw) * 10 + ci) * 20 + co];
            best = fmaxf(best, acc);
        }
        float v = fmaxf(best + b2[co], 0.0f);
        sh[(size_t)(b * 7 + r) * FEATP + f] = __float2half_rn(v);
    }
    for (int i = threadIdx.x; i < 7 * 32; i += 256) {
        int r = i >> 5;
        sh[(size_t)(b * 7 + r) * FEATP + 160 + (i & 31)] = __float2half_rn(0.0f);
    }
}

// ---------------------------------------------------------------------------
// dual-job fp16 1-pass GEMM: tile 128x64, 256 thr (8 warps: 4 wm x 2 wn),
// 3-stage cp.async ring, 4 CTAs/SM. Two independent jobs per launch
// (blockIdx.x selects) — used to run layer2(t) and layer1(t+1) concurrently.
// ---------------------------------------------------------------------------
struct GemmJob {
    const __half* A; int lda; int K;
    const __half* B; int ldb;
    const float* Cadd; int ldca;
    const float* bias;
    float* C; int ldc;
    int relu, gate;
    float* cbuf;
    __half* hout; int hoff;
    int nx;                      // N tiles (N = nx*64)
};

#define ROWB 80
#define A_TILE_B (128 * ROWB)        // 10240
#define B_TILE_B (64 * ROWB)         // 5120
#define STAGE_B (A_TILE_B + B_TILE_B) // 15360
#define GSM_BYTES 46080              // 3*STAGE_B; >= epi 128*68*4=34816
#define EPI_PITCH 68
#define NTHR 256

__device__ __forceinline__ uint32_t smem_u32(const void* p) {
    uint32_t a;
    asm("{ .reg .u64 t; cvta.to.shared.u64 t, %1; cvt.u32.u64 %0, t; }" : "=r"(a) : "l"(p));
    return a;
}
__device__ __forceinline__ void cp_async16(uint32_t sa, const void* gaddr) {
    asm volatile("cp.async.cg.shared.global [%0], [%1], 16;" :: "r"(sa), "l"(gaddr) : "memory");
}
__device__ __forceinline__ void ldmx4(uint32_t* r, uint32_t sa) {
    asm volatile("ldmatrix.sync.aligned.m8n8.x4.shared.b16 {%0,%1,%2,%3}, [%4];"
                 : "=r"(r[0]), "=r"(r[1]), "=r"(r[2]), "=r"(r[3]) : "r"(sa));
}
__device__ __forceinline__ void mma_f16(float* c, const uint32_t* a, uint32_t b0, uint32_t b1) {
    asm volatile(
        "mma.sync.aligned.m16n8k16.row.col.f32.f16.f16.f32 "
        "{%0,%1,%2,%3}, {%4,%5,%6,%7}, {%8,%9}, {%0,%1,%2,%3};"
        : "+f"(c[0]), "+f"(c[1]), "+f"(c[2]), "+f"(c[3])
        : "r"(a[0]), "r"(a[1]), "r"(a[2]), "r"(a[3]), "r"(b0), "r"(b1));
}
__device__ __forceinline__ float sigacc(float x) { return 1.0f / (1.0f + expf(-x)); }

__global__ __launch_bounds__(NTHR, 4) void gemm_dual(int M, GemmJob j0, GemmJob j1) {
    extern __shared__ char smem[];
    uint32_t sb0 = smem_u32(smem);
    int tid = threadIdx.x;
    int lane = tid & 31;
    int warp = tid >> 5;           // 0..7
    int wm = warp >> 1;            // 0..3 -> 32-row slab
    int wn = warp & 1;             // 0..1 -> 32-col slab
    int gid = lane >> 2;
    int tig = lane & 3;
    int lane15 = lane & 15;
    int halfsel = (lane >> 4) << 4;

    int isj0 = (int)(blockIdx.x < (unsigned)j0.nx);
    GemmJob j = isj0 ? j0 : j1;
    int bn = (isj0 ? blockIdx.x : blockIdx.x - j0.nx) * 64;
    int bm = blockIdx.y * 128;

    const __half* A0 = j.A + (size_t)bm * j.lda;
    const __half* B0 = j.B + (size_t)bn * j.ldb;
    int lda = j.lda, ldb = j.ldb;

    float acc[2][4][4];
#pragma unroll
    for (int i = 0; i < 2; i++)
#pragma unroll
        for (int jj = 0; jj < 4; jj++)
#pragma unroll
            for (int r = 0; r < 4; r++) acc[i][jj][r] = 0.0f;

    int nst = j.K >> 5;

    // copy coords: 3 chunks/thread: A rows tid>>2 and 64+(tid>>2), B row tid>>2
    int cp_row = tid >> 2, cp_c4 = tid & 3;

#define ISSUE_STAGE(kt, slot) do {                                             \
        if ((kt) < nst) {                                                      \
            uint32_t st = sb0 + (slot) * STAGE_B;                              \
            int k0 = (kt) << 5;                                                \
            uint32_t sa = st + cp_row * ROWB + cp_c4 * 16;                     \
            cp_async16(sa, A0 + (size_t)cp_row * lda + k0 + cp_c4 * 8);        \
            cp_async16(sa + 64 * ROWB,                                         \
                       A0 + (size_t)(cp_row + 64) * lda + k0 + cp_c4 * 8);     \
            cp_async16(st + A_TILE_B + cp_row * ROWB + cp_c4 * 16,             \
                       B0 + (size_t)cp_row * ldb + k0 + cp_c4 * 8);            \
        }                                                                      \
        asm volatile("cp.async.commit_group;" ::: "memory");                   \
    } while (0)

    ISSUE_STAGE(0, 0);
    ISSUE_STAGE(1, 1);

    int slot = 0, slot2 = 2;
    for (int kt = 0; kt < nst; kt++) {
        asm volatile("cp.async.wait_group 1;" ::: "memory");
        __syncthreads();
        ISSUE_STAGE(kt + 2, slot2);

        uint32_t st = sb0 + slot * STAGE_B;
        uint32_t aAddr = st + (uint32_t)((wm * 32 + lane15) * ROWB) + halfsel;
        uint32_t bAddr = st + A_TILE_B + (uint32_t)((wn * 32 + lane15) * ROWB) + halfsel;

#pragma unroll
        for (int k16 = 0; k16 < 2; k16++) {
            uint32_t kb = k16 * 32;
            uint32_t af[2][4], bf[2][4];
            ldmx4(af[0], aAddr + kb);
            ldmx4(af[1], aAddr + 16 * ROWB + kb);
            ldmx4(bf[0], bAddr + kb);
            ldmx4(bf[1], bAddr + 16 * ROWB + kb);
#pragma unroll
            for (int nb = 0; nb < 2; nb++) {
#pragma unroll
                for (int hf = 0; hf < 2; hf++) {
                    int na = nb * 2 + hf;
#pragma unroll
                    for (int ma = 0; ma < 2; ma++)
                        mma_f16(acc[ma][na], af[ma], bf[nb][hf], bf[nb][2 + hf]);
                }
            }
        }
        slot = (slot == 2) ? 0 : slot + 1;
        slot2 = (slot2 == 2) ? 0 : slot2 + 1;
    }
    __syncthreads();

    // ---- epilogue ----
    if (j.gate) {
        float* sg = (float*)smem;
#pragma unroll
        for (int ma = 0; ma < 2; ma++) {
#pragma unroll
            for (int na = 0; na < 4; na++) {
                int rl = wm * 32 + ma * 16 + gid;
                int cl = wn * 32 + na * 8 + 2 * tig;
                int row0 = bm + rl;
                int col0 = bn + cl;
                float v0 = acc[ma][na][0], v1 = acc[ma][na][1];
                float v2 = acc[ma][na][2], v3 = acc[ma][na][3];
                if (j.Cadd) {
                    float2 ca = *(const float2*)(j.Cadd + (size_t)row0 * j.ldca + col0);
                    float2 cb = *(const float2*)(j.Cadd + (size_t)(row0 + 8) * j.ldca + col0);
                    v0 += ca.x; v1 += ca.y; v2 += cb.x; v3 += cb.y;
                }
                float bb0 = j.bias[col0], bb1 = j.bias[col0 + 1];
                *(float2*)&sg[rl * EPI_PITCH + cl] = make_float2(v0 + bb0, v1 + bb1);
                *(float2*)&sg[(rl + 8) * EPI_PITCH + cl] = make_float2(v2 + bb0, v3 + bb1);
            }
        }
        __syncthreads();
        int jb = bn >> 2;
#pragma unroll
        for (int it = 0; it < 8; it++) {
            int idx = it * NTHR + tid;       // 0..2047 over 128 rows x 16 j
            int rl = idx >> 4, jl = idx & 15;
            float4 g = *(const float4*)&sg[rl * EPI_PITCH + jl * 4];
            int grow = bm + rl;
            int jcol = jb + jl;
            size_t cidx = (size_t)grow * HID + jcol;
            float cv = sigacc(g.y) * j.cbuf[cidx] + sigacc(g.x) * tanhf(g.z);
            j.cbuf[cidx] = cv;
            float h = sigacc(g.w) * tanhf(cv);
            j.hout[(size_t)grow * 1024 + j.hoff + jcol] = __float2half_rn(h);
        }
    } else {
#pragma unroll
        for (int ma = 0; ma < 2; ma++) {
#pragma unroll
            for (int na = 0; na < 4; na++) {
                int row0 = bm + wm * 32 + ma * 16 + gid;
                int col = bn + wn * 32 + na * 8 + 2 * tig;
                float v0 = acc[ma][na][0], v1 = acc[ma][na][1];
                float v2 = acc[ma][na][2], v3 = acc[ma][na][3];
                if (j.bias) {
                    float bb0 = j.bias[col], bb1 = j.bias[col + 1];
                    v0 += bb0; v1 += bb1; v2 += bb0; v3 += bb1;
                }
                if (j.relu) {
                    v0 = fmaxf(v0, 0.0f); v1 = fmaxf(v1, 0.0f);
                    v2 = fmaxf(v2, 0.0f); v3 = fmaxf(v3, 0.0f);
                }
                *(float2*)(j.C + (size_t)row0 * j.ldc + col) = make_float2(v0, v1);
                *(float2*)(j.C + (size_t)(row0 + 8) * j.ldc + col) = make_float2(v2, v3);
            }
        }
    }
#undef ISSUE_STAGE
}

// ---------------------------------------------------------------------------
// launch
// ---------------------------------------------------------------------------
extern "C" void kernel_launch(void* const* d_in, const int* in_sizes, int n_in,
                              void* d_out, int out_size) {
    const float* x = (const float*)d_in[0];
    const float* c1w = (const float*)d_in[1];
    const float* c1b = (const float*)d_in[2];
    const float* c2w = (const float*)d_in[3];
    const float* c2b = (const float*)d_in[4];
    const float* W1 = (const float*)d_in[5];
    const float* U1 = (const float*)d_in[6];
    const float* b1 = (const float*)d_in[7];
    const float* W2 = (const float*)d_in[8];
    const float* U2 = (const float*)d_in[9];
    const float* b2 = (const float*)d_in[10];
    const float* fcw = (const float*)d_in[11];
    const float* fcb = (const float*)d_in[12];
    float* out = (float*)d_out;

    float *zx, *c1, *c2, *pb1, *pb2;
    __half *seqh;
    __half *cat[2];
    __half *w1p, *u1p, *wcp, *fct;
    cudaGetSymbolAddress((void**)&zx, d_zx);
    cudaGetSymbolAddress((void**)&c1, d_c1);
    cudaGetSymbolAddress((void**)&c2, d_c2);
    cudaGetSymbolAddress((void**)&pb1, d_pb1);
    cudaGetSymbolAddress((void**)&pb2, d_pb2);
    cudaGetSymbolAddress((void**)&seqh, d_seq);
    cudaGetSymbolAddress((void**)&cat[0], d_cat0);
    cudaGetSymbolAddress((void**)&cat[1], d_cat1);
    cudaGetSymbolAddress((void**)&w1p, d_W1p);
    cudaGetSymbolAddress((void**)&u1p, d_U1p);
    cudaGetSymbolAddress((void**)&wcp, d_WCp);
    cudaGetSymbolAddress((void**)&fct, d_FCt);

    cudaFuncSetAttribute(gemm_dual, cudaFuncAttributeMaxDynamicSharedMemorySize, GSM_BYTES);

    init_state<<<(BATCH * 1024 / 2) / 256, 256>>>(
        (uint32_t*)cat[0], (uint32_t*)cat[1], c1, c2);
    prep_weights<<<(PREP_TOTAL + 255) / 256, 256>>>(W1, U1, W2, U2, fcw, b1, b2,
                                                    w1p, u1p, wcp, fct, pb1, pb2);
    conv12_pool<<<BATCH, 256>>>(x, c1w, c1b, c2w, c2b, seqh);

    GemmJob nil{};
    nil.nx = 0;

    // layer-1 job for timestep t (reads cat[(t)&1], writes cat[1-(t&1)][0:512])
    auto L1 = [&](int t) {
        GemmJob jb{};
        int p = t & 1;
        jb.A = cat[p]; jb.lda = 1024; jb.K = HID;
        jb.B = u1p; jb.ldb = HID;
        jb.Cadd = zx + t * G4; jb.ldca = SEQLEN * G4;
        jb.bias = pb1;
        jb.C = nullptr; jb.ldc = 0; jb.relu = 0; jb.gate = 1;
        jb.cbuf = c1; jb.hout = cat[1 - p]; jb.hoff = 0;
        jb.nx = G4 / 64;
        return jb;
    };
    // layer-2 job for timestep t (reads cat[1-(t&1)], writes cat[t&1][512:1024])
    auto L2 = [&](int t) {
        GemmJob jb{};
        int p = t & 1;
        jb.A = cat[1 - p]; jb.lda = 1024; jb.K = 1024;
        jb.B = wcp; jb.ldb = 1024;
        jb.Cadd = nullptr; jb.ldca = 0;
        jb.bias = pb2;
        jb.C = nullptr; jb.ldc = 0; jb.relu = 0; jb.gate = 1;
        jb.cbuf = c2; jb.hout = cat[p]; jb.hoff = HID;
        jb.nx = G4 / 64;
        return jb;
    };

    // zx = seq @ W1p : [28672,192] x [192,2048]
    {
        GemmJob jb{};
        jb.A = seqh; jb.lda = FEATP; jb.K = FEATP;
        jb.B = w1p; jb.ldb = FEATP;
        jb.Cadd = nullptr; jb.ldca = 0; jb.bias = nullptr;
        jb.C = zx; jb.ldc = G4; jb.relu = 0; jb.gate = 0;
        jb.cbuf = nullptr; jb.hout = nullptr; jb.hoff = 0;
        jb.nx = G4 / 64;
        dim3 g(jb.nx, BT / 128);
        gemm_dual<<<g, NTHR, GSM_BYTES>>>(BT, jb, nil);
    }

    // L1(0)
    {
        GemmJob jb = L1(0);
        dim3 g(jb.nx, BATCH / 128);
        gemm_dual<<<g, NTHR, GSM_BYTES>>>(BATCH, jb, nil);
    }
    // combined phases: {L2(t) || L1(t+1)} for t = 0..5
    for (int t = 0; t < SEQLEN - 1; t++) {
        GemmJob ja = L2(t);
        GemmJob jb = L1(t + 1);
        dim3 g(ja.nx + jb.nx, BATCH / 128);
        gemm_dual<<<g, NTHR, GSM_BYTES>>>(BATCH, ja, jb);
    }
    // L2(6)
    {
        GemmJob jb = L2(SEQLEN - 1);
        dim3 g(jb.nx, BATCH / 128);
        gemm_dual<<<g, NTHR, GSM_BYTES>>>(BATCH, jb, nil);
    }

    // FC head: relu(h2 @ fc_w + fc_b); final h2 in cat[(SEQLEN-1)&1] = cat[0]
    {
        GemmJob jb{};
        int pf = (SEQLEN - 1) & 1;
        jb.A = cat[pf] + HID; jb.lda = 1024; jb.K = HID;
        jb.B = fct; jb.ldb = HID;
        jb.Cadd = nullptr; jb.ldca = 0; jb.bias = fcb;
        jb.C = out; jb.ldc = NCLS; jb.relu = 1; jb.gate = 0;
        jb.cbuf = nullptr; jb.hout = nullptr; jb.hoff = 0;
        jb.nx = NCLS / 64;
        dim3 g(jb.nx, BATCH / 128);
        gemm_dual<<<g, NTHR, GSM_BYTES>>>(BATCH, jb, nil);
    }
}

// round 16
// speedup vs baseline: 2.3963x; 1.0616x over previous
#include <cuda_runtime.h>
#include <cuda_fp16.h>
#include <cstdint>
#include <math.h>

#define BATCH 4096
#define HID 512
#define SEQLEN 7
#define SEQF 160                 // conv feature dim (no padding; 160 % 32 == 0)
#define G4 2048
#define NCLS 256
#define BT (BATCH * SEQLEN)
#define KL1 (HID + SEQF)         // 672: fused [h1 | x_t] K for layer 1

// ---------------------------------------------------------------------------
// scratch
// ---------------------------------------------------------------------------
__device__ __align__(16) __half d_seq[BT * SEQF];
__device__ __align__(16) __half d_cat0[BATCH * 1024];
__device__ __align__(16) __half d_cat1[BATCH * 1024];
__device__ __align__(16) float d_c1[BATCH * HID];
__device__ __align__(16) float d_c2[BATCH * HID];
// weights: transposed [N,K], gate-permuted cols (col' = 4j+g), fp16
__device__ __align__(16) __half d_UWp[G4 * KL1];    // [U1;W1] fused along K
__device__ __align__(16) __half d_WCp[G4 * 1024];   // [W2;U2]
__device__ __align__(16) __half d_FCt[NCLS * HID];
__device__ __align__(16) float d_pb1[G4];
__device__ __align__(16) float d_pb2[G4];

// ---------------------------------------------------------------------------
__global__ void init_state(uint32_t* __restrict__ c0, uint32_t* __restrict__ c1h,
                           float* __restrict__ c1, float* __restrict__ c2) {
    int i = blockIdx.x * blockDim.x + threadIdx.x;
    c0[i] = 0u;
    c1h[i] = 0u;
    c1[i] = 0.0f;
    c2[i] = 0.0f;
}

// ---------------------------------------------------------------------------
// weight prep: transpose + gate-permute + fp16, fused [U1;W1], + biases
// ---------------------------------------------------------------------------
#define PREP_UW (G4 * KL1)
#define PREP_WC (G4 * 1024)
#define PREP_FC (NCLS * HID)
#define PREP_PB (2 * G4)
#define PREP_TOTAL (PREP_UW + PREP_WC + PREP_FC + PREP_PB)

__global__ void prep_weights(const float* __restrict__ W1, const float* __restrict__ U1,
                             const float* __restrict__ W2, const float* __restrict__ U2,
                             const float* __restrict__ FC,
                             const float* __restrict__ b1, const float* __restrict__ b2,
                             __half* __restrict__ uwp, __half* __restrict__ wcp,
                             __half* __restrict__ fct,
                             float* __restrict__ pb1, float* __restrict__ pb2) {
    int i = blockIdx.x * blockDim.x + threadIdx.x;
    if (i >= PREP_TOTAL) return;
    if (i >= PREP_UW + PREP_WC + PREP_FC) {
        int o = i - (PREP_UW + PREP_WC + PREP_FC);
        int which = o >> 11;
        int np = o & 2047;
        int src = (np & 3) * HID + (np >> 2);
        if (which == 0) pb1[np] = b1[src]; else pb2[np] = b2[src];
        return;
    }
    float v;
    __half* dst;
    int o;
    if (i < PREP_UW) {
        o = i;
        int np = o / KL1, k = o % KL1;
        int n = (np & 3) * HID + (np >> 2);
        v = (k < HID) ? U1[(size_t)k * G4 + n] : W1[(size_t)(k - HID) * G4 + n];
        dst = uwp;
    } else if (i < PREP_UW + PREP_WC) {
        o = i - PREP_UW;
        int np = o >> 10, k = o & 1023;
        int n = (np & 3) * HID + (np >> 2);
        v = (k < HID) ? W2[(size_t)k * G4 + n] : U2[(size_t)(k - HID) * G4 + n];
        dst = wcp;
    } else {
        o = i - PREP_UW - PREP_WC;
        int n = o >> 9, k = o & 511;
        v = FC[(size_t)k * NCLS + n];
        dst = fct;
    }
    dst[o] = __float2half_rn(v);
}

// ---------------------------------------------------------------------------
// fused conv1+pool1+conv2+pool2 -> seq fp16 [B,7,160]; one block per sample.
// ---------------------------------------------------------------------------
__global__ __launch_bounds__(256) void conv12_pool(
    const float* __restrict__ x,
    const float* __restrict__ w1, const float* __restrict__ b1,
    const float* __restrict__ w2, const float* __restrict__ b2,
    __half* __restrict__ sh) {
    __shared__ float sIn[15 * 80 * 3];
    __shared__ float sW1[7 * 3 * 3 * 10];
    __shared__ float sP[9 * 26 * 10];
    __shared__ float sW2[3 * 3 * 10 * 20];
    int b = blockIdx.x;
    const float* xb = x + (size_t)b * 3600;
    for (int i = threadIdx.x; i < 3600; i += 256) sIn[i] = xb[i];
    for (int i = threadIdx.x; i < 630; i += 256) sW1[i] = w1[i];
    for (int i = threadIdx.x; i < 1800; i += 256) sW2[i] = w2[i];
    __syncthreads();

    for (int item = threadIdx.x; item < 9 * 260; item += 256) {
        int r = item / 260;
        int rem = item - r * 260;
        int p = rem / 10, co = rem - p * 10;
        float best = -1e30f;
#pragma unroll
        for (int dx = 0; dx < 3; dx++) {
            int cw = p * 3 + dx;
            float acc = 0.0f;
#pragma unroll
            for (int kh = 0; kh < 7; kh++)
#pragma unroll
                for (int kw = 0; kw < 3; kw++)
#pragma unroll
                    for (int ci = 0; ci < 3; ci++)
                        acc += sIn[(r + kh) * 240 + (cw + kw) * 3 + ci] *
                               sW1[((kh * 3 + kw) * 3 + ci) * 10 + co];
            best = fmaxf(best, acc);
        }
        sP[(r * 26 + p) * 10 + co] = fmaxf(best + b1[co], 0.0f);
    }
    __syncthreads();

    for (int item = threadIdx.x; item < 7 * 160; item += 256) {
        int r = item / 160;
        int f = item - r * 160;
        int p = f / 20, co = f - p * 20;
        float best = -1e30f;
#pragma unroll
        for (int dx = 0; dx < 3; dx++) {
            int cw = p * 3 + dx;
            float acc = 0.0f;
#pragma unroll
            for (int kh = 0; kh < 3; kh++)
#pragma unroll
                for (int kw = 0; kw < 3; kw++)
#pragma unroll
                    for (int ci = 0; ci < 10; ci++)
                        acc += sP[((r + kh) * 26 + (cw + kw)) * 10 + ci] *
                               sW2[((kh * 3 + kw) * 10 + ci) * 20 + co];
            best = fmaxf(best, acc);
        }
        float v = fmaxf(best + b2[co], 0.0f);
        sh[(size_t)(b * 7 + r) * SEQF + f] = __float2half_rn(v);
    }
}

// ---------------------------------------------------------------------------
// dual-job fp16 1-pass GEMM with split-K A source (A for k<KA, A2 after):
// tile 128x64, 256 thr (4x2 warps of 32x32), 3-stage cp.async ring, 4 CTAs/SM.
// gate mode = fused LSTM epilogue staged through SMEM.
// ---------------------------------------------------------------------------
struct GemmJob {
    const __half* A; int lda; int KA;     // first A segment (K multiple of 32)
    const __half* A2; int lda2; int K2;   // optional second A segment
    const __half* B; int ldb;             // B [N, KA+K2]
    const float* bias;
    float* C; int ldc;
    int relu, gate;
    float* cbuf;
    __half* hout; int hoff;
    int nx;                               // N tiles (N = nx*64)
};

#define ROWB 80
#define A_TILE_B (128 * ROWB)             // 10240
#define B_TILE_B (64 * ROWB)              // 5120
#define STAGE_B (A_TILE_B + B_TILE_B)     // 15360
#define GSM_BYTES 46080                   // 3*STAGE_B; >= epi 128*68*4=34816
#define EPI_PITCH 68
#define NTHR 256

__device__ __forceinline__ uint32_t smem_u32(const void* p) {
    uint32_t a;
    asm("{ .reg .u64 t; cvta.to.shared.u64 t, %1; cvt.u32.u64 %0, t; }" : "=r"(a) : "l"(p));
    return a;
}
__device__ __forceinline__ void cp_async16(uint32_t sa, const void* gaddr) {
    asm volatile("cp.async.cg.shared.global [%0], [%1], 16;" :: "r"(sa), "l"(gaddr) : "memory");
}
__device__ __forceinline__ void ldmx4(uint32_t* r, uint32_t sa) {
    asm volatile("ldmatrix.sync.aligned.m8n8.x4.shared.b16 {%0,%1,%2,%3}, [%4];"
                 : "=r"(r[0]), "=r"(r[1]), "=r"(r[2]), "=r"(r[3]) : "r"(sa));
}
__device__ __forceinline__ void mma_f16(float* c, const uint32_t* a, uint32_t b0, uint32_t b1) {
    asm volatile(
        "mma.sync.aligned.m16n8k16.row.col.f32.f16.f16.f32 "
        "{%0,%1,%2,%3}, {%4,%5,%6,%7}, {%8,%9}, {%0,%1,%2,%3};"
        : "+f"(c[0]), "+f"(c[1]), "+f"(c[2]), "+f"(c[3])
        : "r"(a[0]), "r"(a[1]), "r"(a[2]), "r"(a[3]), "r"(b0), "r"(b1));
}
__device__ __forceinline__ float sigacc(float x) { return 1.0f / (1.0f + expf(-x)); }

__global__ __launch_bounds__(NTHR, 4) void gemm_dual(int M, GemmJob j0, GemmJob j1) {
    extern __shared__ char smem[];
    uint32_t sb0 = smem_u32(smem);
    int tid = threadIdx.x;
    int lane = tid & 31;
    int warp = tid >> 5;
    int wm = warp >> 1;
    int wn = warp & 1;
    int gid = lane >> 2;
    int tig = lane & 3;
    int lane15 = lane & 15;
    int halfsel = (lane >> 4) << 4;

    int isj0 = (int)(blockIdx.x < (unsigned)j0.nx);
    GemmJob j = isj0 ? j0 : j1;
    int bn = (isj0 ? blockIdx.x : blockIdx.x - j0.nx) * 64;
    int bm = blockIdx.y * 128;

    const __half* A0 = j.A + (size_t)bm * j.lda;
    const __half* A2 = j.A2 ? (j.A2 + (size_t)bm * j.lda2) : nullptr;
    const __half* B0 = j.B + (size_t)bn * j.ldb;
    int lda = j.lda, lda2 = j.lda2, ldb = j.ldb;
    int KA = j.KA;

    float acc[2][4][4];
#pragma unroll
    for (int i = 0; i < 2; i++)
#pragma unroll
        for (int jj = 0; jj < 4; jj++)
#pragma unroll
            for (int r = 0; r < 4; r++) acc[i][jj][r] = 0.0f;

    int nst = (KA + j.K2) >> 5;

    int cp_row = tid >> 2, cp_c4 = tid & 3;

#define ISSUE_STAGE(kt, slot) do {                                             \
        if ((kt) < nst) {                                                      \
            uint32_t st = sb0 + (slot) * STAGE_B;                              \
            int k0 = (kt) << 5;                                                \
            const __half* Ap; int ldA; int ko;                                 \
            if (k0 < KA) { Ap = A0; ldA = lda; ko = k0; }                      \
            else { Ap = A2; ldA = lda2; ko = k0 - KA; }                        \
            uint32_t sa = st + cp_row * ROWB + cp_c4 * 16;                     \
            cp_async16(sa, Ap + (size_t)cp_row * ldA + ko + cp_c4 * 8);        \
            cp_async16(sa + 64 * ROWB,                                         \
                       Ap + (size_t)(cp_row + 64) * ldA + ko + cp_c4 * 8);     \
            cp_async16(st + A_TILE_B + cp_row * ROWB + cp_c4 * 16,             \
                       B0 + (size_t)cp_row * ldb + k0 + cp_c4 * 8);            \
        }                                                                      \
        asm volatile("cp.async.commit_group;" ::: "memory");                   \
    } while (0)

    ISSUE_STAGE(0, 0);
    ISSUE_STAGE(1, 1);

    int slot = 0, slot2 = 2;
    for (int kt = 0; kt < nst; kt++) {
        asm volatile("cp.async.wait_group 1;" ::: "memory");
        __syncthreads();
        ISSUE_STAGE(kt + 2, slot2);

        uint32_t st = sb0 + slot * STAGE_B;
        uint32_t aAddr = st + (uint32_t)((wm * 32 + lane15) * ROWB) + halfsel;
        uint32_t bAddr = st + A_TILE_B + (uint32_t)((wn * 32 + lane15) * ROWB) + halfsel;

#pragma unroll
        for (int k16 = 0; k16 < 2; k16++) {
            uint32_t kb = k16 * 32;
            uint32_t af[2][4], bf[2][4];
            ldmx4(af[0], aAddr + kb);
            ldmx4(af[1], aAddr + 16 * ROWB + kb);
            ldmx4(bf[0], bAddr + kb);
            ldmx4(bf[1], bAddr + 16 * ROWB + kb);
#pragma unroll
            for (int nb = 0; nb < 2; nb++) {
#pragma unroll
                for (int hf = 0; hf < 2; hf++) {
                    int na = nb * 2 + hf;
#pragma unroll
                    for (int ma = 0; ma < 2; ma++)
                        mma_f16(acc[ma][na], af[ma], bf[nb][hf], bf[nb][2 + hf]);
                }
            }
        }
        slot = (slot == 2) ? 0 : slot + 1;
        slot2 = (slot2 == 2) ? 0 : slot2 + 1;
    }
    __syncthreads();

    // ---- epilogue ----
    if (j.gate) {
        float* sg = (float*)smem;
#pragma unroll
        for (int ma = 0; ma < 2; ma++) {
#pragma unroll
            for (int na = 0; na < 4; na++) {
                int rl = wm * 32 + ma * 16 + gid;
                int cl = wn * 32 + na * 8 + 2 * tig;
                int col0 = bn + cl;
                float bb0 = j.bias[col0], bb1 = j.bias[col0 + 1];
                *(float2*)&sg[rl * EPI_PITCH + cl] =
                    make_float2(acc[ma][na][0] + bb0, acc[ma][na][1] + bb1);
                *(float2*)&sg[(rl + 8) * EPI_PITCH + cl] =
                    make_float2(acc[ma][na][2] + bb0, acc[ma][na][3] + bb1);
            }
        }
        __syncthreads();
        int jb = bn >> 2;
#pragma unroll
        for (int it = 0; it < 8; it++) {
            int idx = it * NTHR + tid;
            int rl = idx >> 4, jl = idx & 15;
            float4 g = *(const float4*)&sg[rl * EPI_PITCH + jl * 4];
            int grow = bm + rl;
            int jcol = jb + jl;
            size_t cidx = (size_t)grow * HID + jcol;
            float cv = sigacc(g.y) * j.cbuf[cidx] + sigacc(g.x) * tanhf(g.z);
            j.cbuf[cidx] = cv;
            float h = sigacc(g.w) * tanhf(cv);
            j.hout[(size_t)grow * 1024 + j.hoff + jcol] = __float2half_rn(h);
        }
    } else {
#pragma unroll
        for (int ma = 0; ma < 2; ma++) {
#pragma unroll
            for (int na = 0; na < 4; na++) {
                int row0 = bm + wm * 32 + ma * 16 + gid;
                int col = bn + wn * 32 + na * 8 + 2 * tig;
                float v0 = acc[ma][na][0], v1 = acc[ma][na][1];
                float v2 = acc[ma][na][2], v3 = acc[ma][na][3];
                if (j.bias) {
                    float bb0 = j.bias[col], bb1 = j.bias[col + 1];
                    v0 += bb0; v1 += bb1; v2 += bb0; v3 += bb1;
                }
                if (j.relu) {
                    v0 = fmaxf(v0, 0.0f); v1 = fmaxf(v1, 0.0f);
                    v2 = fmaxf(v2, 0.0f); v3 = fmaxf(v3, 0.0f);
                }
                *(float2*)(j.C + (size_t)row0 * j.ldc + col) = make_float2(v0, v1);
                *(float2*)(j.C + (size_t)(row0 + 8) * j.ldc + col) = make_float2(v2, v3);
            }
        }
    }
#undef ISSUE_STAGE
}

// ---------------------------------------------------------------------------
// launch
// ---------------------------------------------------------------------------
extern "C" void kernel_launch(void* const* d_in, const int* in_sizes, int n_in,
                              void* d_out, int out_size) {
    const float* x = (const float*)d_in[0];
    const float* c1w = (const float*)d_in[1];
    const float* c1b = (const float*)d_in[2];
    const float* c2w = (const float*)d_in[3];
    const float* c2b = (const float*)d_in[4];
    const float* W1 = (const float*)d_in[5];
    const float* U1 = (const float*)d_in[6];
    const float* b1 = (const float*)d_in[7];
    const float* W2 = (const float*)d_in[8];
    const float* U2 = (const float*)d_in[9];
    const float* b2 = (const float*)d_in[10];
    const float* fcw = (const float*)d_in[11];
    const float* fcb = (const float*)d_in[12];
    float* out = (float*)d_out;

    float *c1, *c2, *pb1, *pb2;
    __half *seqh;
    __half *cat[2];
    __half *uwp, *wcp, *fct;
    cudaGetSymbolAddress((void**)&c1, d_c1);
    cudaGetSymbolAddress((void**)&c2, d_c2);
    cudaGetSymbolAddress((void**)&pb1, d_pb1);
    cudaGetSymbolAddress((void**)&pb2, d_pb2);
    cudaGetSymbolAddress((void**)&seqh, d_seq);
    cudaGetSymbolAddress((void**)&cat[0], d_cat0);
    cudaGetSymbolAddress((void**)&cat[1], d_cat1);
    cudaGetSymbolAddress((void**)&uwp, d_UWp);
    cudaGetSymbolAddress((void**)&wcp, d_WCp);
    cudaGetSymbolAddress((void**)&fct, d_FCt);

    cudaFuncSetAttribute(gemm_dual, cudaFuncAttributeMaxDynamicSharedMemorySize, GSM_BYTES);

    init_state<<<(BATCH * 1024 / 2) / 256, 256>>>(
        (uint32_t*)cat[0], (uint32_t*)cat[1], c1, c2);
    prep_weights<<<(PREP_TOTAL + 255) / 256, 256>>>(W1, U1, W2, U2, fcw, b1, b2,
                                                    uwp, wcp, fct, pb1, pb2);
    conv12_pool<<<BATCH, 256>>>(x, c1w, c1b, c2w, c2b, seqh);

    GemmJob nil{};
    nil.nx = 0;

    // layer 1 (t): gates([h1_{t-1} | x_t] @ [U1;W1]) ; reads cat[t&1],
    // writes h1_t -> cat[1-(t&1)][0:512]
    auto L1 = [&](int t) {
        GemmJob jb{};
        int p = t & 1;
        jb.A = cat[p]; jb.lda = 1024; jb.KA = HID;
        jb.A2 = seqh + t * SEQF; jb.lda2 = SEQLEN * SEQF; jb.K2 = SEQF;
        jb.B = uwp; jb.ldb = KL1;
        jb.bias = pb1;
        jb.C = nullptr; jb.ldc = 0; jb.relu = 0; jb.gate = 1;
        jb.cbuf = c1; jb.hout = cat[1 - p]; jb.hoff = 0;
        jb.nx = G4 / 64;
        return jb;
    };
    // layer 2 (t): gates([h1_t | h2_{t-1}] @ [W2;U2]) ; reads cat[1-(t&1)],
    // writes h2_t -> cat[t&1][512:1024]
    auto L2 = [&](int t) {
        GemmJob jb{};
        int p = t & 1;
        jb.A = cat[1 - p]; jb.lda = 1024; jb.KA = 1024;
        jb.A2 = nullptr; jb.lda2 = 0; jb.K2 = 0;
        jb.B = wcp; jb.ldb = 1024;
        jb.bias = pb2;
        jb.C = nullptr; jb.ldc = 0; jb.relu = 0; jb.gate = 1;
        jb.cbuf = c2; jb.hout = cat[p]; jb.hoff = HID;
        jb.nx = G4 / 64;
        return jb;
    };

    // L1(0)
    {
        GemmJob jb = L1(0);
        dim3 g(jb.nx, BATCH / 128);
        gemm_dual<<<g, NTHR, GSM_BYTES>>>(BATCH, jb, nil);
    }
    // combined phases: {L2(t) || L1(t+1)} for t = 0..5
    for (int t = 0; t < SEQLEN - 1; t++) {
        GemmJob ja = L2(t);
        GemmJob jb = L1(t + 1);
        dim3 g(ja.nx + jb.nx, BATCH / 128);
        gemm_dual<<<g, NTHR, GSM_BYTES>>>(BATCH, ja, jb);
    }
    // L2(6)
    {
        GemmJob jb = L2(SEQLEN - 1);
        dim3 g(jb.nx, BATCH / 128);
        gemm_dual<<<g, NTHR, GSM_BYTES>>>(BATCH, jb, nil);
    }

    // FC head: relu(h2 @ fc_w + fc_b); final h2 in cat[(SEQLEN-1)&1] = cat[0]
    {
        GemmJob jb{};
        int pf = (SEQLEN - 1) & 1;
        jb.A = cat[pf] + HID; jb.lda = 1024; jb.KA = HID;
        jb.A2 = nullptr; jb.lda2 = 0; jb.K2 = 0;
        jb.B = fct; jb.ldb = HID;
        jb.bias = fcb;
        jb.C = out; jb.ldc = NCLS; jb.relu = 1; jb.gate = 0;
        jb.cbuf = nullptr; jb.hout = nullptr; jb.hoff = 0;
        jb.nx = NCLS / 64;
        dim3 g(jb.nx, BATCH / 128);
        gemm_dual<<<g, NTHR, GSM_BYTES>>>(BATCH, jb, nil);
    }
}